// round 2
// baseline (speedup 1.0000x reference)
#include <cuda_runtime.h>
#include <math.h>

#define BSZ 4
#define LEN 1024
#define DM 1024
#define NH 16
#define NAA 25

// ---------------- scratch (static device globals; no allocation) ----------------
__device__ float g_qkv[BSZ * LEN * 3 * DM];   // (B*L, 3072): [q | k | v] per row
__device__ float g_bias[BSZ * LEN * LEN];     // shared (head-independent) bias
__device__ float g_ctx[BSZ * LEN * DM];       // attention output, (B*L, D)
__device__ float g_proj[BSZ * LEN * NH];      // ss @ ss_w^T

// ---------------- proj = secondary_structure @ ss_w^T ----------------
__global__ __launch_bounds__(256) void proj_kernel(const float* __restrict__ ss,
                                                   const float* __restrict__ ss_w,
                                                   float* __restrict__ proj) {
    __shared__ float w[NH][8];
    int t = threadIdx.x;
    if (t < NH * 8) w[t / 8][t % 8] = ss_w[t];
    __syncthreads();
    int idx = blockIdx.x * blockDim.x + t;   // over B*L*NH = 65536
    int h = idx & 15;
    int bl = idx >> 4;
    const float* s = ss + bl * 8;
    float acc = 0.f;
#pragma unroll
    for (int c = 0; c < 8; c++) acc += s[c] * w[h][c];
    proj[idx] = acc;
}

// ---------------- shared bias tensor: dist_pen + inter + struct ----------------
__global__ __launch_bounds__(1024) void bias_kernel(const float* __restrict__ pf,
                                                    const int* __restrict__ ids,
                                                    const float* __restrict__ inter_mat,
                                                    const float* __restrict__ projp,
                                                    const float* __restrict__ physics_scale,
                                                    const float* __restrict__ distance_decay,
                                                    float* __restrict__ biasout) {
    __shared__ float sym[NAA * NAA];
    __shared__ float pi[32][17];
    __shared__ float pj[32][17];
    __shared__ int idi[32], idj[32];

    const int b = blockIdx.z;
    const int i0 = blockIdx.y * 32;
    const int j0 = blockIdx.x * 32;
    const int t = threadIdx.y * 32 + threadIdx.x;

    for (int s = t; s < NAA * NAA; s += 1024) {
        int r = s / NAA, c = s % NAA;
        sym[s] = 0.5f * (inter_mat[r * NAA + c] + inter_mat[c * NAA + r]);
    }
    if (t < 32)       idi[t]      = min(max(ids[b * LEN + i0 + t], 0), NAA - 1);
    else if (t < 64)  idj[t - 32] = min(max(ids[b * LEN + j0 + (t - 32)], 0), NAA - 1);
    if (t < 512) {
        int r = t / 16, c = t % 16;
        pi[r][c] = projp[(b * LEN + i0 + r) * NH + c];
    } else {
        int u = t - 512;
        int r = u / 16, c = u % 16;
        pj[r][c] = projp[(b * LEN + j0 + r) * NH + c];
    }
    __syncthreads();

    const int i = threadIdx.y, j = threadIdx.x;
    float decay = fminf(fmaxf(distance_decay[0], 0.1f), 5.0f);
    float sig = 1.0f / (1.0f + expf(-physics_scale[0]));

    float d = pf[(size_t)b * LEN * LEN + (size_t)(i0 + i) * LEN + (j0 + j)];
    d = fminf(fmaxf(d, 0.1f), 50.0f);
    float pen = -powf(d, decay) * sig;

    float it = sym[idi[i] * NAA + idj[j]] *
               (1.0f / (1.0f + fabsf((float)(i0 + i) - (float)(j0 + j))));

    float dot = 0.f;
#pragma unroll
    for (int hh = 0; hh < NH; hh++) dot += pi[i][hh] * pj[j][hh];
    float st = 1.0f / (1.0f + expf(-dot)) - 0.5f;

    biasout[(size_t)b * LEN * LEN + (size_t)(i0 + i) * LEN + (j0 + j)] = pen + it + st;
}

// ---------------- generic 128x128x8 SGEMM: C = A @ W^T (+bias), W selected by n-tile ----------------
__global__ __launch_bounds__(256, 2)
void sgemm128_kernel(const float* __restrict__ A,
                     const float* __restrict__ W0, const float* __restrict__ W1,
                     const float* __restrict__ W2,
                     const float* __restrict__ bias,
                     float* __restrict__ C, int N, int K) {
    __shared__ float As[8][128];
    __shared__ float Bs[8][128];

    const int t = threadIdx.x;
    const int bm = blockIdx.y, bn = blockIdx.x;
    const int n0 = bn * 128;
    const float* W = W0;
    int wn0 = n0;
    if (n0 >= 2048)      { W = W2; wn0 = n0 - 2048; }
    else if (n0 >= 1024) { W = W1; wn0 = n0 - 1024; }

    const int trow = t >> 1;
    const int tseg = (t & 1) << 2;
    const int ty = t >> 4, tx = t & 15;

    const float* Ap = A + (size_t)(bm * 128 + trow) * K + tseg;
    const float* Wp = W + (size_t)(wn0 + trow) * K + tseg;

    float acc[8][8];
#pragma unroll
    for (int i = 0; i < 8; i++)
#pragma unroll
        for (int j = 0; j < 8; j++) acc[i][j] = 0.f;

    float4 av = *(const float4*)(Ap);
    float4 bv = *(const float4*)(Wp);

    for (int k0 = 0; k0 < K; k0 += 8) {
        __syncthreads();
        As[tseg + 0][trow] = av.x; As[tseg + 1][trow] = av.y;
        As[tseg + 2][trow] = av.z; As[tseg + 3][trow] = av.w;
        Bs[tseg + 0][trow] = bv.x; Bs[tseg + 1][trow] = bv.y;
        Bs[tseg + 2][trow] = bv.z; Bs[tseg + 3][trow] = bv.w;
        __syncthreads();
        if (k0 + 8 < K) {             // prefetch next tile during compute
            av = *(const float4*)(Ap + k0 + 8);
            bv = *(const float4*)(Wp + k0 + 8);
        }
#pragma unroll
        for (int kk = 0; kk < 8; kk++) {
            float4 a0 = *(const float4*)&As[kk][ty * 8];
            float4 a1 = *(const float4*)&As[kk][ty * 8 + 4];
            float4 b0 = *(const float4*)&Bs[kk][tx * 8];
            float4 b1 = *(const float4*)&Bs[kk][tx * 8 + 4];
            float a[8] = {a0.x, a0.y, a0.z, a0.w, a1.x, a1.y, a1.z, a1.w};
            float bb[8] = {b0.x, b0.y, b0.z, b0.w, b1.x, b1.y, b1.z, b1.w};
#pragma unroll
            for (int i = 0; i < 8; i++)
#pragma unroll
                for (int j = 0; j < 8; j++) acc[i][j] += a[i] * bb[j];
        }
    }

#pragma unroll
    for (int i = 0; i < 8; i++) {
        int row = bm * 128 + ty * 8 + i;
        float* cp = C + (size_t)row * N + n0 + tx * 8;
#pragma unroll
        for (int j = 0; j < 8; j++) {
            float v = acc[i][j];
            if (bias) v += bias[n0 + tx * 8 + j];
            cp[j] = v;
        }
    }
}

// ---------------- flash attention: 64 query rows per block, full K sweep ----------------
__global__ __launch_bounds__(256)
void attn_kernel(const float* __restrict__ qkv, const float* __restrict__ biasp,
                 const float* __restrict__ dist_bias, float* __restrict__ ctx) {
    extern __shared__ float smf[];
    float* Qs = smf;                 // [64][64]
    float* Ks = smf + 4096;          // [64][65]  (reused to hold P after scores)
    float* Vs = smf + 4096 + 4160;   // [64][64]

    const int t = threadIdx.x;
    const int ty = t >> 4, tx = t & 15;
    const int i0 = blockIdx.x * 64;
    const int h = blockIdx.y;
    const int b = blockIdx.z;
    const float db = dist_bias[h];

    {   // load Q tile
        int r = t >> 2, c0 = (t & 3) * 16;
        const float* qp = qkv + (size_t)(b * LEN + i0 + r) * 3072 + h * 64 + c0;
#pragma unroll
        for (int c = 0; c < 16; c += 4) {
            float4 v = *(const float4*)(qp + c);
            Qs[r * 64 + c0 + c] = v.x; Qs[r * 64 + c0 + c + 1] = v.y;
            Qs[r * 64 + c0 + c + 2] = v.z; Qs[r * 64 + c0 + c + 3] = v.w;
        }
    }

    float m[4], l[4], O[4][4];
#pragma unroll
    for (int ri = 0; ri < 4; ri++) {
        m[ri] = -3.0e38f; l[ri] = 0.f;
#pragma unroll
        for (int dj = 0; dj < 4; dj++) O[ri][dj] = 0.f;
    }

    const float* brow = biasp + (size_t)b * LEN * LEN + (size_t)i0 * LEN;

    for (int jt = 0; jt < 16; jt++) {
        const int j0 = jt * 64;
        __syncthreads();
        {   // load K, V tiles
            int r = t >> 2, c0 = (t & 3) * 16;
            const float* kp = qkv + (size_t)(b * LEN + j0 + r) * 3072 + DM + h * 64 + c0;
            const float* vp = kp + DM;
#pragma unroll
            for (int c = 0; c < 16; c += 4) {
                float4 kv4 = *(const float4*)(kp + c);
                Ks[r * 65 + c0 + c] = kv4.x; Ks[r * 65 + c0 + c + 1] = kv4.y;
                Ks[r * 65 + c0 + c + 2] = kv4.z; Ks[r * 65 + c0 + c + 3] = kv4.w;
                float4 vv4 = *(const float4*)(vp + c);
                Vs[r * 64 + c0 + c] = vv4.x; Vs[r * 64 + c0 + c + 1] = vv4.y;
                Vs[r * 64 + c0 + c + 2] = vv4.z; Vs[r * 64 + c0 + c + 3] = vv4.w;
            }
        }
        __syncthreads();

        // S = Q K^T (4x4 per thread, strided ownership)
        float s[4][4];
#pragma unroll
        for (int ri = 0; ri < 4; ri++)
#pragma unroll
            for (int cj = 0; cj < 4; cj++) s[ri][cj] = 0.f;

        for (int d = 0; d < 64; d++) {
            float qv[4], kv[4];
#pragma unroll
            for (int ri = 0; ri < 4; ri++) qv[ri] = Qs[(ty + 16 * ri) * 64 + d];
#pragma unroll
            for (int cj = 0; cj < 4; cj++) kv[cj] = Ks[(tx + 16 * cj) * 65 + d];
#pragma unroll
            for (int ri = 0; ri < 4; ri++)
#pragma unroll
                for (int cj = 0; cj < 4; cj++) s[ri][cj] += qv[ri] * kv[cj];
        }
        __syncthreads();  // done reading K; Ks region will be rewritten as P

        // bias + online softmax (rows ty+16*ri, shared across the 16 tx lanes)
#pragma unroll
        for (int ri = 0; ri < 4; ri++) {
            const int row = ty + 16 * ri;
            float sv[4];
            float mx = -3.0e38f;
#pragma unroll
            for (int cj = 0; cj < 4; cj++) {
                float v = s[ri][cj] * 0.125f +
                          brow[(size_t)row * LEN + j0 + tx + 16 * cj] + db;
                sv[cj] = v;
                mx = fmaxf(mx, v);
            }
#pragma unroll
            for (int off = 8; off >= 1; off >>= 1)
                mx = fmaxf(mx, __shfl_xor_sync(0xffffffffu, mx, off, 16));
            float mnew = fmaxf(m[ri], mx);
            float fac = expf(m[ri] - mnew);
            float sum = 0.f;
#pragma unroll
            for (int cj = 0; cj < 4; cj++) {
                float p = expf(sv[cj] - mnew);
                Ks[row * 65 + tx + 16 * cj] = p;   // P into old K buffer
                sum += p;
            }
#pragma unroll
            for (int off = 8; off >= 1; off >>= 1)
                sum += __shfl_xor_sync(0xffffffffu, sum, off, 16);
            l[ri] = l[ri] * fac + sum;
            m[ri] = mnew;
#pragma unroll
            for (int dj = 0; dj < 4; dj++) O[ri][dj] *= fac;
        }
        __syncthreads();  // P visible to all

        // O += P @ V
        for (int j = 0; j < 64; j++) {
            float pv[4], vv[4];
#pragma unroll
            for (int ri = 0; ri < 4; ri++) pv[ri] = Ks[(ty + 16 * ri) * 65 + j];
#pragma unroll
            for (int dj = 0; dj < 4; dj++) vv[dj] = Vs[j * 64 + tx + 16 * dj];
#pragma unroll
            for (int ri = 0; ri < 4; ri++)
#pragma unroll
                for (int dj = 0; dj < 4; dj++) O[ri][dj] += pv[ri] * vv[dj];
        }
    }

    // normalize + store ctx in (B*L, D) layout with head offset
#pragma unroll
    for (int ri = 0; ri < 4; ri++) {
        float inv = 1.0f / l[ri];
        int row = i0 + ty + 16 * ri;
        float* cp = ctx + (size_t)(b * LEN + row) * DM + h * 64 + tx;
#pragma unroll
        for (int dj = 0; dj < 4; dj++) cp[16 * dj] = O[ri][dj] * inv;
    }
}

// ---------------- launch ----------------
extern "C" void kernel_launch(void* const* d_in, const int* in_sizes, int n_in,
                              void* d_out, int out_size) {
    const float* x              = (const float*)d_in[0];
    const float* pf             = (const float*)d_in[1];
    const int*   ids            = (const int*)d_in[2];
    const float* ss             = (const float*)d_in[3];
    const float* Wq             = (const float*)d_in[4];
    const float* Wk             = (const float*)d_in[5];
    const float* Wv             = (const float*)d_in[6];
    const float* Wo             = (const float*)d_in[7];
    const float* bo             = (const float*)d_in[8];
    const float* dist_bias      = (const float*)d_in[9];
    const float* inter_mat      = (const float*)d_in[10];
    const float* ss_w           = (const float*)d_in[11];
    const float* physics_scale  = (const float*)d_in[12];
    const float* distance_decay = (const float*)d_in[13];
    float* out = (float*)d_out;

    float *qkv, *biasb, *ctx, *proj;
    cudaGetSymbolAddress((void**)&qkv,  g_qkv);
    cudaGetSymbolAddress((void**)&biasb, g_bias);
    cudaGetSymbolAddress((void**)&ctx,  g_ctx);
    cudaGetSymbolAddress((void**)&proj, g_proj);

    cudaFuncSetAttribute(attn_kernel, cudaFuncAttributeMaxDynamicSharedMemorySize, 49408);

    proj_kernel<<<256, 256>>>(ss, ss_w, proj);
    bias_kernel<<<dim3(32, 32, BSZ), dim3(32, 32)>>>(pf, ids, inter_mat, proj,
                                                     physics_scale, distance_decay, biasb);
    sgemm128_kernel<<<dim3(24, 32), 256>>>(x, Wq, Wk, Wv, nullptr, qkv, 3072, 1024);
    attn_kernel<<<dim3(16, 16, BSZ), 256, 49408>>>(qkv, biasb, dist_bias, ctx);
    sgemm128_kernel<<<dim3(8, 32), 256>>>(ctx, Wo, Wo, Wo, bo, out, 1024, 1024);
}

// round 4
// speedup vs baseline: 1.6006x; 1.6006x over previous
#include <cuda_runtime.h>
#include <cuda_bf16.h>
#include <math.h>
#include <stdint.h>

#define BSZ 4
#define LEN 1024
#define DM 1024
#define NH 16
#define NAA 25

// ---------------- scratch (static device globals; no allocation) ----------------
__device__ float g_qkv[BSZ * LEN * 3 * DM];   // (B*L, 3072): [q | k | v]
__device__ float g_bias[BSZ * LEN * LEN];     // shared (head-independent) bias
__device__ float g_ctx[BSZ * LEN * DM];       // attention output
__device__ float g_proj[BSZ * LEN * NH];
__device__ __nv_bfloat16 g_a_hi[4096 * 1024]; // activation split (x, later ctx)
__device__ __nv_bfloat16 g_a_lo[4096 * 1024];
__device__ __nv_bfloat16 g_w_hi[4096 * 1024]; // rows 0-3071 = Wq,Wk,Wv; 3072-4095 = Wo
__device__ __nv_bfloat16 g_w_lo[4096 * 1024];

static __device__ __forceinline__ uint32_t smem_u32(const void* p) {
    uint32_t a;
    asm("{ .reg .u64 t; cvta.to.shared.u64 t, %1; cvt.u32.u64 %0, t; }" : "=r"(a) : "l"(p));
    return a;
}

#define LDSM4(r, addr)                                                          \
    asm volatile("ldmatrix.sync.aligned.m8n8.x4.shared.b16 {%0,%1,%2,%3}, [%4];" \
                 : "=r"((r)[0]), "=r"((r)[1]), "=r"((r)[2]), "=r"((r)[3])       \
                 : "r"(addr))

#define MMA16816(d, a, b)                                                       \
    asm volatile("mma.sync.aligned.m16n8k16.row.col.f32.bf16.bf16.f32 "         \
                 "{%0,%1,%2,%3}, {%4,%5,%6,%7}, {%8,%9}, {%0,%1,%2,%3};"        \
                 : "+f"((d)[0]), "+f"((d)[1]), "+f"((d)[2]), "+f"((d)[3])       \
                 : "r"((a)[0]), "r"((a)[1]), "r"((a)[2]), "r"((a)[3]),          \
                   "r"((b)[0]), "r"((b)[1]))

// ---------------- fp32 -> bf16 hi/lo split ----------------
__global__ __launch_bounds__(256)
void split_kernel(const float4* __restrict__ a, __nv_bfloat162* __restrict__ hi,
                  __nv_bfloat162* __restrict__ lo, int n4) {
    int i = blockIdx.x * blockDim.x + threadIdx.x;
    if (i >= n4) return;
    float4 v = a[i];
    __nv_bfloat16 hx = __float2bfloat16(v.x), hy = __float2bfloat16(v.y);
    __nv_bfloat16 hz = __float2bfloat16(v.z), hw = __float2bfloat16(v.w);
    __nv_bfloat16 lx = __float2bfloat16(v.x - __bfloat162float(hx));
    __nv_bfloat16 ly = __float2bfloat16(v.y - __bfloat162float(hy));
    __nv_bfloat16 lz = __float2bfloat16(v.z - __bfloat162float(hz));
    __nv_bfloat16 lw = __float2bfloat16(v.w - __bfloat162float(hw));
    hi[2 * i]     = __halves2bfloat162(hx, hy);
    hi[2 * i + 1] = __halves2bfloat162(hz, hw);
    lo[2 * i]     = __halves2bfloat162(lx, ly);
    lo[2 * i + 1] = __halves2bfloat162(lz, lw);
}

// ---------------- HMMA split-bf16 GEMM: C[M,N] = A[M,K] @ W[N,K]^T (+bias) ----------------
// CTA: 128x128 tile, 8 warps (2x4), warp tile 64x32, K chunk = 32, cp.async double buffer.
// Smem per stage: 4 tensors x 128 rows x 80B (64B data + 16B pad) = 40960B; 2 stages.
#define RS 80           // smem row stride in bytes (32 bf16 data + pad)
#define TEN 10240       // per-tensor smem bytes (128 * 80)
#define STAGE 40960
#define NCH 32          // K / 32

__global__ __launch_bounds__(256, 1)
void gemm_mma(const __nv_bfloat16* __restrict__ Ah, const __nv_bfloat16* __restrict__ Al,
              const __nv_bfloat16* __restrict__ Wh, const __nv_bfloat16* __restrict__ Wl,
              const float* __restrict__ bias, float* __restrict__ C,
              int N, int wrow0) {
    extern __shared__ char sm[];
    const uint32_t sb = smem_u32(sm);
    const int t = threadIdx.x, wid = t >> 5, lane = t & 31;
    const int m0 = blockIdx.y << 7, n0 = blockIdx.x << 7;
    const int wm = wid & 1, wn = wid >> 1;        // 2 (m) x 4 (n) warps

    const char* gsrc[4];
    gsrc[0] = (const char*)(Ah + (size_t)m0 * 1024);
    gsrc[1] = (const char*)(Al + (size_t)m0 * 1024);
    gsrc[2] = (const char*)(Wh + (size_t)(wrow0 + n0) * 1024);
    gsrc[3] = (const char*)(Wl + (size_t)(wrow0 + n0) * 1024);

    // ldmatrix lane address offsets (TN: both operands K-major, no .trans)
    const int mat = lane >> 3, lr = lane & 7;
    const uint32_t a_off = (uint32_t)((((mat & 1) << 3) + lr) * RS + ((mat >> 1) << 4));
    const uint32_t b_off = (uint32_t)((((mat >> 1) << 3) + lr) * RS + ((mat & 1) << 4));

    auto load_stage = [&](int st, int c) {
        uint32_t dbase = sb + st * STAGE;
#pragma unroll
        for (int q = 0; q < 4; q++) {
#pragma unroll
            for (int h = 0; h < 2; h++) {
                int idx = t + h * 256;              // 512 x 16B per tensor
                int row = idx >> 2, seg = idx & 3;
                const char* g = gsrc[q] + (size_t)row * 2048 + c * 64 + seg * 16;
                uint32_t d = dbase + q * TEN + row * RS + seg * 16;
                asm volatile("cp.async.cg.shared.global [%0], [%1], 16;"
                             :: "r"(d), "l"(g));
            }
        }
        asm volatile("cp.async.commit_group;" ::: "memory");
    };

    float acc[4][4][4];
#pragma unroll
    for (int i = 0; i < 4; i++)
#pragma unroll
        for (int j = 0; j < 4; j++)
#pragma unroll
            for (int k = 0; k < 4; k++) acc[i][j][k] = 0.f;

    load_stage(0, 0);

    for (int c = 0; c < NCH; c++) {
        const int st = c & 1;
        if (c + 1 < NCH) {
            load_stage(st ^ 1, c + 1);
            asm volatile("cp.async.wait_group 1;" ::: "memory");
        } else {
            asm volatile("cp.async.wait_group 0;" ::: "memory");
        }
        __syncthreads();

        const uint32_t abase = sb + st * STAGE;
#pragma unroll
        for (int k16 = 0; k16 < 2; k16++) {
            uint32_t ah[4][4], al[4][4], bh[4][2], bl[4][2];
#pragma unroll
            for (int mt = 0; mt < 4; mt++) {
                uint32_t addr = abase + (wm * 64 + mt * 16) * RS + k16 * 32 + a_off;
                LDSM4(ah[mt], addr);
                LDSM4(al[mt], addr + TEN);
            }
#pragma unroll
            for (int p = 0; p < 2; p++) {
                uint32_t addr = abase + 2 * TEN + (wn * 32 + p * 16) * RS + k16 * 32 + b_off;
                uint32_t r[4];
                LDSM4(r, addr);
                bh[2 * p][0] = r[0]; bh[2 * p][1] = r[1];
                bh[2 * p + 1][0] = r[2]; bh[2 * p + 1][1] = r[3];
                LDSM4(r, addr + TEN);
                bl[2 * p][0] = r[0]; bl[2 * p][1] = r[1];
                bl[2 * p + 1][0] = r[2]; bl[2 * p + 1][1] = r[3];
            }
#pragma unroll
            for (int mt = 0; mt < 4; mt++)
#pragma unroll
                for (int nt = 0; nt < 4; nt++) {
                    MMA16816(acc[mt][nt], ah[mt], bh[nt]);
                    MMA16816(acc[mt][nt], ah[mt], bl[nt]);
                    MMA16816(acc[mt][nt], al[mt], bh[nt]);
                }
        }
        __syncthreads();
    }

    // epilogue: acc -> C (+bias)
    const int qrow = lane >> 2, qcol = (lane & 3) * 2;
#pragma unroll
    for (int mt = 0; mt < 4; mt++) {
        const int r0 = m0 + wm * 64 + mt * 16 + qrow;
#pragma unroll
        for (int nt = 0; nt < 4; nt++) {
            const int col = n0 + wn * 32 + nt * 8 + qcol;
            float bx = 0.f, by = 0.f;
            if (bias) { bx = bias[col]; by = bias[col + 1]; }
            float2 v0 = make_float2(acc[mt][nt][0] + bx, acc[mt][nt][1] + by);
            float2 v1 = make_float2(acc[mt][nt][2] + bx, acc[mt][nt][3] + by);
            *(float2*)(C + (size_t)r0 * N + col) = v0;
            *(float2*)(C + (size_t)(r0 + 8) * N + col) = v1;
        }
    }
}

// ---------------- proj = secondary_structure @ ss_w^T ----------------
__global__ __launch_bounds__(256) void proj_kernel(const float* __restrict__ ss,
                                                   const float* __restrict__ ss_w,
                                                   float* __restrict__ proj) {
    __shared__ float w[NH][8];
    int t = threadIdx.x;
    if (t < NH * 8) w[t / 8][t % 8] = ss_w[t];
    __syncthreads();
    int idx = blockIdx.x * blockDim.x + t;
    int h = idx & 15;
    int bl = idx >> 4;
    const float* s = ss + bl * 8;
    float acc = 0.f;
#pragma unroll
    for (int c = 0; c < 8; c++) acc += s[c] * w[h][c];
    proj[idx] = acc;
}

// ---------------- shared bias tensor ----------------
__global__ __launch_bounds__(1024) void bias_kernel(const float* __restrict__ pf,
                                                    const int* __restrict__ ids,
                                                    const float* __restrict__ inter_mat,
                                                    const float* __restrict__ projp,
                                                    const float* __restrict__ physics_scale,
                                                    const float* __restrict__ distance_decay,
                                                    float* __restrict__ biasout) {
    __shared__ float sym[NAA * NAA];
    __shared__ float pi[32][17];
    __shared__ float pj[32][17];
    __shared__ int idi[32], idj[32];

    const int b = blockIdx.z;
    const int i0 = blockIdx.y * 32;
    const int j0 = blockIdx.x * 32;
    const int t = threadIdx.y * 32 + threadIdx.x;

    for (int s = t; s < NAA * NAA; s += 1024) {
        int r = s / NAA, c = s % NAA;
        sym[s] = 0.5f * (inter_mat[r * NAA + c] + inter_mat[c * NAA + r]);
    }
    if (t < 32)       idi[t]      = min(max(ids[b * LEN + i0 + t], 0), NAA - 1);
    else if (t < 64)  idj[t - 32] = min(max(ids[b * LEN + j0 + (t - 32)], 0), NAA - 1);
    if (t < 512) {
        int r = t / 16, c = t % 16;
        pi[r][c] = projp[(b * LEN + i0 + r) * NH + c];
    } else {
        int u = t - 512;
        int r = u / 16, c = u % 16;
        pj[r][c] = projp[(b * LEN + j0 + r) * NH + c];
    }
    __syncthreads();

    const int i = threadIdx.y, j = threadIdx.x;
    float decay = fminf(fmaxf(distance_decay[0], 0.1f), 5.0f);
    float sig = 1.0f / (1.0f + __expf(-physics_scale[0]));

    float d = pf[(size_t)b * LEN * LEN + (size_t)(i0 + i) * LEN + (j0 + j)];
    d = fminf(fmaxf(d, 0.1f), 50.0f);
    float pen = -__powf(d, decay) * sig;

    float it = sym[idi[i] * NAA + idj[j]] *
               (1.0f / (1.0f + fabsf((float)(i0 + i) - (float)(j0 + j))));

    float dot = 0.f;
#pragma unroll
    for (int hh = 0; hh < NH; hh++) dot += pi[i][hh] * pj[j][hh];
    float st = 1.0f / (1.0f + __expf(-dot)) - 0.5f;

    biasout[(size_t)b * LEN * LEN + (size_t)(i0 + i) * LEN + (j0 + j)] = pen + it + st;
}

// ---------------- flash attention (fp32 SIMT; unchanged) ----------------
__global__ __launch_bounds__(256)
void attn_kernel(const float* __restrict__ qkv, const float* __restrict__ biasp,
                 const float* __restrict__ dist_bias, float* __restrict__ ctx) {
    extern __shared__ float smf[];
    float* Qs = smf;
    float* Ks = smf + 4096;
    float* Vs = smf + 4096 + 4160;

    const int t = threadIdx.x;
    const int ty = t >> 4, tx = t & 15;
    const int i0 = blockIdx.x * 64;
    const int h = blockIdx.y;
    const int b = blockIdx.z;
    const float db = dist_bias[h];

    {
        int r = t >> 2, c0 = (t & 3) * 16;
        const float* qp = qkv + (size_t)(b * LEN + i0 + r) * 3072 + h * 64 + c0;
#pragma unroll
        for (int c = 0; c < 16; c += 4) {
            float4 v = *(const float4*)(qp + c);
            Qs[r * 64 + c0 + c] = v.x; Qs[r * 64 + c0 + c + 1] = v.y;
            Qs[r * 64 + c0 + c + 2] = v.z; Qs[r * 64 + c0 + c + 3] = v.w;
        }
    }

    float m[4], l[4], O[4][4];
#pragma unroll
    for (int ri = 0; ri < 4; ri++) {
        m[ri] = -3.0e38f; l[ri] = 0.f;
#pragma unroll
        for (int dj = 0; dj < 4; dj++) O[ri][dj] = 0.f;
    }

    const float* brow = biasp + (size_t)b * LEN * LEN + (size_t)i0 * LEN;

    for (int jt = 0; jt < 16; jt++) {
        const int j0 = jt * 64;
        __syncthreads();
        {
            int r = t >> 2, c0 = (t & 3) * 16;
            const float* kp = qkv + (size_t)(b * LEN + j0 + r) * 3072 + DM + h * 64 + c0;
            const float* vp = kp + DM;
#pragma unroll
            for (int c = 0; c < 16; c += 4) {
                float4 kv4 = *(const float4*)(kp + c);
                Ks[r * 65 + c0 + c] = kv4.x; Ks[r * 65 + c0 + c + 1] = kv4.y;
                Ks[r * 65 + c0 + c + 2] = kv4.z; Ks[r * 65 + c0 + c + 3] = kv4.w;
                float4 vv4 = *(const float4*)(vp + c);
                Vs[r * 64 + c0 + c] = vv4.x; Vs[r * 64 + c0 + c + 1] = vv4.y;
                Vs[r * 64 + c0 + c + 2] = vv4.z; Vs[r * 64 + c0 + c + 3] = vv4.w;
            }
        }
        __syncthreads();

        float s[4][4];
#pragma unroll
        for (int ri = 0; ri < 4; ri++)
#pragma unroll
            for (int cj = 0; cj < 4; cj++) s[ri][cj] = 0.f;

        for (int d = 0; d < 64; d++) {
            float qv[4], kv[4];
#pragma unroll
            for (int ri = 0; ri < 4; ri++) qv[ri] = Qs[(ty + 16 * ri) * 64 + d];
#pragma unroll
            for (int cj = 0; cj < 4; cj++) kv[cj] = Ks[(tx + 16 * cj) * 65 + d];
#pragma unroll
            for (int ri = 0; ri < 4; ri++)
#pragma unroll
                for (int cj = 0; cj < 4; cj++) s[ri][cj] += qv[ri] * kv[cj];
        }
        __syncthreads();

#pragma unroll
        for (int ri = 0; ri < 4; ri++) {
            const int row = ty + 16 * ri;
            float sv[4];
            float mx = -3.0e38f;
#pragma unroll
            for (int cj = 0; cj < 4; cj++) {
                float v = s[ri][cj] * 0.125f +
                          brow[(size_t)row * LEN + j0 + tx + 16 * cj] + db;
                sv[cj] = v;
                mx = fmaxf(mx, v);
            }
#pragma unroll
            for (int off = 8; off >= 1; off >>= 1)
                mx = fmaxf(mx, __shfl_xor_sync(0xffffffffu, mx, off, 16));
            float mnew = fmaxf(m[ri], mx);
            float fac = expf(m[ri] - mnew);
            float sum = 0.f;
#pragma unroll
            for (int cj = 0; cj < 4; cj++) {
                float p = expf(sv[cj] - mnew);
                Ks[row * 65 + tx + 16 * cj] = p;
                sum += p;
            }
#pragma unroll
            for (int off = 8; off >= 1; off >>= 1)
                sum += __shfl_xor_sync(0xffffffffu, sum, off, 16);
            l[ri] = l[ri] * fac + sum;
            m[ri] = mnew;
#pragma unroll
            for (int dj = 0; dj < 4; dj++) O[ri][dj] *= fac;
        }
        __syncthreads();

        for (int j = 0; j < 64; j++) {
            float pv[4], vv[4];
#pragma unroll
            for (int ri = 0; ri < 4; ri++) pv[ri] = Ks[(ty + 16 * ri) * 65 + j];
#pragma unroll
            for (int dj = 0; dj < 4; dj++) vv[dj] = Vs[j * 64 + tx + 16 * dj];
#pragma unroll
            for (int ri = 0; ri < 4; ri++)
#pragma unroll
                for (int dj = 0; dj < 4; dj++) O[ri][dj] += pv[ri] * vv[dj];
        }
    }

#pragma unroll
    for (int ri = 0; ri < 4; ri++) {
        float inv = 1.0f / l[ri];
        int row = i0 + ty + 16 * ri;
        float* cp = ctx + (size_t)(b * LEN + row) * DM + h * 64 + tx;
#pragma unroll
        for (int dj = 0; dj < 4; dj++) cp[16 * dj] = O[ri][dj] * inv;
    }
}

// ---------------- launch ----------------
extern "C" void kernel_launch(void* const* d_in, const int* in_sizes, int n_in,
                              void* d_out, int out_size) {
    const float* x              = (const float*)d_in[0];
    const float* pf             = (const float*)d_in[1];
    const int*   ids            = (const int*)d_in[2];
    const float* ss             = (const float*)d_in[3];
    const float* Wq             = (const float*)d_in[4];
    const float* Wk             = (const float*)d_in[5];
    const float* Wv             = (const float*)d_in[6];
    const float* Wo             = (const float*)d_in[7];
    const float* bo             = (const float*)d_in[8];
    const float* dist_bias      = (const float*)d_in[9];
    const float* inter_mat      = (const float*)d_in[10];
    const float* ss_w           = (const float*)d_in[11];
    const float* physics_scale  = (const float*)d_in[12];
    const float* distance_decay = (const float*)d_in[13];
    float* out = (float*)d_out;

    float *qkv, *biasb, *ctx, *proj;
    __nv_bfloat16 *ahi, *alo, *whi, *wlo;
    cudaGetSymbolAddress((void**)&qkv,  g_qkv);
    cudaGetSymbolAddress((void**)&biasb, g_bias);
    cudaGetSymbolAddress((void**)&ctx,  g_ctx);
    cudaGetSymbolAddress((void**)&proj, g_proj);
    cudaGetSymbolAddress((void**)&ahi,  g_a_hi);
    cudaGetSymbolAddress((void**)&alo,  g_a_lo);
    cudaGetSymbolAddress((void**)&whi,  g_w_hi);
    cudaGetSymbolAddress((void**)&wlo,  g_w_lo);

    cudaFuncSetAttribute(attn_kernel, cudaFuncAttributeMaxDynamicSharedMemorySize, 49408);
    cudaFuncSetAttribute(gemm_mma, cudaFuncAttributeMaxDynamicSharedMemorySize, 2 * STAGE);

    const int W1M = 1024 * 1024;

    // weight + activation splits (bf16 hi/lo)
    split_kernel<<<1024, 256>>>((const float4*)Wq, (__nv_bfloat162*)(whi),
                                (__nv_bfloat162*)(wlo), W1M / 4);
    split_kernel<<<1024, 256>>>((const float4*)Wk, (__nv_bfloat162*)(whi + W1M),
                                (__nv_bfloat162*)(wlo + W1M), W1M / 4);
    split_kernel<<<1024, 256>>>((const float4*)Wv, (__nv_bfloat162*)(whi + 2 * W1M),
                                (__nv_bfloat162*)(wlo + 2 * W1M), W1M / 4);
    split_kernel<<<1024, 256>>>((const float4*)Wo, (__nv_bfloat162*)(whi + 3 * W1M),
                                (__nv_bfloat162*)(wlo + 3 * W1M), W1M / 4);
    split_kernel<<<4096, 256>>>((const float4*)x, (__nv_bfloat162*)ahi,
                                (__nv_bfloat162*)alo, 4 * W1M / 4);

    // bias tensor (independent of GEMMs)
    proj_kernel<<<256, 256>>>(ss, ss_w, proj);
    bias_kernel<<<dim3(32, 32, BSZ), dim3(32, 32)>>>(pf, ids, inter_mat, proj,
                                                     physics_scale, distance_decay, biasb);

    // QKV projection: (4096 x 3072) = x @ [Wq;Wk;Wv]^T
    gemm_mma<<<dim3(24, 32), 256, 2 * STAGE>>>(ahi, alo, whi, wlo, nullptr, qkv, 3072, 0);

    // attention
    attn_kernel<<<dim3(16, 16, BSZ), 256, 49408>>>(qkv, biasb, dist_bias, ctx);

    // out projection: ctx @ Wo^T + bo
    split_kernel<<<4096, 256>>>((const float4*)ctx, (__nv_bfloat162*)ahi,
                                (__nv_bfloat162*)alo, 4 * W1M / 4);
    gemm_mma<<<dim3(8, 32), 256, 2 * STAGE>>>(ahi, alo, whi, wlo, bo, out, 1024, 3072);
}

// round 6
// speedup vs baseline: 2.5566x; 1.5973x over previous
#include <cuda_runtime.h>
#include <cuda_bf16.h>
#include <math.h>
#include <stdint.h>

#define BSZ 4
#define LEN 1024
#define DM 1024
#define NH 16
#define NAA 25

// ---------------- scratch (static device globals; no allocation) ----------------
__device__ float g_bias[BSZ * LEN * LEN];
__device__ float g_proj[BSZ * LEN * NH];
__device__ __nv_bfloat16 g_a_hi[4096 * 1024];   // x split, later ctx split (attn epilogue)
__device__ __nv_bfloat16 g_a_lo[4096 * 1024];
__device__ __nv_bfloat16 g_w_hi[4096 * 1024];   // rows 0-3071 = Wq,Wk,Wv; 3072-4095 = Wo
__device__ __nv_bfloat16 g_w_lo[4096 * 1024];
__device__ __nv_bfloat16 g_qkv_hi[BSZ * LEN * 3 * DM];
__device__ __nv_bfloat16 g_qkv_lo[BSZ * LEN * 3 * DM];

static __device__ __forceinline__ uint32_t smem_u32(const void* p) {
    uint32_t a;
    asm("{ .reg .u64 t; cvta.to.shared.u64 t, %1; cvt.u32.u64 %0, t; }" : "=r"(a) : "l"(p));
    return a;
}
static __device__ __forceinline__ uint32_t pack_bf16(float x, float y) {
    __nv_bfloat162 h;
    h.x = __float2bfloat16(x);
    h.y = __float2bfloat16(y);
    uint32_t u;
    __builtin_memcpy(&u, &h, 4);
    return u;
}

#define LDSM4(r, addr)                                                            \
    asm volatile("ldmatrix.sync.aligned.m8n8.x4.shared.b16 {%0,%1,%2,%3}, [%4];"  \
                 : "=r"((r)[0]), "=r"((r)[1]), "=r"((r)[2]), "=r"((r)[3])         \
                 : "r"(addr))
#define LDSM4T(r, addr)                                                                \
    asm volatile("ldmatrix.sync.aligned.m8n8.x4.trans.shared.b16 {%0,%1,%2,%3}, [%4];" \
                 : "=r"((r)[0]), "=r"((r)[1]), "=r"((r)[2]), "=r"((r)[3])              \
                 : "r"(addr))
#define MMA16816(d, a, b)                                                         \
    asm volatile("mma.sync.aligned.m16n8k16.row.col.f32.bf16.bf16.f32 "           \
                 "{%0,%1,%2,%3}, {%4,%5,%6,%7}, {%8,%9}, {%0,%1,%2,%3};"          \
                 : "+f"((d)[0]), "+f"((d)[1]), "+f"((d)[2]), "+f"((d)[3])         \
                 : "r"((a)[0]), "r"((a)[1]), "r"((a)[2]), "r"((a)[3]),            \
                   "r"((b)[0]), "r"((b)[1]))
#define CPA16(d, g) asm volatile("cp.async.cg.shared.global [%0], [%1], 16;" :: "r"(d), "l"(g))

// ---------------- fp32 -> bf16 hi/lo split ----------------
__global__ __launch_bounds__(256)
void split_kernel(const float4* __restrict__ a, __nv_bfloat162* __restrict__ hi,
                  __nv_bfloat162* __restrict__ lo, int n4) {
    int i = blockIdx.x * blockDim.x + threadIdx.x;
    if (i >= n4) return;
    float4 v = a[i];
    __nv_bfloat16 hx = __float2bfloat16(v.x), hy = __float2bfloat16(v.y);
    __nv_bfloat16 hz = __float2bfloat16(v.z), hw = __float2bfloat16(v.w);
    __nv_bfloat16 lx = __float2bfloat16(v.x - __bfloat162float(hx));
    __nv_bfloat16 ly = __float2bfloat16(v.y - __bfloat162float(hy));
    __nv_bfloat16 lz = __float2bfloat16(v.z - __bfloat162float(hz));
    __nv_bfloat16 lw = __float2bfloat16(v.w - __bfloat162float(hw));
    hi[2 * i]     = __halves2bfloat162(hx, hy);
    hi[2 * i + 1] = __halves2bfloat162(hz, hw);
    lo[2 * i]     = __halves2bfloat162(lx, ly);
    lo[2 * i + 1] = __halves2bfloat162(lz, lw);
}

// ---------------- HMMA split-bf16 GEMM: C[M,N] = A[M,K] @ W[N,K]^T ----------------
// Output either fp32 (+bias) via Cf, or bf16 hi/lo split via Chi/Clo.
#define RS 80
#define TEN 10240
#define STAGE 40960
#define NCH 32

__global__ __launch_bounds__(256, 1)
void gemm_mma(const __nv_bfloat16* __restrict__ Ah, const __nv_bfloat16* __restrict__ Al,
              const __nv_bfloat16* __restrict__ Wh, const __nv_bfloat16* __restrict__ Wl,
              const float* __restrict__ bias, float* __restrict__ Cf,
              __nv_bfloat16* __restrict__ Chi, __nv_bfloat16* __restrict__ Clo,
              int N, int wrow0) {
    extern __shared__ char sm[];
    const uint32_t sb = smem_u32(sm);
    const int t = threadIdx.x, wid = t >> 5, lane = t & 31;
    const int m0 = blockIdx.y << 7, n0 = blockIdx.x << 7;
    const int wm = wid & 1, wn = wid >> 1;

    const char* gsrc[4];
    gsrc[0] = (const char*)(Ah + (size_t)m0 * 1024);
    gsrc[1] = (const char*)(Al + (size_t)m0 * 1024);
    gsrc[2] = (const char*)(Wh + (size_t)(wrow0 + n0) * 1024);
    gsrc[3] = (const char*)(Wl + (size_t)(wrow0 + n0) * 1024);

    const int mat = lane >> 3, lr = lane & 7;
    const uint32_t a_off = (uint32_t)((((mat & 1) << 3) + lr) * RS + ((mat >> 1) << 4));
    const uint32_t b_off = (uint32_t)((((mat >> 1) << 3) + lr) * RS + ((mat & 1) << 4));

    auto load_stage = [&](int st, int c) {
        uint32_t dbase = sb + st * STAGE;
#pragma unroll
        for (int q = 0; q < 4; q++) {
#pragma unroll
            for (int h = 0; h < 2; h++) {
                int idx = t + h * 256;
                int row = idx >> 2, seg = idx & 3;
                const char* g = gsrc[q] + (size_t)row * 2048 + c * 64 + seg * 16;
                uint32_t d = dbase + q * TEN + row * RS + seg * 16;
                CPA16(d, g);
            }
        }
        asm volatile("cp.async.commit_group;" ::: "memory");
    };

    float acc[4][4][4];
#pragma unroll
    for (int i = 0; i < 4; i++)
#pragma unroll
        for (int j = 0; j < 4; j++)
#pragma unroll
            for (int k = 0; k < 4; k++) acc[i][j][k] = 0.f;

    load_stage(0, 0);

    for (int c = 0; c < NCH; c++) {
        const int st = c & 1;
        if (c + 1 < NCH) {
            load_stage(st ^ 1, c + 1);
            asm volatile("cp.async.wait_group 1;" ::: "memory");
        } else {
            asm volatile("cp.async.wait_group 0;" ::: "memory");
        }
        __syncthreads();

        const uint32_t abase = sb + st * STAGE;
#pragma unroll
        for (int k16 = 0; k16 < 2; k16++) {
            uint32_t ah[4][4], al[4][4], bh[4][2], bl[4][2];
#pragma unroll
            for (int mt = 0; mt < 4; mt++) {
                uint32_t addr = abase + (wm * 64 + mt * 16) * RS + k16 * 32 + a_off;
                LDSM4(ah[mt], addr);
                LDSM4(al[mt], addr + TEN);
            }
#pragma unroll
            for (int p = 0; p < 2; p++) {
                uint32_t addr = abase + 2 * TEN + (wn * 32 + p * 16) * RS + k16 * 32 + b_off;
                uint32_t r[4];
                LDSM4(r, addr);
                bh[2 * p][0] = r[0]; bh[2 * p][1] = r[1];
                bh[2 * p + 1][0] = r[2]; bh[2 * p + 1][1] = r[3];
                LDSM4(r, addr + TEN);
                bl[2 * p][0] = r[0]; bl[2 * p][1] = r[1];
                bl[2 * p + 1][0] = r[2]; bl[2 * p + 1][1] = r[3];
            }
#pragma unroll
            for (int mt = 0; mt < 4; mt++)
#pragma unroll
                for (int nt = 0; nt < 4; nt++) {
                    MMA16816(acc[mt][nt], ah[mt], bh[nt]);
                    MMA16816(acc[mt][nt], ah[mt], bl[nt]);
                    MMA16816(acc[mt][nt], al[mt], bh[nt]);
                }
        }
        __syncthreads();
    }

    const int qrow = lane >> 2, qcol = (lane & 3) * 2;
#pragma unroll
    for (int mt = 0; mt < 4; mt++) {
        const int r0 = m0 + wm * 64 + mt * 16 + qrow;
#pragma unroll
        for (int nt = 0; nt < 4; nt++) {
            const int col = n0 + wn * 32 + nt * 8 + qcol;
            if (Cf) {
                float bx = 0.f, by = 0.f;
                if (bias) { bx = bias[col]; by = bias[col + 1]; }
                *(float2*)(Cf + (size_t)r0 * N + col) =
                    make_float2(acc[mt][nt][0] + bx, acc[mt][nt][1] + by);
                *(float2*)(Cf + (size_t)(r0 + 8) * N + col) =
                    make_float2(acc[mt][nt][2] + bx, acc[mt][nt][3] + by);
            } else {
#pragma unroll
                for (int rr = 0; rr < 2; rr++) {
                    float vx = acc[mt][nt][2 * rr], vy = acc[mt][nt][2 * rr + 1];
                    __nv_bfloat16 hx = __float2bfloat16(vx), hy = __float2bfloat16(vy);
                    float lx = vx - __bfloat162float(hx), ly = vy - __bfloat162float(hy);
                    size_t off = (size_t)(r0 + rr * 8) * N + col;
                    *(uint32_t*)(Chi + off) = pack_bf16(__bfloat162float(hx), __bfloat162float(hy));
                    *(uint32_t*)(Clo + off) = pack_bf16(lx, ly);
                }
            }
        }
    }
}

// ---------------- proj = secondary_structure @ ss_w^T ----------------
__global__ __launch_bounds__(256) void proj_kernel(const float* __restrict__ ss,
                                                   const float* __restrict__ ss_w,
                                                   float* __restrict__ proj) {
    __shared__ float w[NH][8];
    int t = threadIdx.x;
    if (t < NH * 8) w[t / 8][t % 8] = ss_w[t];
    __syncthreads();
    int idx = blockIdx.x * blockDim.x + t;
    int h = idx & 15;
    int bl = idx >> 4;
    const float* s = ss + bl * 8;
    float acc = 0.f;
#pragma unroll
    for (int c = 0; c < 8; c++) acc += s[c] * w[h][c];
    proj[idx] = acc;
}

// ---------------- shared bias tensor ----------------
__global__ __launch_bounds__(1024) void bias_kernel(const float* __restrict__ pf,
                                                    const int* __restrict__ ids,
                                                    const float* __restrict__ inter_mat,
                                                    const float* __restrict__ projp,
                                                    const float* __restrict__ physics_scale,
                                                    const float* __restrict__ distance_decay,
                                                    float* __restrict__ biasout) {
    __shared__ float sym[NAA * NAA];
    __shared__ float pi[32][17];
    __shared__ float pj[32][17];
    __shared__ int idi[32], idj[32];

    const int b = blockIdx.z;
    const int i0 = blockIdx.y * 32;
    const int j0 = blockIdx.x * 32;
    const int t = threadIdx.y * 32 + threadIdx.x;

    for (int s = t; s < NAA * NAA; s += 1024) {
        int r = s / NAA, c = s % NAA;
        sym[s] = 0.5f * (inter_mat[r * NAA + c] + inter_mat[c * NAA + r]);
    }
    if (t < 32)       idi[t]      = min(max(ids[b * LEN + i0 + t], 0), NAA - 1);
    else if (t < 64)  idj[t - 32] = min(max(ids[b * LEN + j0 + (t - 32)], 0), NAA - 1);
    if (t < 512) {
        int r = t / 16, c = t % 16;
        pi[r][c] = projp[(b * LEN + i0 + r) * NH + c];
    } else {
        int u = t - 512;
        int r = u / 16, c = u % 16;
        pj[r][c] = projp[(b * LEN + j0 + r) * NH + c];
    }
    __syncthreads();

    const int i = threadIdx.y, j = threadIdx.x;
    float decay = fminf(fmaxf(distance_decay[0], 0.1f), 5.0f);
    float sig = 1.0f / (1.0f + __expf(-physics_scale[0]));

    float d = pf[(size_t)b * LEN * LEN + (size_t)(i0 + i) * LEN + (j0 + j)];
    d = fminf(fmaxf(d, 0.1f), 50.0f);
    float pen = -__powf(d, decay) * sig;

    float it = sym[idi[i] * NAA + idj[j]] *
               (1.0f / (1.0f + fabsf((float)(i0 + i) - (float)(j0 + j))));

    float dot = 0.f;
#pragma unroll
    for (int hh = 0; hh < NH; hh++) dot += pi[i][hh] * pj[j][hh];
    float st = 1.0f / (1.0f + __expf(-dot)) - 0.5f;

    biasout[(size_t)b * LEN * LEN + (size_t)(i0 + i) * LEN + (j0 + j)] = pen + it + st;
}

// ---------------- HMMA flash attention ----------------
// 128 q-rows per CTA, 8 warps x 16 rows, j-tiles of 64, bf16 hi/lo 3-pass MMA.
#define ARS 144
#define QBYTES (128 * ARS)       // 18432 per Q tensor
#define KVT 9216                 // 64 * ARS per tensor
#define KVSTAGE (4 * KVT)        // Khi,Klo,Vhi,Vlo
#define ATTN_SMEM (2 * QBYTES + 2 * KVSTAGE)   // 110592

__global__ __launch_bounds__(256, 1)
void attn_mma(const __nv_bfloat16* __restrict__ qkvhi, const __nv_bfloat16* __restrict__ qkvlo,
              const float* __restrict__ biasp, const float* __restrict__ dist_bias,
              __nv_bfloat16* __restrict__ ctxhi, __nv_bfloat16* __restrict__ ctxlo) {
    extern __shared__ char sm[];
    const uint32_t sb = smem_u32(sm);
    const int t = threadIdx.x, wid = t >> 5, lane = t & 31;
    const int i0 = blockIdx.x * 128, h = blockIdx.y, b = blockIdx.z;
    const float db = dist_bias[h];

    const int mat = lane >> 3, lr = lane & 7;
    const uint32_t a_off = (uint32_t)((((mat & 1) << 3) + lr) * ARS + ((mat >> 1) << 4));
    const uint32_t b_off = (uint32_t)((((mat >> 1) << 3) + lr) * ARS + ((mat & 1) << 4));
    const uint32_t v_off = (uint32_t)((lane & 15) * ARS + ((lane >> 4) << 4));

    // Q tile: 2 tensors x 128 rows x 8 chunks
#pragma unroll
    for (int i = 0; i < 8; i++) {
        int idx = t + i * 256;
        int tensor = idx >> 10;
        int row = (idx >> 3) & 127;
        int seg = idx & 7;
        const __nv_bfloat16* src = tensor ? qkvlo : qkvhi;
        const char* g = (const char*)(src + (size_t)(b * LEN + i0 + row) * 3072 + h * 64) + seg * 16;
        CPA16(sb + tensor * QBYTES + row * ARS + seg * 16, g);
    }
    auto load_kv = [&](int st, int jt) {
        int j0 = jt * 64;
#pragma unroll
        for (int i = 0; i < 8; i++) {
            int idx = t + i * 256;
            int tensor = idx >> 9;           // 0 Khi, 1 Klo, 2 Vhi, 3 Vlo
            int row = (idx >> 3) & 63;
            int seg = idx & 7;
            const __nv_bfloat16* src = (tensor & 1) ? qkvlo : qkvhi;
            int coloff = 1024 + ((tensor >> 1) << 10) + h * 64;
            const char* g = (const char*)(src + (size_t)(b * LEN + j0 + row) * 3072 + coloff) + seg * 16;
            CPA16(sb + 2 * QBYTES + st * KVSTAGE + tensor * KVT + row * ARS + seg * 16, g);
        }
        asm volatile("cp.async.commit_group;" ::: "memory");
    };
    load_kv(0, 0);   // Q chunks + KV0 in one group

    float O[8][4];
#pragma unroll
    for (int f = 0; f < 8; f++)
#pragma unroll
        for (int k = 0; k < 4; k++) O[f][k] = 0.f;
    float m0r = -3.0e38f, m1r = -3.0e38f, l0 = 0.f, l1 = 0.f;

    const int r0 = lane >> 2, c0 = (lane & 3) * 2;
    const float* bp = biasp + ((size_t)b * LEN + i0 + wid * 16) * LEN;

    for (int jt = 0; jt < 16; jt++) {
        const int st = jt & 1;
        if (jt + 1 < 16) {
            load_kv(st ^ 1, jt + 1);
            asm volatile("cp.async.wait_group 1;" ::: "memory");
        } else {
            asm volatile("cp.async.wait_group 0;" ::: "memory");
        }
        __syncthreads();

        // bias prefetch (L2-resident fp32), latency hidden under S MMAs
        float2 bpre[8][2];
        {
            const float* bj = bp + jt * 64 + c0;
#pragma unroll
            for (int f = 0; f < 8; f++) {
                bpre[f][0] = *(const float2*)(bj + (size_t)r0 * LEN + f * 8);
                bpre[f][1] = *(const float2*)(bj + (size_t)(r0 + 8) * LEN + f * 8);
            }
        }

        // S = Q K^T (3-pass split)
        float sacc[8][4];
#pragma unroll
        for (int f = 0; f < 8; f++)
#pragma unroll
            for (int k = 0; k < 4; k++) sacc[f][k] = 0.f;

        const uint32_t kb = sb + 2 * QBYTES + st * KVSTAGE;
#pragma unroll
        for (int kk = 0; kk < 4; kk++) {
            uint32_t ah[4], al[4];
            uint32_t qaddr = sb + (wid * 16) * ARS + kk * 32 + a_off;
            LDSM4(ah, qaddr);
            LDSM4(al, qaddr + QBYTES);
#pragma unroll
            for (int p = 0; p < 4; p++) {
                uint32_t rh[4], rl[4];
                uint32_t kaddr = kb + (p * 16) * ARS + kk * 32 + b_off;
                LDSM4(rh, kaddr);
                LDSM4(rl, kaddr + KVT);
                uint32_t bh0[2] = {rh[0], rh[1]}, bh1[2] = {rh[2], rh[3]};
                uint32_t bl0[2] = {rl[0], rl[1]}, bl1[2] = {rl[2], rl[3]};
                MMA16816(sacc[2 * p], ah, bh0);
                MMA16816(sacc[2 * p], al, bh0);
                MMA16816(sacc[2 * p], ah, bl0);
                MMA16816(sacc[2 * p + 1], ah, bh1);
                MMA16816(sacc[2 * p + 1], al, bh1);
                MMA16816(sacc[2 * p + 1], ah, bl1);
            }
        }

        // bias + online softmax
        float mx0 = -3.0e38f, mx1 = -3.0e38f;
#pragma unroll
        for (int f = 0; f < 8; f++) {
            sacc[f][0] = sacc[f][0] * 0.125f + bpre[f][0].x + db;
            sacc[f][1] = sacc[f][1] * 0.125f + bpre[f][0].y + db;
            sacc[f][2] = sacc[f][2] * 0.125f + bpre[f][1].x + db;
            sacc[f][3] = sacc[f][3] * 0.125f + bpre[f][1].y + db;
            mx0 = fmaxf(mx0, fmaxf(sacc[f][0], sacc[f][1]));
            mx1 = fmaxf(mx1, fmaxf(sacc[f][2], sacc[f][3]));
        }
        mx0 = fmaxf(mx0, __shfl_xor_sync(0xffffffffu, mx0, 1));
        mx0 = fmaxf(mx0, __shfl_xor_sync(0xffffffffu, mx0, 2));
        mx1 = fmaxf(mx1, __shfl_xor_sync(0xffffffffu, mx1, 1));
        mx1 = fmaxf(mx1, __shfl_xor_sync(0xffffffffu, mx1, 2));

        float mn0 = fmaxf(m0r, mx0), mn1 = fmaxf(m1r, mx1);
        float fac0 = __expf(m0r - mn0), fac1 = __expf(m1r - mn1);
        m0r = mn0; m1r = mn1;

        uint32_t pa_hi[4][4], pa_lo[4][4];
        float sum0 = 0.f, sum1 = 0.f;
#pragma unroll
        for (int f = 0; f < 8; f++) {
            float p0 = __expf(sacc[f][0] - mn0);
            float p1 = __expf(sacc[f][1] - mn0);
            float p2 = __expf(sacc[f][2] - mn1);
            float p3 = __expf(sacc[f][3] - mn1);
            sum0 += p0 + p1; sum1 += p2 + p3;
            __nv_bfloat16 h0 = __float2bfloat16(p0), h1 = __float2bfloat16(p1);
            __nv_bfloat16 h2 = __float2bfloat16(p2), h3 = __float2bfloat16(p3);
            int jc = f >> 1, half = (f & 1) << 1;
            pa_hi[jc][half]     = pack_bf16(__bfloat162float(h0), __bfloat162float(h1));
            pa_hi[jc][half + 1] = pack_bf16(__bfloat162float(h2), __bfloat162float(h3));
            pa_lo[jc][half]     = pack_bf16(p0 - __bfloat162float(h0), p1 - __bfloat162float(h1));
            pa_lo[jc][half + 1] = pack_bf16(p2 - __bfloat162float(h2), p3 - __bfloat162float(h3));
        }
        sum0 += __shfl_xor_sync(0xffffffffu, sum0, 1);
        sum0 += __shfl_xor_sync(0xffffffffu, sum0, 2);
        sum1 += __shfl_xor_sync(0xffffffffu, sum1, 1);
        sum1 += __shfl_xor_sync(0xffffffffu, sum1, 2);
        l0 = l0 * fac0 + sum0;
        l1 = l1 * fac1 + sum1;

#pragma unroll
        for (int f = 0; f < 8; f++) {
            O[f][0] *= fac0; O[f][1] *= fac0;
            O[f][2] *= fac1; O[f][3] *= fac1;
        }

        // O += P V (3-pass split), V via ldmatrix.trans
        const uint32_t vb = kb + 2 * KVT;
#pragma unroll
        for (int jc = 0; jc < 4; jc++) {
#pragma unroll
            for (int dbk = 0; dbk < 4; dbk++) {
                uint32_t rh[4], rl[4];
                uint32_t vaddr = vb + (jc * 16) * ARS + dbk * 32 + v_off;
                LDSM4T(rh, vaddr);
                LDSM4T(rl, vaddr + KVT);
                uint32_t bh0[2] = {rh[0], rh[1]}, bh1[2] = {rh[2], rh[3]};
                uint32_t bl0[2] = {rl[0], rl[1]}, bl1[2] = {rl[2], rl[3]};
                MMA16816(O[2 * dbk], pa_hi[jc], bh0);
                MMA16816(O[2 * dbk], pa_lo[jc], bh0);
                MMA16816(O[2 * dbk], pa_hi[jc], bl0);
                MMA16816(O[2 * dbk + 1], pa_hi[jc], bh1);
                MMA16816(O[2 * dbk + 1], pa_lo[jc], bh1);
                MMA16816(O[2 * dbk + 1], pa_hi[jc], bl1);
            }
        }
        __syncthreads();   // all warps done with stage st before it is reloaded
    }

    // epilogue: normalize, split to bf16 hi/lo, store ctx (row-major (B*L) x 1024)
    const float inv0 = 1.0f / l0, inv1 = 1.0f / l1;
    const size_t row0 = (size_t)(b * LEN + i0 + wid * 16 + r0) * DM;
    const size_t row1 = row0 + 8 * DM;
    const int colb = h * 64 + c0;
#pragma unroll
    for (int f = 0; f < 8; f++) {
        float v0 = O[f][0] * inv0, v1 = O[f][1] * inv0;
        float v2 = O[f][2] * inv1, v3 = O[f][3] * inv1;
        __nv_bfloat16 h0 = __float2bfloat16(v0), h1 = __float2bfloat16(v1);
        __nv_bfloat16 h2 = __float2bfloat16(v2), h3 = __float2bfloat16(v3);
        *(uint32_t*)(ctxhi + row0 + colb + f * 8) = pack_bf16(__bfloat162float(h0), __bfloat162float(h1));
        *(uint32_t*)(ctxhi + row1 + colb + f * 8) = pack_bf16(__bfloat162float(h2), __bfloat162float(h3));
        *(uint32_t*)(ctxlo + row0 + colb + f * 8) = pack_bf16(v0 - __bfloat162float(h0), v1 - __bfloat162float(h1));
        *(uint32_t*)(ctxlo + row1 + colb + f * 8) = pack_bf16(v2 - __bfloat162float(h2), v3 - __bfloat162float(h3));
    }
}

// ---------------- launch ----------------
extern "C" void kernel_launch(void* const* d_in, const int* in_sizes, int n_in,
                              void* d_out, int out_size) {
    const float* x              = (const float*)d_in[0];
    const float* pf             = (const float*)d_in[1];
    const int*   ids            = (const int*)d_in[2];
    const float* ss             = (const float*)d_in[3];
    const float* Wq             = (const float*)d_in[4];
    const float* Wk             = (const float*)d_in[5];
    const float* Wv             = (const float*)d_in[6];
    const float* Wo             = (const float*)d_in[7];
    const float* bo             = (const float*)d_in[8];
    const float* dist_bias      = (const float*)d_in[9];
    const float* inter_mat      = (const float*)d_in[10];
    const float* ss_w           = (const float*)d_in[11];
    const float* physics_scale  = (const float*)d_in[12];
    const float* distance_decay = (const float*)d_in[13];
    float* out = (float*)d_out;

    float *biasb, *proj;
    __nv_bfloat16 *ahi, *alo, *whi, *wlo, *qh, *ql;
    cudaGetSymbolAddress((void**)&biasb, g_bias);
    cudaGetSymbolAddress((void**)&proj, g_proj);
    cudaGetSymbolAddress((void**)&ahi,  g_a_hi);
    cudaGetSymbolAddress((void**)&alo,  g_a_lo);
    cudaGetSymbolAddress((void**)&whi,  g_w_hi);
    cudaGetSymbolAddress((void**)&wlo,  g_w_lo);
    cudaGetSymbolAddress((void**)&qh,   g_qkv_hi);
    cudaGetSymbolAddress((void**)&ql,   g_qkv_lo);

    cudaFuncSetAttribute(gemm_mma, cudaFuncAttributeMaxDynamicSharedMemorySize, 2 * STAGE);
    cudaFuncSetAttribute(attn_mma, cudaFuncAttributeMaxDynamicSharedMemorySize, ATTN_SMEM);

    const int W1M = 1024 * 1024;

    split_kernel<<<1024, 256>>>((const float4*)Wq, (__nv_bfloat162*)(whi),
                                (__nv_bfloat162*)(wlo), W1M / 4);
    split_kernel<<<1024, 256>>>((const float4*)Wk, (__nv_bfloat162*)(whi + W1M),
                                (__nv_bfloat162*)(wlo + W1M), W1M / 4);
    split_kernel<<<1024, 256>>>((const float4*)Wv, (__nv_bfloat162*)(whi + 2 * W1M),
                                (__nv_bfloat162*)(wlo + 2 * W1M), W1M / 4);
    split_kernel<<<1024, 256>>>((const float4*)Wo, (__nv_bfloat162*)(whi + 3 * W1M),
                                (__nv_bfloat162*)(wlo + 3 * W1M), W1M / 4);
    split_kernel<<<4096, 256>>>((const float4*)x, (__nv_bfloat162*)ahi,
                                (__nv_bfloat162*)alo, 4 * W1M / 4);

    proj_kernel<<<256, 256>>>(ss, ss_w, proj);
    bias_kernel<<<dim3(32, 32, BSZ), dim3(32, 32)>>>(pf, ids, inter_mat, proj,
                                                     physics_scale, distance_decay, biasb);

    // QKV projection -> bf16 hi/lo directly
    gemm_mma<<<dim3(24, 32), 256, 2 * STAGE>>>(ahi, alo, whi, wlo, nullptr,
                                               nullptr, qh, ql, 3072, 0);

    // HMMA flash attention -> ctx hi/lo (overwrites g_a_hi/g_a_lo)
    attn_mma<<<dim3(8, NH, BSZ), 256, ATTN_SMEM>>>(qh, ql, biasb, dist_bias, ahi, alo);

    // out projection: ctx @ Wo^T + bo -> fp32 out
    gemm_mma<<<dim3(8, 32), 256, 2 * STAGE>>>(ahi, alo, whi, wlo, bo,
                                              out, nullptr, nullptr, 1024, 3072);
}

// round 8
// speedup vs baseline: 3.2118x; 1.2563x over previous
#include <cuda_runtime.h>
#include <cuda_fp16.h>
#include <math.h>
#include <stdint.h>

#define BSZ 4
#define LEN 1024
#define DM 1024
#define NH 16
#define NAA 25

// ---------------- scratch (static device globals; no allocation) ----------------
__device__ float g_bias[BSZ * LEN * LEN];
__device__ float g_proj[BSZ * LEN * NH];
__device__ __half g_a_hi[4096 * 1024];          // x split, later ctx split
__device__ __half g_a_lo[4096 * 1024];
__device__ __half g_w[4096 * 1024];             // rows 0-3071 = Wq,Wk,Wv; 3072-4095 = Wo (single fp16)
__device__ __half g_qkv_hi[BSZ * LEN * 3 * DM];
__device__ __half g_qkv_lo[BSZ * LEN * 3 * DM];

static __device__ __forceinline__ uint32_t smem_u32(const void* p) {
    uint32_t a;
    asm("{ .reg .u64 t; cvta.to.shared.u64 t, %1; cvt.u32.u64 %0, t; }" : "=r"(a) : "l"(p));
    return a;
}
static __device__ __forceinline__ uint32_t pack_h2(float x, float y) {
    __half2 h = __floats2half2_rn(x, y);
    uint32_t u;
    __builtin_memcpy(&u, &h, 4);
    return u;
}
static __device__ __forceinline__ uint32_t pack_hh(__half x, __half y) {
    __half2 h = __halves2half2(x, y);
    uint32_t u;
    __builtin_memcpy(&u, &h, 4);
    return u;
}

#define LDSM4(r, addr)                                                            \
    asm volatile("ldmatrix.sync.aligned.m8n8.x4.shared.b16 {%0,%1,%2,%3}, [%4];"  \
                 : "=r"((r)[0]), "=r"((r)[1]), "=r"((r)[2]), "=r"((r)[3])         \
                 : "r"(addr))
#define LDSM4T(r, addr)                                                                \
    asm volatile("ldmatrix.sync.aligned.m8n8.x4.trans.shared.b16 {%0,%1,%2,%3}, [%4];" \
                 : "=r"((r)[0]), "=r"((r)[1]), "=r"((r)[2]), "=r"((r)[3])              \
                 : "r"(addr))
#define MMA16816(d, a, b)                                                         \
    asm volatile("mma.sync.aligned.m16n8k16.row.col.f32.f16.f16.f32 "             \
                 "{%0,%1,%2,%3}, {%4,%5,%6,%7}, {%8,%9}, {%0,%1,%2,%3};"          \
                 : "+f"((d)[0]), "+f"((d)[1]), "+f"((d)[2]), "+f"((d)[3])         \
                 : "r"((a)[0]), "r"((a)[1]), "r"((a)[2]), "r"((a)[3]),            \
                   "r"((b)[0]), "r"((b)[1]))
#define CPA16(d, g) asm volatile("cp.async.cg.shared.global [%0], [%1], 16;" :: "r"(d), "l"(g))

// ---------------- fp32 -> fp16 hi/lo split ----------------
__global__ __launch_bounds__(256)
void split_kernel(const float4* __restrict__ a, __half2* __restrict__ hi,
                  __half2* __restrict__ lo, int n4) {
    int i = blockIdx.x * blockDim.x + threadIdx.x;
    if (i >= n4) return;
    float4 v = a[i];
    __half hx = __float2half_rn(v.x), hy = __float2half_rn(v.y);
    __half hz = __float2half_rn(v.z), hw = __float2half_rn(v.w);
    hi[2 * i]     = __halves2half2(hx, hy);
    hi[2 * i + 1] = __halves2half2(hz, hw);
    lo[2 * i]     = __floats2half2_rn(v.x - __half2float(hx), v.y - __half2float(hy));
    lo[2 * i + 1] = __floats2half2_rn(v.z - __half2float(hz), v.w - __half2float(hw));
}

// ---------------- fp32 -> fp16 convert (weights, single precision) ----------------
__global__ __launch_bounds__(256)
void conv_kernel(const float4* __restrict__ a, __half2* __restrict__ w, int n4) {
    int i = blockIdx.x * blockDim.x + threadIdx.x;
    if (i >= n4) return;
    float4 v = a[i];
    w[2 * i]     = __floats2half2_rn(v.x, v.y);
    w[2 * i + 1] = __floats2half2_rn(v.z, v.w);
}

// ---------------- HMMA fp16 2-pass GEMM: C[M,N] = (Ah+Al)[M,K] @ W[N,K]^T ----------------
#define RS 80
#define TEN 10240
#define STAGE 30720       // 3 tensors (Ah, Al, W) x 10240
#define NCH 32

__global__ __launch_bounds__(256, 1)
void gemm_mma(const __half* __restrict__ Ah, const __half* __restrict__ Al,
              const __half* __restrict__ W,
              const float* __restrict__ bias, float* __restrict__ Cf,
              __half* __restrict__ Chi, __half* __restrict__ Clo,
              int N, int wrow0) {
    extern __shared__ char sm[];
    const uint32_t sb = smem_u32(sm);
    const int t = threadIdx.x, wid = t >> 5, lane = t & 31;
    const int m0 = blockIdx.y << 7, n0 = blockIdx.x << 7;
    const int wm = wid & 1, wn = wid >> 1;

    const char* gsrc[3];
    gsrc[0] = (const char*)(Ah + (size_t)m0 * 1024);
    gsrc[1] = (const char*)(Al + (size_t)m0 * 1024);
    gsrc[2] = (const char*)(W + (size_t)(wrow0 + n0) * 1024);

    const int mat = lane >> 3, lr = lane & 7;
    const uint32_t a_off = (uint32_t)((((mat & 1) << 3) + lr) * RS + ((mat >> 1) << 4));
    const uint32_t b_off = (uint32_t)((((mat >> 1) << 3) + lr) * RS + ((mat & 1) << 4));

    auto load_stage = [&](int st, int c) {
        uint32_t dbase = sb + st * STAGE;
#pragma unroll
        for (int q = 0; q < 3; q++) {
#pragma unroll
            for (int h = 0; h < 2; h++) {
                int idx = t + h * 256;
                int row = idx >> 2, seg = idx & 3;
                const char* g = gsrc[q] + (size_t)row * 2048 + c * 64 + seg * 16;
                uint32_t d = dbase + q * TEN + row * RS + seg * 16;
                CPA16(d, g);
            }
        }
        asm volatile("cp.async.commit_group;" ::: "memory");
    };

    float acc[4][4][4];
#pragma unroll
    for (int i = 0; i < 4; i++)
#pragma unroll
        for (int j = 0; j < 4; j++)
#pragma unroll
            for (int k = 0; k < 4; k++) acc[i][j][k] = 0.f;

    load_stage(0, 0);

    for (int c = 0; c < NCH; c++) {
        const int st = c & 1;
        if (c + 1 < NCH) {
            load_stage(st ^ 1, c + 1);
            asm volatile("cp.async.wait_group 1;" ::: "memory");
        } else {
            asm volatile("cp.async.wait_group 0;" ::: "memory");
        }
        __syncthreads();

        const uint32_t abase = sb + st * STAGE;
#pragma unroll
        for (int k16 = 0; k16 < 2; k16++) {
            uint32_t ah[4][4], al[4][4], bfrag[4][2];
#pragma unroll
            for (int mt = 0; mt < 4; mt++) {
                uint32_t addr = abase + (wm * 64 + mt * 16) * RS + k16 * 32 + a_off;
                LDSM4(ah[mt], addr);
                LDSM4(al[mt], addr + TEN);
            }
#pragma unroll
            for (int p = 0; p < 2; p++) {
                uint32_t addr = abase + 2 * TEN + (wn * 32 + p * 16) * RS + k16 * 32 + b_off;
                uint32_t r[4];
                LDSM4(r, addr);
                bfrag[2 * p][0] = r[0]; bfrag[2 * p][1] = r[1];
                bfrag[2 * p + 1][0] = r[2]; bfrag[2 * p + 1][1] = r[3];
            }
#pragma unroll
            for (int mt = 0; mt < 4; mt++)
#pragma unroll
                for (int nt = 0; nt < 4; nt++) {
                    MMA16816(acc[mt][nt], ah[mt], bfrag[nt]);
                    MMA16816(acc[mt][nt], al[mt], bfrag[nt]);
                }
        }
        __syncthreads();
    }

    const int qrow = lane >> 2, qcol = (lane & 3) * 2;
#pragma unroll
    for (int mt = 0; mt < 4; mt++) {
        const int r0 = m0 + wm * 64 + mt * 16 + qrow;
#pragma unroll
        for (int nt = 0; nt < 4; nt++) {
            const int col = n0 + wn * 32 + nt * 8 + qcol;
            if (Cf) {
                float bx = 0.f, by = 0.f;
                if (bias) { bx = bias[col]; by = bias[col + 1]; }
                *(float2*)(Cf + (size_t)r0 * N + col) =
                    make_float2(acc[mt][nt][0] + bx, acc[mt][nt][1] + by);
                *(float2*)(Cf + (size_t)(r0 + 8) * N + col) =
                    make_float2(acc[mt][nt][2] + bx, acc[mt][nt][3] + by);
            } else {
#pragma unroll
                for (int rr = 0; rr < 2; rr++) {
                    float vx = acc[mt][nt][2 * rr], vy = acc[mt][nt][2 * rr + 1];
                    __half hx = __float2half_rn(vx), hy = __float2half_rn(vy);
                    size_t off = (size_t)(r0 + rr * 8) * N + col;
                    *(uint32_t*)(Chi + off) = pack_hh(hx, hy);
                    *(uint32_t*)(Clo + off) =
                        pack_h2(vx - __half2float(hx), vy - __half2float(hy));
                }
            }
        }
    }
}

// ---------------- proj = secondary_structure @ ss_w^T ----------------
__global__ __launch_bounds__(256) void proj_kernel(const float* __restrict__ ss,
                                                   const float* __restrict__ ss_w,
                                                   float* __restrict__ proj) {
    __shared__ float w[NH][8];
    int t = threadIdx.x;
    if (t < NH * 8) w[t / 8][t % 8] = ss_w[t];
    __syncthreads();
    int idx = blockIdx.x * blockDim.x + t;
    int h = idx & 15;
    int bl = idx >> 4;
    const float* s = ss + bl * 8;
    float acc = 0.f;
#pragma unroll
    for (int c = 0; c < 8; c++) acc += s[c] * w[h][c];
    proj[idx] = acc;
}

// ---------------- shared bias tensor ----------------
__global__ __launch_bounds__(1024) void bias_kernel(const float* __restrict__ pf,
                                                    const int* __restrict__ ids,
                                                    const float* __restrict__ inter_mat,
                                                    const float* __restrict__ projp,
                                                    const float* __restrict__ physics_scale,
                                                    const float* __restrict__ distance_decay,
                                                    float* __restrict__ biasout) {
    __shared__ float sym[NAA * NAA];
    __shared__ float pi[32][17];
    __shared__ float pj[32][17];
    __shared__ int idi[32], idj[32];

    const int b = blockIdx.z;
    const int i0 = blockIdx.y * 32;
    const int j0 = blockIdx.x * 32;
    const int t = threadIdx.y * 32 + threadIdx.x;

    for (int s = t; s < NAA * NAA; s += 1024) {
        int r = s / NAA, c = s % NAA;
        sym[s] = 0.5f * (inter_mat[r * NAA + c] + inter_mat[c * NAA + r]);
    }
    if (t < 32)       idi[t]      = min(max(ids[b * LEN + i0 + t], 0), NAA - 1);
    else if (t < 64)  idj[t - 32] = min(max(ids[b * LEN + j0 + (t - 32)], 0), NAA - 1);
    if (t < 512) {
        int r = t / 16, c = t % 16;
        pi[r][c] = projp[(b * LEN + i0 + r) * NH + c];
    } else {
        int u = t - 512;
        int r = u / 16, c = u % 16;
        pj[r][c] = projp[(b * LEN + j0 + r) * NH + c];
    }
    __syncthreads();

    const int i = threadIdx.y, j = threadIdx.x;
    float decay = fminf(fmaxf(distance_decay[0], 0.1f), 5.0f);
    float sig = 1.0f / (1.0f + __expf(-physics_scale[0]));

    float d = pf[(size_t)b * LEN * LEN + (size_t)(i0 + i) * LEN + (j0 + j)];
    d = fminf(fmaxf(d, 0.1f), 50.0f);
    float pen = -__powf(d, decay) * sig;

    float it = sym[idi[i] * NAA + idj[j]] *
               (1.0f / (1.0f + fabsf((float)(i0 + i) - (float)(j0 + j))));

    float dot = 0.f;
#pragma unroll
    for (int hh = 0; hh < NH; hh++) dot += pi[i][hh] * pj[j][hh];
    float st = 1.0f / (1.0f + __expf(-dot)) - 0.5f;

    biasout[(size_t)b * LEN * LEN + (size_t)(i0 + i) * LEN + (j0 + j)] = pen + it + st;
}

// ---------------- HMMA fp16 flash attention ----------------
// 128 q-rows per CTA, 8 warps x 16 rows, j-tiles of 64.
// S = (Qh+Ql) K^T (2-pass, K single fp16); O += P (Vh+Vl) (2-pass, P single fp16).
#define ARS 144
#define QBYTES (128 * ARS)       // 18432 per Q tensor
#define KVT 9216                 // 64 * ARS per tensor
#define KVSTAGE (3 * KVT)        // Kh, Vh, Vl
#define ATTN_SMEM (2 * QBYTES + 2 * KVSTAGE)   // 92160

__global__ __launch_bounds__(256, 1)
void attn_mma(const __half* __restrict__ qkvhi, const __half* __restrict__ qkvlo,
              const float* __restrict__ biasp, const float* __restrict__ dist_bias,
              __half* __restrict__ ctxhi, __half* __restrict__ ctxlo) {
    extern __shared__ char sm[];
    const uint32_t sb = smem_u32(sm);
    const int t = threadIdx.x, wid = t >> 5, lane = t & 31;
    const int i0 = blockIdx.x * 128, h = blockIdx.y, b = blockIdx.z;
    const float db = dist_bias[h];

    const int mat = lane >> 3, lr = lane & 7;
    const uint32_t a_off = (uint32_t)((((mat & 1) << 3) + lr) * ARS + ((mat >> 1) << 4));
    const uint32_t b_off = (uint32_t)((((mat >> 1) << 3) + lr) * ARS + ((mat & 1) << 4));
    const uint32_t v_off = (uint32_t)((lane & 15) * ARS + ((lane >> 4) << 4));

    // Q tile: Qh, Ql (2 tensors x 128 rows x 8 chunks)
#pragma unroll
    for (int i = 0; i < 8; i++) {
        int idx = t + i * 256;
        int tensor = idx >> 10;
        int row = (idx >> 3) & 127;
        int seg = idx & 7;
        const __half* src = tensor ? qkvlo : qkvhi;
        const char* g = (const char*)(src + (size_t)(b * LEN + i0 + row) * 3072 + h * 64) + seg * 16;
        CPA16(sb + tensor * QBYTES + row * ARS + seg * 16, g);
    }
    auto load_kv = [&](int st, int jt) {
        int j0 = jt * 64;
#pragma unroll
        for (int i = 0; i < 6; i++) {
            int idx = t + i * 256;
            int tensor = idx >> 9;           // 0 Kh, 1 Vh, 2 Vl
            int row = (idx >> 3) & 63;
            int seg = idx & 7;
            const __half* src = (tensor == 2) ? qkvlo : qkvhi;
            int coloff = (tensor == 0 ? 1024 : 2048) + h * 64;
            const char* g = (const char*)(src + (size_t)(b * LEN + j0 + row) * 3072 + coloff) + seg * 16;
            CPA16(sb + 2 * QBYTES + st * KVSTAGE + tensor * KVT + row * ARS + seg * 16, g);
        }
        asm volatile("cp.async.commit_group;" ::: "memory");
    };
    load_kv(0, 0);

    float O[8][4];
#pragma unroll
    for (int f = 0; f < 8; f++)
#pragma unroll
        for (int k = 0; k < 4; k++) O[f][k] = 0.f;
    float m0r = -3.0e38f, m1r = -3.0e38f, l0 = 0.f, l1 = 0.f;

    const int r0 = lane >> 2, c0 = (lane & 3) * 2;
    const float* bp = biasp + ((size_t)b * LEN + i0 + wid * 16) * LEN;

    for (int jt = 0; jt < 16; jt++) {
        const int st = jt & 1;
        if (jt + 1 < 16) {
            load_kv(st ^ 1, jt + 1);
            asm volatile("cp.async.wait_group 1;" ::: "memory");
        } else {
            asm volatile("cp.async.wait_group 0;" ::: "memory");
        }
        __syncthreads();

        // bias prefetch (L2-resident), latency hidden under S MMAs
        float2 bpre[8][2];
        {
            const float* bj = bp + jt * 64 + c0;
#pragma unroll
            for (int f = 0; f < 8; f++) {
                bpre[f][0] = *(const float2*)(bj + (size_t)r0 * LEN + f * 8);
                bpre[f][1] = *(const float2*)(bj + (size_t)(r0 + 8) * LEN + f * 8);
            }
        }

        // S = Q K^T (2-pass)
        float sacc[8][4];
#pragma unroll
        for (int f = 0; f < 8; f++)
#pragma unroll
            for (int k = 0; k < 4; k++) sacc[f][k] = 0.f;

        const uint32_t kb = sb + 2 * QBYTES + st * KVSTAGE;
#pragma unroll
        for (int kk = 0; kk < 4; kk++) {
            uint32_t ah[4], al[4];
            uint32_t qaddr = sb + (wid * 16) * ARS + kk * 32 + a_off;
            LDSM4(ah, qaddr);
            LDSM4(al, qaddr + QBYTES);
#pragma unroll
            for (int p = 0; p < 4; p++) {
                uint32_t rh[4];
                uint32_t kaddr = kb + (p * 16) * ARS + kk * 32 + b_off;
                LDSM4(rh, kaddr);
                uint32_t b0[2] = {rh[0], rh[1]}, b1[2] = {rh[2], rh[3]};
                MMA16816(sacc[2 * p], ah, b0);
                MMA16816(sacc[2 * p], al, b0);
                MMA16816(sacc[2 * p + 1], ah, b1);
                MMA16816(sacc[2 * p + 1], al, b1);
            }
        }

        // bias + online softmax
        float mx0 = -3.0e38f, mx1 = -3.0e38f;
#pragma unroll
        for (int f = 0; f < 8; f++) {
            sacc[f][0] = sacc[f][0] * 0.125f + bpre[f][0].x + db;
            sacc[f][1] = sacc[f][1] * 0.125f + bpre[f][0].y + db;
            sacc[f][2] = sacc[f][2] * 0.125f + bpre[f][1].x + db;
            sacc[f][3] = sacc[f][3] * 0.125f + bpre[f][1].y + db;
            mx0 = fmaxf(mx0, fmaxf(sacc[f][0], sacc[f][1]));
            mx1 = fmaxf(mx1, fmaxf(sacc[f][2], sacc[f][3]));
        }
        mx0 = fmaxf(mx0, __shfl_xor_sync(0xffffffffu, mx0, 1));
        mx0 = fmaxf(mx0, __shfl_xor_sync(0xffffffffu, mx0, 2));
        mx1 = fmaxf(mx1, __shfl_xor_sync(0xffffffffu, mx1, 1));
        mx1 = fmaxf(mx1, __shfl_xor_sync(0xffffffffu, mx1, 2));

        float mn0 = fmaxf(m0r, mx0), mn1 = fmaxf(m1r, mx1);
        float fac0 = __expf(m0r - mn0), fac1 = __expf(m1r - mn1);
        m0r = mn0; m1r = mn1;

        uint32_t pa[4][4];
        float sum0 = 0.f, sum1 = 0.f;
#pragma unroll
        for (int f = 0; f < 8; f++) {
            float p0 = __expf(sacc[f][0] - mn0);
            float p1 = __expf(sacc[f][1] - mn0);
            float p2 = __expf(sacc[f][2] - mn1);
            float p3 = __expf(sacc[f][3] - mn1);
            sum0 += p0 + p1; sum1 += p2 + p3;
            int jc = f >> 1, half = (f & 1) << 1;
            pa[jc][half]     = pack_h2(p0, p1);
            pa[jc][half + 1] = pack_h2(p2, p3);
        }
        sum0 += __shfl_xor_sync(0xffffffffu, sum0, 1);
        sum0 += __shfl_xor_sync(0xffffffffu, sum0, 2);
        sum1 += __shfl_xor_sync(0xffffffffu, sum1, 1);
        sum1 += __shfl_xor_sync(0xffffffffu, sum1, 2);
        l0 = l0 * fac0 + sum0;
        l1 = l1 * fac1 + sum1;

#pragma unroll
        for (int f = 0; f < 8; f++) {
            O[f][0] *= fac0; O[f][1] *= fac0;
            O[f][2] *= fac1; O[f][3] *= fac1;
        }

        // O += P V (2-pass: V hi + V lo), V via ldmatrix.trans
        const uint32_t vb = kb + KVT;
#pragma unroll
        for (int jc = 0; jc < 4; jc++) {
#pragma unroll
            for (int dbk = 0; dbk < 4; dbk++) {
                uint32_t rh[4], rl[4];
                uint32_t vaddr = vb + (jc * 16) * ARS + dbk * 32 + v_off;
                LDSM4T(rh, vaddr);
                LDSM4T(rl, vaddr + KVT);
                uint32_t bh0[2] = {rh[0], rh[1]}, bh1[2] = {rh[2], rh[3]};
                uint32_t bl0[2] = {rl[0], rl[1]}, bl1[2] = {rl[2], rl[3]};
                MMA16816(O[2 * dbk], pa[jc], bh0);
                MMA16816(O[2 * dbk], pa[jc], bl0);
                MMA16816(O[2 * dbk + 1], pa[jc], bh1);
                MMA16816(O[2 * dbk + 1], pa[jc], bl1);
            }
        }
        __syncthreads();
    }

    // epilogue: normalize, split to fp16 hi/lo, store ctx
    const float inv0 = 1.0f / l0, inv1 = 1.0f / l1;
    const size_t row0 = (size_t)(b * LEN + i0 + wid * 16 + r0) * DM;
    const size_t row1 = row0 + 8 * DM;
    const int colb = h * 64 + c0;
#pragma unroll
    for (int f = 0; f < 8; f++) {
        float v0 = O[f][0] * inv0, v1 = O[f][1] * inv0;
        float v2 = O[f][2] * inv1, v3 = O[f][3] * inv1;
        __half h0 = __float2half_rn(v0), h1 = __float2half_rn(v1);
        __half h2 = __float2half_rn(v2), h3 = __float2half_rn(v3);
        *(uint32_t*)(ctxhi + row0 + colb + f * 8) = pack_hh(h0, h1);
        *(uint32_t*)(ctxhi + row1 + colb + f * 8) = pack_hh(h2, h3);
        *(uint32_t*)(ctxlo + row0 + colb + f * 8) =
            pack_h2(v0 - __half2float(h0), v1 - __half2float(h1));
        *(uint32_t*)(ctxlo + row1 + colb + f * 8) =
            pack_h2(v2 - __half2float(h2), v3 - __half2float(h3));
    }
}

// ---------------- launch ----------------
extern "C" void kernel_launch(void* const* d_in, const int* in_sizes, int n_in,
                              void* d_out, int out_size) {
    const float* x              = (const float*)d_in[0];
    const float* pf             = (const float*)d_in[1];
    const int*   ids            = (const int*)d_in[2];
    const float* ss             = (const float*)d_in[3];
    const float* Wq             = (const float*)d_in[4];
    const float* Wk             = (const float*)d_in[5];
    const float* Wv             = (const float*)d_in[6];
    const float* Wo             = (const float*)d_in[7];
    const float* bo             = (const float*)d_in[8];
    const float* dist_bias      = (const float*)d_in[9];
    const float* inter_mat      = (const float*)d_in[10];
    const float* ss_w           = (const float*)d_in[11];
    const float* physics_scale  = (const float*)d_in[12];
    const float* distance_decay = (const float*)d_in[13];
    float* out = (float*)d_out;

    float *biasb, *proj;
    __half *ahi, *alo, *w, *qh, *ql;
    cudaGetSymbolAddress((void**)&biasb, g_bias);
    cudaGetSymbolAddress((void**)&proj, g_proj);
    cudaGetSymbolAddress((void**)&ahi,  g_a_hi);
    cudaGetSymbolAddress((void**)&alo,  g_a_lo);
    cudaGetSymbolAddress((void**)&w,    g_w);
    cudaGetSymbolAddress((void**)&qh,   g_qkv_hi);
    cudaGetSymbolAddress((void**)&ql,   g_qkv_lo);

    cudaFuncSetAttribute(gemm_mma, cudaFuncAttributeMaxDynamicSharedMemorySize, 2 * STAGE);
    cudaFuncSetAttribute(attn_mma, cudaFuncAttributeMaxDynamicSharedMemorySize, ATTN_SMEM);

    const int W1M = 1024 * 1024;

    conv_kernel<<<1024, 256>>>((const float4*)Wq, (__half2*)(w), W1M / 4);
    conv_kernel<<<1024, 256>>>((const float4*)Wk, (__half2*)(w + W1M), W1M / 4);
    conv_kernel<<<1024, 256>>>((const float4*)Wv, (__half2*)(w + 2 * W1M), W1M / 4);
    conv_kernel<<<1024, 256>>>((const float4*)Wo, (__half2*)(w + 3 * W1M), W1M / 4);
    split_kernel<<<4096, 256>>>((const float4*)x, (__half2*)ahi, (__half2*)alo, 4 * W1M / 4);

    proj_kernel<<<256, 256>>>(ss, ss_w, proj);
    bias_kernel<<<dim3(32, 32, BSZ), dim3(32, 32)>>>(pf, ids, inter_mat, proj,
                                                     physics_scale, distance_decay, biasb);

    // QKV projection -> fp16 hi/lo
    gemm_mma<<<dim3(24, 32), 256, 2 * STAGE>>>(ahi, alo, w, nullptr,
                                               nullptr, qh, ql, 3072, 0);

    // HMMA flash attention -> ctx hi/lo (overwrites g_a_hi/g_a_lo)
    attn_mma<<<dim3(8, NH, BSZ), 256, ATTN_SMEM>>>(qh, ql, biasb, dist_bias, ahi, alo);

    // out projection: ctx @ Wo^T + bo -> fp32 out
    gemm_mma<<<dim3(8, 32), 256, 2 * STAGE>>>(ahi, alo, w, bo,
                                              out, nullptr, nullptr, 1024, 3072);
}

// round 10
// speedup vs baseline: 3.2377x; 1.0081x over previous
#include <cuda_runtime.h>
#include <cuda_fp16.h>
#include <math.h>
#include <stdint.h>

#define BSZ 4
#define LEN 1024
#define DM 1024
#define NH 16
#define NAA 25

// ---------------- scratch (static device globals; no allocation) ----------------
__device__ float g_bias[BSZ * LEN * LEN];
__device__ float g_proj[BSZ * LEN * NH];
__device__ __half g_a_hi[4096 * 1024];          // x split, later ctx split
__device__ __half g_a_lo[4096 * 1024];
__device__ __half g_w[4096 * 1024];             // rows 0-3071 = Wq,Wk,Wv; 3072-4095 = Wo
__device__ __half g_qkv_hi[BSZ * LEN * 3 * DM];
__device__ __half g_qkv_lo[BSZ * LEN * 3 * DM];

static __device__ __forceinline__ uint32_t smem_u32(const void* p) {
    uint32_t a;
    asm("{ .reg .u64 t; cvta.to.shared.u64 t, %1; cvt.u32.u64 %0, t; }" : "=r"(a) : "l"(p));
    return a;
}
static __device__ __forceinline__ uint32_t pack_h2(float x, float y) {
    __half2 h = __floats2half2_rn(x, y);
    uint32_t u;
    __builtin_memcpy(&u, &h, 4);
    return u;
}
static __device__ __forceinline__ uint32_t pack_hh(__half x, __half y) {
    __half2 h = __halves2half2(x, y);
    uint32_t u;
    __builtin_memcpy(&u, &h, 4);
    return u;
}

#define LDSM4(r, addr)                                                            \
    asm volatile("ldmatrix.sync.aligned.m8n8.x4.shared.b16 {%0,%1,%2,%3}, [%4];"  \
                 : "=r"((r)[0]), "=r"((r)[1]), "=r"((r)[2]), "=r"((r)[3])         \
                 : "r"(addr))
#define LDSM4T(r, addr)                                                                \
    asm volatile("ldmatrix.sync.aligned.m8n8.x4.trans.shared.b16 {%0,%1,%2,%3}, [%4];" \
                 : "=r"((r)[0]), "=r"((r)[1]), "=r"((r)[2]), "=r"((r)[3])              \
                 : "r"(addr))
#define MMA16816(d, a, b)                                                         \
    asm volatile("mma.sync.aligned.m16n8k16.row.col.f32.f16.f16.f32 "             \
                 "{%0,%1,%2,%3}, {%4,%5,%6,%7}, {%8,%9}, {%0,%1,%2,%3};"          \
                 : "+f"((d)[0]), "+f"((d)[1]), "+f"((d)[2]), "+f"((d)[3])         \
                 : "r"((a)[0]), "r"((a)[1]), "r"((a)[2]), "r"((a)[3]),            \
                   "r"((b)[0]), "r"((b)[1]))
#define CPA16(d, g) asm volatile("cp.async.cg.shared.global [%0], [%1], 16;" :: "r"(d), "l"(g))

// ---------------- fp32 -> fp16 hi/lo split ----------------
__global__ __launch_bounds__(256)
void split_kernel(const float4* __restrict__ a, __half2* __restrict__ hi,
                  __half2* __restrict__ lo, int n4) {
    int i = blockIdx.x * blockDim.x + threadIdx.x;
    if (i >= n4) return;
    float4 v = a[i];
    __half hx = __float2half_rn(v.x), hy = __float2half_rn(v.y);
    __half hz = __float2half_rn(v.z), hw = __float2half_rn(v.w);
    hi[2 * i]     = __halves2half2(hx, hy);
    hi[2 * i + 1] = __halves2half2(hz, hw);
    lo[2 * i]     = __floats2half2_rn(v.x - __half2float(hx), v.y - __half2float(hy));
    lo[2 * i + 1] = __floats2half2_rn(v.z - __half2float(hz), v.w - __half2float(hw));
}

// ---------------- fused fp32 -> fp16 convert for 4 weight tensors ----------------
__global__ __launch_bounds__(256)
void conv4_kernel(const float4* __restrict__ a0, const float4* __restrict__ a1,
                  const float4* __restrict__ a2, const float4* __restrict__ a3,
                  __half2* __restrict__ w) {
    const int tensor = blockIdx.y;
    const float4* a = (tensor == 0) ? a0 : (tensor == 1) ? a1 : (tensor == 2) ? a2 : a3;
    int i = blockIdx.x * blockDim.x + threadIdx.x;   // 0 .. 262143
    float4 v = a[i];
    __half2* dst = w + (size_t)tensor * 524288;
    dst[2 * i]     = __floats2half2_rn(v.x, v.y);
    dst[2 * i + 1] = __floats2half2_rn(v.z, v.w);
}

// ---------------- HMMA fp16 2-pass GEMM: C[M,N] = (Ah+Al)[M,K] @ W[N,K]^T ----------------
#define RS 80
#define TEN 10240
#define STAGE 30720       // 3 tensors (Ah, Al, W) x 10240
#define NCH 32

__global__ __launch_bounds__(256, 1)
void gemm_mma(const __half* __restrict__ Ah, const __half* __restrict__ Al,
              const __half* __restrict__ W,
              const float* __restrict__ bias, float* __restrict__ Cf,
              __half* __restrict__ Chi, __half* __restrict__ Clo,
              int N, int wrow0) {
    extern __shared__ char sm[];
    const uint32_t sb = smem_u32(sm);
    const int t = threadIdx.x, wid = t >> 5, lane = t & 31;
    const int m0 = blockIdx.y << 7, n0 = blockIdx.x << 7;
    const int wm = wid & 1, wn = wid >> 1;

    const char* gsrc[3];
    gsrc[0] = (const char*)(Ah + (size_t)m0 * 1024);
    gsrc[1] = (const char*)(Al + (size_t)m0 * 1024);
    gsrc[2] = (const char*)(W + (size_t)(wrow0 + n0) * 1024);

    const int mat = lane >> 3, lr = lane & 7;
    const uint32_t a_off = (uint32_t)((((mat & 1) << 3) + lr) * RS + ((mat >> 1) << 4));
    const uint32_t b_off = (uint32_t)((((mat >> 1) << 3) + lr) * RS + ((mat & 1) << 4));

    auto load_stage = [&](int st, int c) {
        uint32_t dbase = sb + st * STAGE;
#pragma unroll
        for (int q = 0; q < 3; q++) {
#pragma unroll
            for (int h = 0; h < 2; h++) {
                int idx = t + h * 256;
                int row = idx >> 2, seg = idx & 3;
                const char* g = gsrc[q] + (size_t)row * 2048 + c * 64 + seg * 16;
                uint32_t d = dbase + q * TEN + row * RS + seg * 16;
                CPA16(d, g);
            }
        }
        asm volatile("cp.async.commit_group;" ::: "memory");
    };

    float acc[4][4][4];
#pragma unroll
    for (int i = 0; i < 4; i++)
#pragma unroll
        for (int j = 0; j < 4; j++)
#pragma unroll
            for (int k = 0; k < 4; k++) acc[i][j][k] = 0.f;

    load_stage(0, 0);

    for (int c = 0; c < NCH; c++) {
        const int st = c & 1;
        if (c + 1 < NCH) {
            load_stage(st ^ 1, c + 1);
            asm volatile("cp.async.wait_group 1;" ::: "memory");
        } else {
            asm volatile("cp.async.wait_group 0;" ::: "memory");
        }
        __syncthreads();

        const uint32_t abase = sb + st * STAGE;
#pragma unroll
        for (int k16 = 0; k16 < 2; k16++) {
            uint32_t ah[4][4], al[4][4], bfrag[4][2];
#pragma unroll
            for (int mt = 0; mt < 4; mt++) {
                uint32_t addr = abase + (wm * 64 + mt * 16) * RS + k16 * 32 + a_off;
                LDSM4(ah[mt], addr);
                LDSM4(al[mt], addr + TEN);
            }
#pragma unroll
            for (int p = 0; p < 2; p++) {
                uint32_t addr = abase + 2 * TEN + (wn * 32 + p * 16) * RS + k16 * 32 + b_off;
                uint32_t r[4];
                LDSM4(r, addr);
                bfrag[2 * p][0] = r[0]; bfrag[2 * p][1] = r[1];
                bfrag[2 * p + 1][0] = r[2]; bfrag[2 * p + 1][1] = r[3];
            }
#pragma unroll
            for (int mt = 0; mt < 4; mt++)
#pragma unroll
                for (int nt = 0; nt < 4; nt++) {
                    MMA16816(acc[mt][nt], ah[mt], bfrag[nt]);
                    MMA16816(acc[mt][nt], al[mt], bfrag[nt]);
                }
        }
        __syncthreads();
    }

    const int qrow = lane >> 2, qcol = (lane & 3) * 2;
#pragma unroll
    for (int mt = 0; mt < 4; mt++) {
        const int r0 = m0 + wm * 64 + mt * 16 + qrow;
#pragma unroll
        for (int nt = 0; nt < 4; nt++) {
            const int col = n0 + wn * 32 + nt * 8 + qcol;
            if (Cf) {
                float bx = 0.f, by = 0.f;
                if (bias) { bx = bias[col]; by = bias[col + 1]; }
                *(float2*)(Cf + (size_t)r0 * N + col) =
                    make_float2(acc[mt][nt][0] + bx, acc[mt][nt][1] + by);
                *(float2*)(Cf + (size_t)(r0 + 8) * N + col) =
                    make_float2(acc[mt][nt][2] + bx, acc[mt][nt][3] + by);
            } else {
#pragma unroll
                for (int rr = 0; rr < 2; rr++) {
                    float vx = acc[mt][nt][2 * rr], vy = acc[mt][nt][2 * rr + 1];
                    __half hx = __float2half_rn(vx), hy = __float2half_rn(vy);
                    size_t off = (size_t)(r0 + rr * 8) * N + col;
                    *(uint32_t*)(Chi + off) = pack_hh(hx, hy);
                    *(uint32_t*)(Clo + off) =
                        pack_h2(vx - __half2float(hx), vy - __half2float(hy));
                }
            }
        }
    }
}

// ---------------- proj = secondary_structure @ ss_w^T ----------------
__global__ __launch_bounds__(256) void proj_kernel(const float* __restrict__ ss,
                                                   const float* __restrict__ ss_w,
                                                   float* __restrict__ proj) {
    __shared__ float w[NH][8];
    int t = threadIdx.x;
    if (t < NH * 8) w[t / 8][t % 8] = ss_w[t];
    __syncthreads();
    int idx = blockIdx.x * blockDim.x + t;
    int h = idx & 15;
    int bl = idx >> 4;
    const float* s = ss + bl * 8;
    float acc = 0.f;
#pragma unroll
    for (int c = 0; c < 8; c++) acc += s[c] * w[h][c];
    proj[idx] = acc;
}

// ---------------- shared bias tensor ----------------
__global__ __launch_bounds__(1024) void bias_kernel(const float* __restrict__ pf,
                                                    const int* __restrict__ ids,
                                                    const float* __restrict__ inter_mat,
                                                    const float* __restrict__ projp,
                                                    const float* __restrict__ physics_scale,
                                                    const float* __restrict__ distance_decay,
                                                    float* __restrict__ biasout) {
    __shared__ float sym[NAA * NAA];
    __shared__ float pi[32][17];
    __shared__ float pj[32][17];
    __shared__ int idi[32], idj[32];

    const int b = blockIdx.z;
    const int i0 = blockIdx.y * 32;
    const int j0 = blockIdx.x * 32;
    const int t = threadIdx.y * 32 + threadIdx.x;

    for (int s = t; s < NAA * NAA; s += 1024) {
        int r = s / NAA, c = s % NAA;
        sym[s] = 0.5f * (inter_mat[r * NAA + c] + inter_mat[c * NAA + r]);
    }
    if (t < 32)       idi[t]      = min(max(ids[b * LEN + i0 + t], 0), NAA - 1);
    else if (t < 64)  idj[t - 32] = min(max(ids[b * LEN + j0 + (t - 32)], 0), NAA - 1);
    if (t < 512) {
        int r = t / 16, c = t % 16;
        pi[r][c] = projp[(b * LEN + i0 + r) * NH + c];
    } else {
        int u = t - 512;
        int r = u / 16, c = u % 16;
        pj[r][c] = projp[(b * LEN + j0 + r) * NH + c];
    }
    __syncthreads();

    const int i = threadIdx.y, j = threadIdx.x;
    float decay = fminf(fmaxf(distance_decay[0], 0.1f), 5.0f);
    float sig = 1.0f / (1.0f + __expf(-physics_scale[0]));

    float d = pf[(size_t)b * LEN * LEN + (size_t)(i0 + i) * LEN + (j0 + j)];
    d = fminf(fmaxf(d, 0.1f), 50.0f);
    float pen = -__powf(d, decay) * sig;

    float it = sym[idi[i] * NAA + idj[j]] *
               (1.0f / (1.0f + fabsf((float)(i0 + i) - (float)(j0 + j))));

    float dot = 0.f;
#pragma unroll
    for (int hh = 0; hh < NH; hh++) dot += pi[i][hh] * pj[j][hh];
    float st = 1.0f / (1.0f + __expf(-dot)) - 0.5f;

    biasout[(size_t)b * LEN * LEN + (size_t)(i0 + i) * LEN + (j0 + j)] = pen + it + st;
}

// ---------------- HMMA fp16 flash attention, 2 CTAs/SM ----------------
// 128 q-rows per CTA, 8 warps x 16 rows, j-tiles of 32.
// S = Qh (Kh+Kl)^T (2-pass, Q single fp16); O += P (Vh+Vl) (2-pass).
#define ARS 144
#define QB (128 * ARS)           // 18432 (Q single tensor)
#define KVT32 (32 * ARS)         // 4608 per KV tensor
#define KVSTG (4 * KVT32)        // Kh, Kl, Vh, Vl = 18432
#define ATTN_SMEM (QB + 2 * KVSTG)   // 55296

__global__ __launch_bounds__(256, 2)
void attn_mma(const __half* __restrict__ qkvhi, const __half* __restrict__ qkvlo,
              const float* __restrict__ biasp, const float* __restrict__ dist_bias,
              __half* __restrict__ ctxhi, __half* __restrict__ ctxlo) {
    extern __shared__ char sm[];
    const uint32_t sb = smem_u32(sm);
    const int t = threadIdx.x, wid = t >> 5, lane = t & 31;
    const int i0 = blockIdx.x * 128, h = blockIdx.y, b = blockIdx.z;
    const float db = dist_bias[h];

    const int mat = lane >> 3, lr = lane & 7;
    const uint32_t a_off = (uint32_t)((((mat & 1) << 3) + lr) * ARS + ((mat >> 1) << 4));
    const uint32_t b_off = (uint32_t)((((mat >> 1) << 3) + lr) * ARS + ((mat & 1) << 4));
    const uint32_t v_off = (uint32_t)((lane & 15) * ARS + ((lane >> 4) << 4));

    // Q tile (hi only): 128 rows x 8 chunks of 16B
#pragma unroll
    for (int i = 0; i < 4; i++) {
        int idx = t + i * 256;
        int row = idx >> 3, seg = idx & 7;
        const char* g = (const char*)(qkvhi + (size_t)(b * LEN + i0 + row) * 3072 + h * 64) + seg * 16;
        CPA16(sb + row * ARS + seg * 16, g);
    }
    auto load_kv = [&](int st, int jt) {
        int j0 = jt * 32;
#pragma unroll
        for (int i = 0; i < 4; i++) {
            int idx = t + i * 256;                 // 1024 chunks: 4 tensors x 32 rows x 8 segs
            int tensor = idx >> 8;                 // 0 Kh, 1 Kl, 2 Vh, 3 Vl
            int row = (idx >> 3) & 31;
            int seg = idx & 7;
            const __half* src = (tensor & 1) ? qkvlo : qkvhi;
            int coloff = ((tensor >> 1) ? 2048 : 1024) + h * 64;
            const char* g = (const char*)(src + (size_t)(b * LEN + j0 + row) * 3072 + coloff) + seg * 16;
            CPA16(sb + QB + st * KVSTG + tensor * KVT32 + row * ARS + seg * 16, g);
        }
        asm volatile("cp.async.commit_group;" ::: "memory");
    };
    load_kv(0, 0);   // Q chunks + KV0 in one group

    float O[8][4];
#pragma unroll
    for (int f = 0; f < 8; f++)
#pragma unroll
        for (int k = 0; k < 4; k++) O[f][k] = 0.f;
    float m0r = -3.0e38f, m1r = -3.0e38f, l0 = 0.f, l1 = 0.f;

    const int r0 = lane >> 2, c0 = (lane & 3) * 2;
    const float* bp = biasp + ((size_t)b * LEN + i0 + wid * 16) * LEN;

    for (int jt = 0; jt < 32; jt++) {
        const int st = jt & 1;
        if (jt + 1 < 32) {
            load_kv(st ^ 1, jt + 1);
            asm volatile("cp.async.wait_group 1;" ::: "memory");
        } else {
            asm volatile("cp.async.wait_group 0;" ::: "memory");
        }
        __syncthreads();

        // bias prefetch (L2-resident), latency hidden under S MMAs
        float2 bpre[4][2];
        {
            const float* bj = bp + jt * 32 + c0;
#pragma unroll
            for (int f = 0; f < 4; f++) {
                bpre[f][0] = *(const float2*)(bj + (size_t)r0 * LEN + f * 8);
                bpre[f][1] = *(const float2*)(bj + (size_t)(r0 + 8) * LEN + f * 8);
            }
        }

        // S = Q K^T (2-pass: K hi + K lo)
        float sacc[4][4];
#pragma unroll
        for (int f = 0; f < 4; f++)
#pragma unroll
            for (int k = 0; k < 4; k++) sacc[f][k] = 0.f;

        const uint32_t kb = sb + QB + st * KVSTG;
#pragma unroll
        for (int kk = 0; kk < 4; kk++) {
            uint32_t a[4];
            LDSM4(a, sb + (wid * 16) * ARS + kk * 32 + a_off);
#pragma unroll
            for (int p = 0; p < 2; p++) {
                uint32_t rh[4], rl[4];
                uint32_t kaddr = kb + (p * 16) * ARS + kk * 32 + b_off;
                LDSM4(rh, kaddr);
                LDSM4(rl, kaddr + KVT32);
                uint32_t bh0[2] = {rh[0], rh[1]}, bh1[2] = {rh[2], rh[3]};
                uint32_t bl0[2] = {rl[0], rl[1]}, bl1[2] = {rl[2], rl[3]};
                MMA16816(sacc[2 * p], a, bh0);
                MMA16816(sacc[2 * p], a, bl0);
                MMA16816(sacc[2 * p + 1], a, bh1);
                MMA16816(sacc[2 * p + 1], a, bl1);
            }
        }

        // bias + online softmax
        float mx0 = -3.0e38f, mx1 = -3.0e38f;
#pragma unroll
        for (int f = 0; f < 4; f++) {
            sacc[f][0] = sacc[f][0] * 0.125f + bpre[f][0].x + db;
            sacc[f][1] = sacc[f][1] * 0.125f + bpre[f][0].y + db;
            sacc[f][2] = sacc[f][2] * 0.125f + bpre[f][1].x + db;
            sacc[f][3] = sacc[f][3] * 0.125f + bpre[f][1].y + db;
            mx0 = fmaxf(mx0, fmaxf(sacc[f][0], sacc[f][1]));
            mx1 = fmaxf(mx1, fmaxf(sacc[f][2], sacc[f][3]));
        }
        mx0 = fmaxf(mx0, __shfl_xor_sync(0xffffffffu, mx0, 1));
        mx0 = fmaxf(mx0, __shfl_xor_sync(0xffffffffu, mx0, 2));
        mx1 = fmaxf(mx1, __shfl_xor_sync(0xffffffffu, mx1, 1));
        mx1 = fmaxf(mx1, __shfl_xor_sync(0xffffffffu, mx1, 2));

        float mn0 = fmaxf(m0r, mx0), mn1 = fmaxf(m1r, mx1);
        float fac0 = __expf(m0r - mn0), fac1 = __expf(m1r - mn1);
        m0r = mn0; m1r = mn1;

        uint32_t pa[2][4];
        float sum0 = 0.f, sum1 = 0.f;
#pragma unroll
        for (int f = 0; f < 4; f++) {
            float p0 = __expf(sacc[f][0] - mn0);
            float p1 = __expf(sacc[f][1] - mn0);
            float p2 = __expf(sacc[f][2] - mn1);
            float p3 = __expf(sacc[f][3] - mn1);
            sum0 += p0 + p1; sum1 += p2 + p3;
            int jc = f >> 1, half = (f & 1) << 1;
            pa[jc][half]     = pack_h2(p0, p1);
            pa[jc][half + 1] = pack_h2(p2, p3);
        }
        sum0 += __shfl_xor_sync(0xffffffffu, sum0, 1);
        sum0 += __shfl_xor_sync(0xffffffffu, sum0, 2);
        sum1 += __shfl_xor_sync(0xffffffffu, sum1, 1);
        sum1 += __shfl_xor_sync(0xffffffffu, sum1, 2);
        l0 = l0 * fac0 + sum0;
        l1 = l1 * fac1 + sum1;

#pragma unroll
        for (int f = 0; f < 8; f++) {
            O[f][0] *= fac0; O[f][1] *= fac0;
            O[f][2] *= fac1; O[f][3] *= fac1;
        }

        // O += P V (2-pass: V hi + V lo), V via ldmatrix.trans
        const uint32_t vb = kb + 2 * KVT32;
#pragma unroll
        for (int jc = 0; jc < 2; jc++) {
#pragma unroll
            for (int dbk = 0; dbk < 4; dbk++) {
                uint32_t rh[4], rl[4];
                uint32_t vaddr = vb + (jc * 16) * ARS + dbk * 32 + v_off;
                LDSM4T(rh, vaddr);
                LDSM4T(rl, vaddr + KVT32);
                uint32_t bh0[2] = {rh[0], rh[1]}, bh1[2] = {rh[2], rh[3]};
                uint32_t bl0[2] = {rl[0], rl[1]}, bl1[2] = {rl[2], rl[3]};
                MMA16816(O[2 * dbk], pa[jc], bh0);
                MMA16816(O[2 * dbk], pa[jc], bl0);
                MMA16816(O[2 * dbk + 1], pa[jc], bh1);
                MMA16816(O[2 * dbk + 1], pa[jc], bl1);
            }
        }
        __syncthreads();
    }

    // epilogue: normalize, split to fp16 hi/lo, store ctx
    const float inv0 = 1.0f / l0, inv1 = 1.0f / l1;
    const size_t row0 = (size_t)(b * LEN + i0 + wid * 16 + r0) * DM;
    const size_t row1 = row0 + 8 * DM;
    const int colb = h * 64 + c0;
#pragma unroll
    for (int f = 0; f < 8; f++) {
        float v0 = O[f][0] * inv0, v1 = O[f][1] * inv0;
        float v2 = O[f][2] * inv1, v3 = O[f][3] * inv1;
        __half h0 = __float2half_rn(v0), h1 = __float2half_rn(v1);
        __half h2 = __float2half_rn(v2), h3 = __float2half_rn(v3);
        *(uint32_t*)(ctxhi + row0 + colb + f * 8) = pack_hh(h0, h1);
        *(uint32_t*)(ctxhi + row1 + colb + f * 8) = pack_hh(h2, h3);
        *(uint32_t*)(ctxlo + row0 + colb + f * 8) =
            pack_h2(v0 - __half2float(h0), v1 - __half2float(h1));
        *(uint32_t*)(ctxlo + row1 + colb + f * 8) =
            pack_h2(v2 - __half2float(h2), v3 - __half2float(h3));
    }
}

// ---------------- launch ----------------
extern "C" void kernel_launch(void* const* d_in, const int* in_sizes, int n_in,
                              void* d_out, int out_size) {
    const float* x              = (const float*)d_in[0];
    const float* pf             = (const float*)d_in[1];
    const int*   ids            = (const int*)d_in[2];
    const float* ss             = (const float*)d_in[3];
    const float* Wq             = (const float*)d_in[4];
    const float* Wk             = (const float*)d_in[5];
    const float* Wv             = (const float*)d_in[6];
    const float* Wo             = (const float*)d_in[7];
    const float* bo             = (const float*)d_in[8];
    const float* dist_bias      = (const float*)d_in[9];
    const float* inter_mat      = (const float*)d_in[10];
    const float* ss_w           = (const float*)d_in[11];
    const float* physics_scale  = (const float*)d_in[12];
    const float* distance_decay = (const float*)d_in[13];
    float* out = (float*)d_out;

    float *biasb, *proj;
    __half *ahi, *alo, *w, *qh, *ql;
    cudaGetSymbolAddress((void**)&biasb, g_bias);
    cudaGetSymbolAddress((void**)&proj, g_proj);
    cudaGetSymbolAddress((void**)&ahi,  g_a_hi);
    cudaGetSymbolAddress((void**)&alo,  g_a_lo);
    cudaGetSymbolAddress((void**)&w,    g_w);
    cudaGetSymbolAddress((void**)&qh,   g_qkv_hi);
    cudaGetSymbolAddress((void**)&ql,   g_qkv_lo);

    cudaFuncSetAttribute(gemm_mma, cudaFuncAttributeMaxDynamicSharedMemorySize, 2 * STAGE);
    cudaFuncSetAttribute(attn_mma, cudaFuncAttributeMaxDynamicSharedMemorySize, ATTN_SMEM);

    conv4_kernel<<<dim3(1024, 4), 256>>>((const float4*)Wq, (const float4*)Wk,
                                         (const float4*)Wv, (const float4*)Wo, (__half2*)w);
    split_kernel<<<4096, 256>>>((const float4*)x, (__half2*)ahi, (__half2*)alo, 1024 * 1024);

    proj_kernel<<<256, 256>>>(ss, ss_w, proj);
    bias_kernel<<<dim3(32, 32, BSZ), dim3(32, 32)>>>(pf, ids, inter_mat, proj,
                                                     physics_scale, distance_decay, biasb);

    // QKV projection -> fp16 hi/lo
    gemm_mma<<<dim3(24, 32), 256, 2 * STAGE>>>(ahi, alo, w, nullptr,
                                               nullptr, qh, ql, 3072, 0);

    // HMMA flash attention (2 CTAs/SM) -> ctx hi/lo (overwrites g_a_hi/g_a_lo)
    attn_mma<<<dim3(8, NH, BSZ), 256, ATTN_SMEM>>>(qh, ql, biasb, dist_bias, ahi, alo);

    // out projection: ctx @ Wo^T + bo -> fp32 out
    gemm_mma<<<dim3(8, 32), 256, 2 * STAGE>>>(ahi, alo, w, bo,
                                              out, nullptr, nullptr, 1024, 3072);
}

// round 11
// speedup vs baseline: 4.0294x; 1.2445x over previous
#include <cuda_runtime.h>
#include <cuda_fp16.h>
#include <math.h>
#include <stdint.h>

#define BSZ 4
#define LEN 1024
#define DM 1024
#define NH 16
#define NAA 25

// ---------------- scratch (static device globals; no allocation) ----------------
__device__ float g_bias[BSZ * LEN * LEN];
__device__ float g_proj[BSZ * LEN * NH];
__device__ __half g_a_hi[4096 * 1024];          // x fp16, later ctx hi
__device__ __half g_a_lo[4096 * 1024];          // ctx lo
__device__ __half g_w[4096 * 1024];             // rows 0-3071 = Wq,Wk,Wv; 3072-4095 = Wo
__device__ __half g_qkv_hi[BSZ * LEN * 3 * DM];
__device__ __half g_qkv_lo[BSZ * LEN * 3 * DM];

static __device__ __forceinline__ uint32_t smem_u32(const void* p) {
    uint32_t a;
    asm("{ .reg .u64 t; cvta.to.shared.u64 t, %1; cvt.u32.u64 %0, t; }" : "=r"(a) : "l"(p));
    return a;
}
static __device__ __forceinline__ uint32_t pack_h2(float x, float y) {
    __half2 h = __floats2half2_rn(x, y);
    uint32_t u;
    __builtin_memcpy(&u, &h, 4);
    return u;
}
static __device__ __forceinline__ uint32_t pack_hh(__half x, __half y) {
    __half2 h = __halves2half2(x, y);
    uint32_t u;
    __builtin_memcpy(&u, &h, 4);
    return u;
}

#define LDSM4(r, addr)                                                            \
    asm volatile("ldmatrix.sync.aligned.m8n8.x4.shared.b16 {%0,%1,%2,%3}, [%4];"  \
                 : "=r"((r)[0]), "=r"((r)[1]), "=r"((r)[2]), "=r"((r)[3])         \
                 : "r"(addr))
#define LDSM4T(r, addr)                                                                \
    asm volatile("ldmatrix.sync.aligned.m8n8.x4.trans.shared.b16 {%0,%1,%2,%3}, [%4];" \
                 : "=r"((r)[0]), "=r"((r)[1]), "=r"((r)[2]), "=r"((r)[3])              \
                 : "r"(addr))
#define MMA16816(d, a, b)                                                         \
    asm volatile("mma.sync.aligned.m16n8k16.row.col.f32.f16.f16.f32 "             \
                 "{%0,%1,%2,%3}, {%4,%5,%6,%7}, {%8,%9}, {%0,%1,%2,%3};"          \
                 : "+f"((d)[0]), "+f"((d)[1]), "+f"((d)[2]), "+f"((d)[3])         \
                 : "r"((a)[0]), "r"((a)[1]), "r"((a)[2]), "r"((a)[3]),            \
                   "r"((b)[0]), "r"((b)[1]))
#define CPA16(d, g) asm volatile("cp.async.cg.shared.global [%0], [%1], 16;" :: "r"(d), "l"(g))

// ---------------- fp32 -> fp16 convert (single) ----------------
__global__ __launch_bounds__(256)
void conv_kernel(const float4* __restrict__ a, __half2* __restrict__ w, int n4) {
    int i = blockIdx.x * blockDim.x + threadIdx.x;
    if (i >= n4) return;
    float4 v = a[i];
    w[2 * i]     = __floats2half2_rn(v.x, v.y);
    w[2 * i + 1] = __floats2half2_rn(v.z, v.w);
}

// ---------------- fused fp32 -> fp16 convert for 4 weight tensors ----------------
__global__ __launch_bounds__(256)
void conv4_kernel(const float4* __restrict__ a0, const float4* __restrict__ a1,
                  const float4* __restrict__ a2, const float4* __restrict__ a3,
                  __half2* __restrict__ w) {
    const int tensor = blockIdx.y;
    const float4* a = (tensor == 0) ? a0 : (tensor == 1) ? a1 : (tensor == 2) ? a2 : a3;
    int i = blockIdx.x * blockDim.x + threadIdx.x;
    float4 v = a[i];
    __half2* dst = w + (size_t)tensor * 524288;
    dst[2 * i]     = __floats2half2_rn(v.x, v.y);
    dst[2 * i + 1] = __floats2half2_rn(v.z, v.w);
}

// ---------------- HMMA fp16 GEMM: C[M,N] = A[M,K] @ W[N,K]^T ----------------
// TWO=1: A = Ah + Al (2-pass). TWO=0: A = Ah only (1-pass).
#define RS 80
#define TEN 10240
#define NCH 32

template <int TWO>
__global__ __launch_bounds__(256, 1)
void gemm_mma(const __half* __restrict__ Ah, const __half* __restrict__ Al,
              const __half* __restrict__ W,
              const float* __restrict__ bias, float* __restrict__ Cf,
              __half* __restrict__ Chi, __half* __restrict__ Clo,
              int N, int wrow0) {
    const int NT = TWO ? 3 : 2;
    const int STG = NT * TEN;
    extern __shared__ char sm[];
    const uint32_t sb = smem_u32(sm);
    const int t = threadIdx.x, wid = t >> 5, lane = t & 31;
    const int m0 = blockIdx.y << 7, n0 = blockIdx.x << 7;
    const int wm = wid & 1, wn = wid >> 1;

    const char* gsrc[3];
    gsrc[0] = (const char*)(Ah + (size_t)m0 * 1024);
    gsrc[1] = TWO ? (const char*)(Al + (size_t)m0 * 1024)
                  : (const char*)(W + (size_t)(wrow0 + n0) * 1024);
    gsrc[2] = (const char*)(W + (size_t)(wrow0 + n0) * 1024);

    const int mat = lane >> 3, lr = lane & 7;
    const uint32_t a_off = (uint32_t)((((mat & 1) << 3) + lr) * RS + ((mat >> 1) << 4));
    const uint32_t b_off = (uint32_t)((((mat >> 1) << 3) + lr) * RS + ((mat & 1) << 4));

    auto load_stage = [&](int st, int c) {
        uint32_t dbase = sb + st * STG;
#pragma unroll
        for (int q = 0; q < NT; q++) {
#pragma unroll
            for (int h = 0; h < 2; h++) {
                int idx = t + h * 256;
                int row = idx >> 2, seg = idx & 3;
                const char* g = gsrc[q] + (size_t)row * 2048 + c * 64 + seg * 16;
                uint32_t d = dbase + q * TEN + row * RS + seg * 16;
                CPA16(d, g);
            }
        }
        asm volatile("cp.async.commit_group;" ::: "memory");
    };

    float acc[4][4][4];
#pragma unroll
    for (int i = 0; i < 4; i++)
#pragma unroll
        for (int j = 0; j < 4; j++)
#pragma unroll
            for (int k = 0; k < 4; k++) acc[i][j][k] = 0.f;

    load_stage(0, 0);

    for (int c = 0; c < NCH; c++) {
        const int st = c & 1;
        if (c + 1 < NCH) {
            load_stage(st ^ 1, c + 1);
            asm volatile("cp.async.wait_group 1;" ::: "memory");
        } else {
            asm volatile("cp.async.wait_group 0;" ::: "memory");
        }
        __syncthreads();

        const uint32_t abase = sb + st * STG;
#pragma unroll
        for (int k16 = 0; k16 < 2; k16++) {
            uint32_t ah[4][4], al[4][4], bfrag[4][2];
#pragma unroll
            for (int mt = 0; mt < 4; mt++) {
                uint32_t addr = abase + (wm * 64 + mt * 16) * RS + k16 * 32 + a_off;
                LDSM4(ah[mt], addr);
                if (TWO) LDSM4(al[mt], addr + TEN);
            }
#pragma unroll
            for (int p = 0; p < 2; p++) {
                uint32_t addr = abase + (NT - 1) * TEN + (wn * 32 + p * 16) * RS + k16 * 32 + b_off;
                uint32_t r[4];
                LDSM4(r, addr);
                bfrag[2 * p][0] = r[0]; bfrag[2 * p][1] = r[1];
                bfrag[2 * p + 1][0] = r[2]; bfrag[2 * p + 1][1] = r[3];
            }
#pragma unroll
            for (int mt = 0; mt < 4; mt++)
#pragma unroll
                for (int nt = 0; nt < 4; nt++) {
                    MMA16816(acc[mt][nt], ah[mt], bfrag[nt]);
                    if (TWO) MMA16816(acc[mt][nt], al[mt], bfrag[nt]);
                }
        }
        __syncthreads();
    }

    const int qrow = lane >> 2, qcol = (lane & 3) * 2;
#pragma unroll
    for (int mt = 0; mt < 4; mt++) {
        const int r0 = m0 + wm * 64 + mt * 16 + qrow;
#pragma unroll
        for (int nt = 0; nt < 4; nt++) {
            const int col = n0 + wn * 32 + nt * 8 + qcol;
            if (Cf) {
                float bx = 0.f, by = 0.f;
                if (bias) { bx = bias[col]; by = bias[col + 1]; }
                *(float2*)(Cf + (size_t)r0 * N + col) =
                    make_float2(acc[mt][nt][0] + bx, acc[mt][nt][1] + by);
                *(float2*)(Cf + (size_t)(r0 + 8) * N + col) =
                    make_float2(acc[mt][nt][2] + bx, acc[mt][nt][3] + by);
            } else {
#pragma unroll
                for (int rr = 0; rr < 2; rr++) {
                    float vx = acc[mt][nt][2 * rr], vy = acc[mt][nt][2 * rr + 1];
                    __half hx = __float2half_rn(vx), hy = __float2half_rn(vy);
                    size_t off = (size_t)(r0 + rr * 8) * N + col;
                    *(uint32_t*)(Chi + off) = pack_hh(hx, hy);
                    *(uint32_t*)(Clo + off) =
                        pack_h2(vx - __half2float(hx), vy - __half2float(hy));
                }
            }
        }
    }
}

// ---------------- proj = secondary_structure @ ss_w^T ----------------
__global__ __launch_bounds__(256) void proj_kernel(const float* __restrict__ ss,
                                                   const float* __restrict__ ss_w,
                                                   float* __restrict__ proj) {
    __shared__ float w[NH][8];
    int t = threadIdx.x;
    if (t < NH * 8) w[t / 8][t % 8] = ss_w[t];
    __syncthreads();
    int idx = blockIdx.x * blockDim.x + t;
    int h = idx & 15;
    int bl = idx >> 4;
    const float* s = ss + bl * 8;
    float acc = 0.f;
#pragma unroll
    for (int c = 0; c < 8; c++) acc += s[c] * w[h][c];
    proj[idx] = acc;
}

// ---------------- shared bias tensor ----------------
__global__ __launch_bounds__(1024) void bias_kernel(const float* __restrict__ pf,
                                                    const int* __restrict__ ids,
                                                    const float* __restrict__ inter_mat,
                                                    const float* __restrict__ projp,
                                                    const float* __restrict__ physics_scale,
                                                    const float* __restrict__ distance_decay,
                                                    float* __restrict__ biasout) {
    __shared__ float sym[NAA * NAA];
    __shared__ float pi[32][17];
    __shared__ float pj[32][17];
    __shared__ int idi[32], idj[32];

    const int b = blockIdx.z;
    const int i0 = blockIdx.y * 32;
    const int j0 = blockIdx.x * 32;
    const int t = threadIdx.y * 32 + threadIdx.x;

    for (int s = t; s < NAA * NAA; s += 1024) {
        int r = s / NAA, c = s % NAA;
        sym[s] = 0.5f * (inter_mat[r * NAA + c] + inter_mat[c * NAA + r]);
    }
    if (t < 32)       idi[t]      = min(max(ids[b * LEN + i0 + t], 0), NAA - 1);
    else if (t < 64)  idj[t - 32] = min(max(ids[b * LEN + j0 + (t - 32)], 0), NAA - 1);
    if (t < 512) {
        int r = t / 16, c = t % 16;
        pi[r][c] = projp[(b * LEN + i0 + r) * NH + c];
    } else {
        int u = t - 512;
        int r = u / 16, c = u % 16;
        pj[r][c] = projp[(b * LEN + j0 + r) * NH + c];
    }
    __syncthreads();

    const int i = threadIdx.y, j = threadIdx.x;
    float decay = fminf(fmaxf(distance_decay[0], 0.1f), 5.0f);
    float sig = 1.0f / (1.0f + __expf(-physics_scale[0]));

    float d = pf[(size_t)b * LEN * LEN + (size_t)(i0 + i) * LEN + (j0 + j)];
    d = fminf(fmaxf(d, 0.1f), 50.0f);
    float pen = -__powf(d, decay) * sig;

    float it = sym[idi[i] * NAA + idj[j]] *
               (1.0f / (1.0f + fabsf((float)(i0 + i) - (float)(j0 + j))));

    float dot = 0.f;
#pragma unroll
    for (int hh = 0; hh < NH; hh++) dot += pi[i][hh] * pj[j][hh];
    float st = 1.0f / (1.0f + __expf(-dot)) - 0.5f;

    biasout[(size_t)b * LEN * LEN + (size_t)(i0 + i) * LEN + (j0 + j)] = pen + it + st;
}

// ---------------- HMMA fp16 flash attention, 2 CTAs/SM ----------------
// 128 q-rows per CTA, 8 warps x 16 rows, j-tiles of 32.
// S = Qh (Kh+Kl)^T (2-pass); O += P Vh (1-pass).
#define ARS 144
#define QB (128 * ARS)           // 18432
#define KVT32 (32 * ARS)         // 4608 per KV tensor
#define KVSTG (3 * KVT32)        // Kh, Kl, Vh = 13824
#define ATTN_SMEM (QB + 2 * KVSTG)   // 46080

__global__ __launch_bounds__(256, 2)
void attn_mma(const __half* __restrict__ qkvhi, const __half* __restrict__ qkvlo,
              const float* __restrict__ biasp, const float* __restrict__ dist_bias,
              __half* __restrict__ ctxhi, __half* __restrict__ ctxlo) {
    extern __shared__ char sm[];
    const uint32_t sb = smem_u32(sm);
    const int t = threadIdx.x, wid = t >> 5, lane = t & 31;
    const int i0 = blockIdx.x * 128, h = blockIdx.y, b = blockIdx.z;
    const float db = dist_bias[h];

    const int mat = lane >> 3, lr = lane & 7;
    const uint32_t a_off = (uint32_t)((((mat & 1) << 3) + lr) * ARS + ((mat >> 1) << 4));
    const uint32_t b_off = (uint32_t)((((mat >> 1) << 3) + lr) * ARS + ((mat & 1) << 4));
    const uint32_t v_off = (uint32_t)((lane & 15) * ARS + ((lane >> 4) << 4));

    // Q tile (hi only): 128 rows x 8 chunks of 16B
#pragma unroll
    for (int i = 0; i < 4; i++) {
        int idx = t + i * 256;
        int row = idx >> 3, seg = idx & 7;
        const char* g = (const char*)(qkvhi + (size_t)(b * LEN + i0 + row) * 3072 + h * 64) + seg * 16;
        CPA16(sb + row * ARS + seg * 16, g);
    }
    auto load_kv = [&](int st, int jt) {
        int j0 = jt * 32;
#pragma unroll
        for (int i = 0; i < 3; i++) {
            int idx = t + i * 256;                 // 768 chunks: 3 tensors x 32 rows x 8 segs
            int tensor = idx >> 8;                 // 0 Kh, 1 Kl, 2 Vh
            int row = (idx >> 3) & 31;
            int seg = idx & 7;
            const __half* src = (tensor == 1) ? qkvlo : qkvhi;
            int coloff = ((tensor == 2) ? 2048 : 1024) + h * 64;
            const char* g = (const char*)(src + (size_t)(b * LEN + j0 + row) * 3072 + coloff) + seg * 16;
            CPA16(sb + QB + st * KVSTG + tensor * KVT32 + row * ARS + seg * 16, g);
        }
        asm volatile("cp.async.commit_group;" ::: "memory");
    };
    load_kv(0, 0);

    float O[8][4];
#pragma unroll
    for (int f = 0; f < 8; f++)
#pragma unroll
        for (int k = 0; k < 4; k++) O[f][k] = 0.f;
    float m0r = -3.0e38f, m1r = -3.0e38f, l0 = 0.f, l1 = 0.f;

    const int r0 = lane >> 2, c0 = (lane & 3) * 2;
    const float* bp = biasp + ((size_t)b * LEN + i0 + wid * 16) * LEN;

    for (int jt = 0; jt < 32; jt++) {
        const int st = jt & 1;
        if (jt + 1 < 32) {
            load_kv(st ^ 1, jt + 1);
            asm volatile("cp.async.wait_group 1;" ::: "memory");
        } else {
            asm volatile("cp.async.wait_group 0;" ::: "memory");
        }
        __syncthreads();

        // bias prefetch (L2-resident)
        float2 bpre[4][2];
        {
            const float* bj = bp + jt * 32 + c0;
#pragma unroll
            for (int f = 0; f < 4; f++) {
                bpre[f][0] = *(const float2*)(bj + (size_t)r0 * LEN + f * 8);
                bpre[f][1] = *(const float2*)(bj + (size_t)(r0 + 8) * LEN + f * 8);
            }
        }

        // S = Q K^T (2-pass: K hi + K lo)
        float sacc[4][4];
#pragma unroll
        for (int f = 0; f < 4; f++)
#pragma unroll
            for (int k = 0; k < 4; k++) sacc[f][k] = 0.f;

        const uint32_t kb = sb + QB + st * KVSTG;
#pragma unroll
        for (int kk = 0; kk < 4; kk++) {
            uint32_t a[4];
            LDSM4(a, sb + (wid * 16) * ARS + kk * 32 + a_off);
#pragma unroll
            for (int p = 0; p < 2; p++) {
                uint32_t rh[4], rl[4];
                uint32_t kaddr = kb + (p * 16) * ARS + kk * 32 + b_off;
                LDSM4(rh, kaddr);
                LDSM4(rl, kaddr + KVT32);
                uint32_t bh0[2] = {rh[0], rh[1]}, bh1[2] = {rh[2], rh[3]};
                uint32_t bl0[2] = {rl[0], rl[1]}, bl1[2] = {rl[2], rl[3]};
                MMA16816(sacc[2 * p], a, bh0);
                MMA16816(sacc[2 * p], a, bl0);
                MMA16816(sacc[2 * p + 1], a, bh1);
                MMA16816(sacc[2 * p + 1], a, bl1);
            }
        }

        // bias + online softmax
        float mx0 = -3.0e38f, mx1 = -3.0e38f;
#pragma unroll
        for (int f = 0; f < 4; f++) {
            sacc[f][0] = sacc[f][0] * 0.125f + bpre[f][0].x + db;
            sacc[f][1] = sacc[f][1] * 0.125f + bpre[f][0].y + db;
            sacc[f][2] = sacc[f][2] * 0.125f + bpre[f][1].x + db;
            sacc[f][3] = sacc[f][3] * 0.125f + bpre[f][1].y + db;
            mx0 = fmaxf(mx0, fmaxf(sacc[f][0], sacc[f][1]));
            mx1 = fmaxf(mx1, fmaxf(sacc[f][2], sacc[f][3]));
        }
        mx0 = fmaxf(mx0, __shfl_xor_sync(0xffffffffu, mx0, 1));
        mx0 = fmaxf(mx0, __shfl_xor_sync(0xffffffffu, mx0, 2));
        mx1 = fmaxf(mx1, __shfl_xor_sync(0xffffffffu, mx1, 1));
        mx1 = fmaxf(mx1, __shfl_xor_sync(0xffffffffu, mx1, 2));

        float mn0 = fmaxf(m0r, mx0), mn1 = fmaxf(m1r, mx1);
        float fac0 = __expf(m0r - mn0), fac1 = __expf(m1r - mn1);
        m0r = mn0; m1r = mn1;

        uint32_t pa[2][4];
        float sum0 = 0.f, sum1 = 0.f;
#pragma unroll
        for (int f = 0; f < 4; f++) {
            float p0 = __expf(sacc[f][0] - mn0);
            float p1 = __expf(sacc[f][1] - mn0);
            float p2 = __expf(sacc[f][2] - mn1);
            float p3 = __expf(sacc[f][3] - mn1);
            sum0 += p0 + p1; sum1 += p2 + p3;
            int jc = f >> 1, half = (f & 1) << 1;
            pa[jc][half]     = pack_h2(p0, p1);
            pa[jc][half + 1] = pack_h2(p2, p3);
        }
        sum0 += __shfl_xor_sync(0xffffffffu, sum0, 1);
        sum0 += __shfl_xor_sync(0xffffffffu, sum0, 2);
        sum1 += __shfl_xor_sync(0xffffffffu, sum1, 1);
        sum1 += __shfl_xor_sync(0xffffffffu, sum1, 2);
        l0 = l0 * fac0 + sum0;
        l1 = l1 * fac1 + sum1;

#pragma unroll
        for (int f = 0; f < 8; f++) {
            O[f][0] *= fac0; O[f][1] *= fac0;
            O[f][2] *= fac1; O[f][3] *= fac1;
        }

        // O += P Vh (1-pass), V via ldmatrix.trans
        const uint32_t vb = kb + 2 * KVT32;
#pragma unroll
        for (int jc = 0; jc < 2; jc++) {
#pragma unroll
            for (int dbk = 0; dbk < 4; dbk++) {
                uint32_t rh[4];
                LDSM4T(rh, vb + (jc * 16) * ARS + dbk * 32 + v_off);
                uint32_t bh0[2] = {rh[0], rh[1]}, bh1[2] = {rh[2], rh[3]};
                MMA16816(O[2 * dbk], pa[jc], bh0);
                MMA16816(O[2 * dbk + 1], pa[jc], bh1);
            }
        }
        __syncthreads();
    }

    // epilogue: normalize, split to fp16 hi/lo, store ctx
    const float inv0 = 1.0f / l0, inv1 = 1.0f / l1;
    const size_t row0 = (size_t)(b * LEN + i0 + wid * 16 + r0) * DM;
    const size_t row1 = row0 + 8 * DM;
    const int colb = h * 64 + c0;
#pragma unroll
    for (int f = 0; f < 8; f++) {
        float v0 = O[f][0] * inv0, v1 = O[f][1] * inv0;
        float v2 = O[f][2] * inv1, v3 = O[f][3] * inv1;
        __half h0 = __float2half_rn(v0), h1 = __float2half_rn(v1);
        __half h2 = __float2half_rn(v2), h3 = __float2half_rn(v3);
        *(uint32_t*)(ctxhi + row0 + colb + f * 8) = pack_hh(h0, h1);
        *(uint32_t*)(ctxhi + row1 + colb + f * 8) = pack_hh(h2, h3);
        *(uint32_t*)(ctxlo + row0 + colb + f * 8) =
            pack_h2(v0 - __half2float(h0), v1 - __half2float(h1));
        *(uint32_t*)(ctxlo + row1 + colb + f * 8) =
            pack_h2(v2 - __half2float(h2), v3 - __half2float(h3));
    }
}

// ---------------- launch ----------------
extern "C" void kernel_launch(void* const* d_in, const int* in_sizes, int n_in,
                              void* d_out, int out_size) {
    const float* x              = (const float*)d_in[0];
    const float* pf             = (const float*)d_in[1];
    const int*   ids            = (const int*)d_in[2];
    const float* ss             = (const float*)d_in[3];
    const float* Wq             = (const float*)d_in[4];
    const float* Wk             = (const float*)d_in[5];
    const float* Wv             = (const float*)d_in[6];
    const float* Wo             = (const float*)d_in[7];
    const float* bo             = (const float*)d_in[8];
    const float* dist_bias      = (const float*)d_in[9];
    const float* inter_mat      = (const float*)d_in[10];
    const float* ss_w           = (const float*)d_in[11];
    const float* physics_scale  = (const float*)d_in[12];
    const float* distance_decay = (const float*)d_in[13];
    float* out = (float*)d_out;

    float *biasb, *proj;
    __half *ahi, *alo, *w, *qh, *ql;
    cudaGetSymbolAddress((void**)&biasb, g_bias);
    cudaGetSymbolAddress((void**)&proj, g_proj);
    cudaGetSymbolAddress((void**)&ahi,  g_a_hi);
    cudaGetSymbolAddress((void**)&alo,  g_a_lo);
    cudaGetSymbolAddress((void**)&w,    g_w);
    cudaGetSymbolAddress((void**)&qh,   g_qkv_hi);
    cudaGetSymbolAddress((void**)&ql,   g_qkv_lo);

    cudaFuncSetAttribute(gemm_mma<0>, cudaFuncAttributeMaxDynamicSharedMemorySize, 2 * 2 * TEN);
    cudaFuncSetAttribute(gemm_mma<1>, cudaFuncAttributeMaxDynamicSharedMemorySize, 2 * 3 * TEN);
    cudaFuncSetAttribute(attn_mma, cudaFuncAttributeMaxDynamicSharedMemorySize, ATTN_SMEM);

    conv4_kernel<<<dim3(1024, 4), 256>>>((const float4*)Wq, (const float4*)Wk,
                                         (const float4*)Wv, (const float4*)Wo, (__half2*)w);
    conv_kernel<<<4096, 256>>>((const float4*)x, (__half2*)ahi, 1024 * 1024);

    proj_kernel<<<256, 256>>>(ss, ss_w, proj);
    bias_kernel<<<dim3(32, 32, BSZ), dim3(32, 32)>>>(pf, ids, inter_mat, proj,
                                                     physics_scale, distance_decay, biasb);

    // QKV projection: 1-pass (x fp16 single) -> qkv hi/lo
    gemm_mma<0><<<dim3(24, 32), 256, 2 * 2 * TEN>>>(ahi, nullptr, w, nullptr,
                                                    nullptr, qh, ql, 3072, 0);

    // HMMA flash attention -> ctx hi/lo (overwrites g_a_hi/g_a_lo)
    attn_mma<<<dim3(8, NH, BSZ), 256, ATTN_SMEM>>>(qh, ql, biasb, dist_bias, ahi, alo);

    // out projection: 2-pass (ctx hi/lo) @ Wo^T + bo -> fp32 out
    gemm_mma<1><<<dim3(8, 32), 256, 2 * 3 * TEN>>>(ahi, alo, w, bo,
                                                   out, nullptr, nullptr, 1024, 3072);
}

// round 12
// speedup vs baseline: 4.2567x; 1.0564x over previous
#include <cuda_runtime.h>
#include <cuda_fp16.h>
#include <math.h>
#include <stdint.h>

#define BSZ 4
#define LEN 1024
#define DM 1024
#define NH 16
#define NAA 25

// ---------------- scratch (static device globals; no allocation) ----------------
__device__ float g_bias[BSZ * LEN * LEN];
__device__ float g_proj[BSZ * LEN * NH];
__device__ __half g_a_hi[4096 * 1024];          // x fp16, later ctx hi
__device__ __half g_a_lo[4096 * 1024];          // ctx lo
__device__ __half g_w[4096 * 1024];             // rows 0-3071 = Wq,Wk,Wv; 3072-4095 = Wo
__device__ __half g_qkv_hi[BSZ * LEN * 3 * DM];
__device__ __half g_qkv_lo[BSZ * LEN * 3 * DM];

static __device__ __forceinline__ uint32_t smem_u32(const void* p) {
    uint32_t a;
    asm("{ .reg .u64 t; cvta.to.shared.u64 t, %1; cvt.u32.u64 %0, t; }" : "=r"(a) : "l"(p));
    return a;
}
static __device__ __forceinline__ uint32_t pack_h2(float x, float y) {
    __half2 h = __floats2half2_rn(x, y);
    uint32_t u;
    __builtin_memcpy(&u, &h, 4);
    return u;
}
static __device__ __forceinline__ uint32_t pack_hh(__half x, __half y) {
    __half2 h = __halves2half2(x, y);
    uint32_t u;
    __builtin_memcpy(&u, &h, 4);
    return u;
}

#define LDSM4(r, addr)                                                            \
    asm volatile("ldmatrix.sync.aligned.m8n8.x4.shared.b16 {%0,%1,%2,%3}, [%4];"  \
                 : "=r"((r)[0]), "=r"((r)[1]), "=r"((r)[2]), "=r"((r)[3])         \
                 : "r"(addr))
#define LDSM4T(r, addr)                                                                \
    asm volatile("ldmatrix.sync.aligned.m8n8.x4.trans.shared.b16 {%0,%1,%2,%3}, [%4];" \
                 : "=r"((r)[0]), "=r"((r)[1]), "=r"((r)[2]), "=r"((r)[3])              \
                 : "r"(addr))
#define MMA16816(d, a, b)                                                         \
    asm volatile("mma.sync.aligned.m16n8k16.row.col.f32.f16.f16.f32 "             \
                 "{%0,%1,%2,%3}, {%4,%5,%6,%7}, {%8,%9}, {%0,%1,%2,%3};"          \
                 : "+f"((d)[0]), "+f"((d)[1]), "+f"((d)[2]), "+f"((d)[3])         \
                 : "r"((a)[0]), "r"((a)[1]), "r"((a)[2]), "r"((a)[3]),            \
                   "r"((b)[0]), "r"((b)[1]))
#define CPA16(d, g) asm volatile("cp.async.cg.shared.global [%0], [%1], 16;" :: "r"(d), "l"(g))

// ---------------- fp32 -> fp16 convert (single) ----------------
__global__ __launch_bounds__(256)
void conv_kernel(const float4* __restrict__ a, __half2* __restrict__ w, int n4) {
    int i = blockIdx.x * blockDim.x + threadIdx.x;
    if (i >= n4) return;
    float4 v = a[i];
    w[2 * i]     = __floats2half2_rn(v.x, v.y);
    w[2 * i + 1] = __floats2half2_rn(v.z, v.w);
}

// ---------------- fused fp32 -> fp16 convert for 4 weight tensors ----------------
__global__ __launch_bounds__(256)
void conv4_kernel(const float4* __restrict__ a0, const float4* __restrict__ a1,
                  const float4* __restrict__ a2, const float4* __restrict__ a3,
                  __half2* __restrict__ w) {
    const int tensor = blockIdx.y;
    const float4* a = (tensor == 0) ? a0 : (tensor == 1) ? a1 : (tensor == 2) ? a2 : a3;
    int i = blockIdx.x * blockDim.x + threadIdx.x;
    float4 v = a[i];
    __half2* dst = w + (size_t)tensor * 524288;
    dst[2 * i]     = __floats2half2_rn(v.x, v.y);
    dst[2 * i + 1] = __floats2half2_rn(v.z, v.w);
}

// ---------------- HMMA fp16 GEMM: C[M,N] = A[M,K] @ W[N,K]^T ----------------
#define RS 80
#define TEN 10240
#define NCH 32

template <int TWO>
__global__ __launch_bounds__(256, 1)
void gemm_mma(const __half* __restrict__ Ah, const __half* __restrict__ Al,
              const __half* __restrict__ W,
              const float* __restrict__ bias, float* __restrict__ Cf,
              __half* __restrict__ Chi, __half* __restrict__ Clo,
              int N, int wrow0) {
    const int NT = TWO ? 3 : 2;
    const int STG = NT * TEN;
    extern __shared__ char sm[];
    const uint32_t sb = smem_u32(sm);
    const int t = threadIdx.x, wid = t >> 5, lane = t & 31;
    const int m0 = blockIdx.y << 7, n0 = blockIdx.x << 7;
    const int wm = wid & 1, wn = wid >> 1;

    const char* gsrc[3];
    gsrc[0] = (const char*)(Ah + (size_t)m0 * 1024);
    gsrc[1] = TWO ? (const char*)(Al + (size_t)m0 * 1024)
                  : (const char*)(W + (size_t)(wrow0 + n0) * 1024);
    gsrc[2] = (const char*)(W + (size_t)(wrow0 + n0) * 1024);

    const int mat = lane >> 3, lr = lane & 7;
    const uint32_t a_off = (uint32_t)((((mat & 1) << 3) + lr) * RS + ((mat >> 1) << 4));
    const uint32_t b_off = (uint32_t)((((mat >> 1) << 3) + lr) * RS + ((mat & 1) << 4));

    auto load_stage = [&](int st, int c) {
        uint32_t dbase = sb + st * STG;
#pragma unroll
        for (int q = 0; q < NT; q++) {
#pragma unroll
            for (int h = 0; h < 2; h++) {
                int idx = t + h * 256;
                int row = idx >> 2, seg = idx & 3;
                const char* g = gsrc[q] + (size_t)row * 2048 + c * 64 + seg * 16;
                uint32_t d = dbase + q * TEN + row * RS + seg * 16;
                CPA16(d, g);
            }
        }
        asm volatile("cp.async.commit_group;" ::: "memory");
    };

    float acc[4][4][4];
#pragma unroll
    for (int i = 0; i < 4; i++)
#pragma unroll
        for (int j = 0; j < 4; j++)
#pragma unroll
            for (int k = 0; k < 4; k++) acc[i][j][k] = 0.f;

    load_stage(0, 0);

    for (int c = 0; c < NCH; c++) {
        const int st = c & 1;
        if (c + 1 < NCH) {
            load_stage(st ^ 1, c + 1);
            asm volatile("cp.async.wait_group 1;" ::: "memory");
        } else {
            asm volatile("cp.async.wait_group 0;" ::: "memory");
        }
        __syncthreads();

        const uint32_t abase = sb + st * STG;
#pragma unroll
        for (int k16 = 0; k16 < 2; k16++) {
            uint32_t ah[4][4], al[4][4], bfrag[4][2];
#pragma unroll
            for (int mt = 0; mt < 4; mt++) {
                uint32_t addr = abase + (wm * 64 + mt * 16) * RS + k16 * 32 + a_off;
                LDSM4(ah[mt], addr);
                if (TWO) LDSM4(al[mt], addr + TEN);
            }
#pragma unroll
            for (int p = 0; p < 2; p++) {
                uint32_t addr = abase + (NT - 1) * TEN + (wn * 32 + p * 16) * RS + k16 * 32 + b_off;
                uint32_t r[4];
                LDSM4(r, addr);
                bfrag[2 * p][0] = r[0]; bfrag[2 * p][1] = r[1];
                bfrag[2 * p + 1][0] = r[2]; bfrag[2 * p + 1][1] = r[3];
            }
#pragma unroll
            for (int mt = 0; mt < 4; mt++)
#pragma unroll
                for (int nt = 0; nt < 4; nt++) {
                    MMA16816(acc[mt][nt], ah[mt], bfrag[nt]);
                    if (TWO) MMA16816(acc[mt][nt], al[mt], bfrag[nt]);
                }
        }
        __syncthreads();
    }

    const int qrow = lane >> 2, qcol = (lane & 3) * 2;
#pragma unroll
    for (int mt = 0; mt < 4; mt++) {
        const int r0 = m0 + wm * 64 + mt * 16 + qrow;
#pragma unroll
        for (int nt = 0; nt < 4; nt++) {
            const int col = n0 + wn * 32 + nt * 8 + qcol;
            if (Cf) {
                float bx = 0.f, by = 0.f;
                if (bias) { bx = bias[col]; by = bias[col + 1]; }
                *(float2*)(Cf + (size_t)r0 * N + col) =
                    make_float2(acc[mt][nt][0] + bx, acc[mt][nt][1] + by);
                *(float2*)(Cf + (size_t)(r0 + 8) * N + col) =
                    make_float2(acc[mt][nt][2] + bx, acc[mt][nt][3] + by);
            } else {
#pragma unroll
                for (int rr = 0; rr < 2; rr++) {
                    float vx = acc[mt][nt][2 * rr], vy = acc[mt][nt][2 * rr + 1];
                    __half hx = __float2half_rn(vx), hy = __float2half_rn(vy);
                    size_t off = (size_t)(r0 + rr * 8) * N + col;
                    *(uint32_t*)(Chi + off) = pack_hh(hx, hy);
                    *(uint32_t*)(Clo + off) =
                        pack_h2(vx - __half2float(hx), vy - __half2float(hy));
                }
            }
        }
    }
}

// ---------------- proj = secondary_structure @ ss_w^T ----------------
__global__ __launch_bounds__(256) void proj_kernel(const float* __restrict__ ss,
                                                   const float* __restrict__ ss_w,
                                                   float* __restrict__ proj) {
    __shared__ float w[NH][8];
    int t = threadIdx.x;
    if (t < NH * 8) w[t / 8][t % 8] = ss_w[t];
    __syncthreads();
    int idx = blockIdx.x * blockDim.x + t;
    int h = idx & 15;
    int bl = idx >> 4;
    const float* s = ss + bl * 8;
    float acc = 0.f;
#pragma unroll
    for (int c = 0; c < 8; c++) acc += s[c] * w[h][c];
    proj[idx] = acc;
}

// ---------------- shared bias tensor ----------------
__global__ __launch_bounds__(1024) void bias_kernel(const float* __restrict__ pf,
                                                    const int* __restrict__ ids,
                                                    const float* __restrict__ inter_mat,
                                                    const float* __restrict__ projp,
                                                    const float* __restrict__ physics_scale,
                                                    const float* __restrict__ distance_decay,
                                                    float* __restrict__ biasout) {
    __shared__ float sym[NAA * NAA];
    __shared__ float pi[32][17];
    __shared__ float pj[32][17];
    __shared__ int idi[32], idj[32];

    const int b = blockIdx.z;
    const int i0 = blockIdx.y * 32;
    const int j0 = blockIdx.x * 32;
    const int t = threadIdx.y * 32 + threadIdx.x;

    for (int s = t; s < NAA * NAA; s += 1024) {
        int r = s / NAA, c = s % NAA;
        sym[s] = 0.5f * (inter_mat[r * NAA + c] + inter_mat[c * NAA + r]);
    }
    if (t < 32)       idi[t]      = min(max(ids[b * LEN + i0 + t], 0), NAA - 1);
    else if (t < 64)  idj[t - 32] = min(max(ids[b * LEN + j0 + (t - 32)], 0), NAA - 1);
    if (t < 512) {
        int r = t / 16, c = t % 16;
        pi[r][c] = projp[(b * LEN + i0 + r) * NH + c];
    } else {
        int u = t - 512;
        int r = u / 16, c = u % 16;
        pj[r][c] = projp[(b * LEN + j0 + r) * NH + c];
    }
    __syncthreads();

    const int i = threadIdx.y, j = threadIdx.x;
    float decay = fminf(fmaxf(distance_decay[0], 0.1f), 5.0f);
    float sig = 1.0f / (1.0f + __expf(-physics_scale[0]));

    float d = pf[(size_t)b * LEN * LEN + (size_t)(i0 + i) * LEN + (j0 + j)];
    d = fminf(fmaxf(d, 0.1f), 50.0f);
    float pen = -__powf(d, decay) * sig;

    float it = sym[idi[i] * NAA + idj[j]] *
               (1.0f / (1.0f + fabsf((float)(i0 + i) - (float)(j0 + j))));

    float dot = 0.f;
#pragma unroll
    for (int hh = 0; hh < NH; hh++) dot += pi[i][hh] * pj[j][hh];
    float st = 1.0f / (1.0f + __expf(-dot)) - 0.5f;

    biasout[(size_t)b * LEN * LEN + (size_t)(i0 + i) * LEN + (j0 + j)] = pen + it + st;
}

// ---------------- HMMA fp16 flash attention: j-tile 64, 2 CTAs/SM ----------------
// 128 q-rows per CTA, 8 warps x 16 rows.
// S = Qh (Kh+Kl)^T (2-pass); O += P Vh (1-pass).
#define ARS 144
#define QB (128 * ARS)           // 18432
#define KVT64 (64 * ARS)         // 9216 per KV tensor
#define KVSTG (3 * KVT64)        // Kh, Kl, Vh = 27648
#define ATTN_SMEM (QB + 2 * KVSTG)   // 73728

__global__ __launch_bounds__(256, 2)
void attn_mma(const __half* __restrict__ qkvhi, const __half* __restrict__ qkvlo,
              const float* __restrict__ biasp, const float* __restrict__ dist_bias,
              __half* __restrict__ ctxhi, __half* __restrict__ ctxlo) {
    extern __shared__ char sm[];
    const uint32_t sb = smem_u32(sm);
    const int t = threadIdx.x, wid = t >> 5, lane = t & 31;
    const int i0 = blockIdx.x * 128, h = blockIdx.y, b = blockIdx.z;
    const float db = dist_bias[h];

    const int mat = lane >> 3, lr = lane & 7;
    const uint32_t a_off = (uint32_t)((((mat & 1) << 3) + lr) * ARS + ((mat >> 1) << 4));
    const uint32_t b_off = (uint32_t)((((mat >> 1) << 3) + lr) * ARS + ((mat & 1) << 4));
    const uint32_t v_off = (uint32_t)((lane & 15) * ARS + ((lane >> 4) << 4));

    // Q tile (hi only): 128 rows x 8 chunks of 16B
#pragma unroll
    for (int i = 0; i < 4; i++) {
        int idx = t + i * 256;
        int row = idx >> 3, seg = idx & 7;
        const char* g = (const char*)(qkvhi + (size_t)(b * LEN + i0 + row) * 3072 + h * 64) + seg * 16;
        CPA16(sb + row * ARS + seg * 16, g);
    }
    auto load_kv = [&](int st, int jt) {
        int j0 = jt * 64;
#pragma unroll
        for (int i = 0; i < 6; i++) {
            int idx = t + i * 256;                 // 1536 chunks: 3 tensors x 64 rows x 8 segs
            int tensor = idx >> 9;                 // 0 Kh, 1 Kl, 2 Vh
            int row = (idx >> 3) & 63;
            int seg = idx & 7;
            const __half* src = (tensor == 1) ? qkvlo : qkvhi;
            int coloff = ((tensor == 2) ? 2048 : 1024) + h * 64;
            const char* g = (const char*)(src + (size_t)(b * LEN + j0 + row) * 3072 + coloff) + seg * 16;
            CPA16(sb + QB + st * KVSTG + tensor * KVT64 + row * ARS + seg * 16, g);
        }
        asm volatile("cp.async.commit_group;" ::: "memory");
    };
    load_kv(0, 0);

    float O[8][4];
#pragma unroll
    for (int f = 0; f < 8; f++)
#pragma unroll
        for (int k = 0; k < 4; k++) O[f][k] = 0.f;
    float m0r = -3.0e38f, m1r = -3.0e38f, l0 = 0.f, l1 = 0.f;

    const int r0 = lane >> 2, c0 = (lane & 3) * 2;
    const float* bp = biasp + ((size_t)b * LEN + i0 + wid * 16) * LEN;

    for (int jt = 0; jt < 16; jt++) {
        const int st = jt & 1;
        // bias prefetch (gmem/L2, independent of cp.async) — issue before the wait
        float2 bpre[8][2];
        {
            const float* bj = bp + jt * 64 + c0;
#pragma unroll
            for (int f = 0; f < 8; f++) {
                bpre[f][0] = *(const float2*)(bj + (size_t)r0 * LEN + f * 8);
                bpre[f][1] = *(const float2*)(bj + (size_t)(r0 + 8) * LEN + f * 8);
            }
        }
        if (jt + 1 < 16) {
            load_kv(st ^ 1, jt + 1);
            asm volatile("cp.async.wait_group 1;" ::: "memory");
        } else {
            asm volatile("cp.async.wait_group 0;" ::: "memory");
        }
        __syncthreads();

        // S = Q K^T (2-pass: K hi + K lo)
        float sacc[8][4];
#pragma unroll
        for (int f = 0; f < 8; f++)
#pragma unroll
            for (int k = 0; k < 4; k++) sacc[f][k] = 0.f;

        const uint32_t kb = sb + QB + st * KVSTG;
#pragma unroll
        for (int kk = 0; kk < 4; kk++) {
            uint32_t a[4];
            LDSM4(a, sb + (wid * 16) * ARS + kk * 32 + a_off);
#pragma unroll
            for (int p = 0; p < 4; p++) {
                uint32_t rh[4], rl[4];
                uint32_t kaddr = kb + (p * 16) * ARS + kk * 32 + b_off;
                LDSM4(rh, kaddr);
                LDSM4(rl, kaddr + KVT64);
                uint32_t bh0[2] = {rh[0], rh[1]}, bh1[2] = {rh[2], rh[3]};
                uint32_t bl0[2] = {rl[0], rl[1]}, bl1[2] = {rl[2], rl[3]};
                MMA16816(sacc[2 * p], a, bh0);
                MMA16816(sacc[2 * p], a, bl0);
                MMA16816(sacc[2 * p + 1], a, bh1);
                MMA16816(sacc[2 * p + 1], a, bl1);
            }
        }

        // bias + online softmax
        float mx0 = -3.0e38f, mx1 = -3.0e38f;
#pragma unroll
        for (int f = 0; f < 8; f++) {
            sacc[f][0] = sacc[f][0] * 0.125f + bpre[f][0].x + db;
            sacc[f][1] = sacc[f][1] * 0.125f + bpre[f][0].y + db;
            sacc[f][2] = sacc[f][2] * 0.125f + bpre[f][1].x + db;
            sacc[f][3] = sacc[f][3] * 0.125f + bpre[f][1].y + db;
            mx0 = fmaxf(mx0, fmaxf(sacc[f][0], sacc[f][1]));
            mx1 = fmaxf(mx1, fmaxf(sacc[f][2], sacc[f][3]));
        }
        mx0 = fmaxf(mx0, __shfl_xor_sync(0xffffffffu, mx0, 1));
        mx0 = fmaxf(mx0, __shfl_xor_sync(0xffffffffu, mx0, 2));
        mx1 = fmaxf(mx1, __shfl_xor_sync(0xffffffffu, mx1, 1));
        mx1 = fmaxf(mx1, __shfl_xor_sync(0xffffffffu, mx1, 2));

        float mn0 = fmaxf(m0r, mx0), mn1 = fmaxf(m1r, mx1);
        float fac0 = __expf(m0r - mn0), fac1 = __expf(m1r - mn1);
        m0r = mn0; m1r = mn1;

        uint32_t pa[4][4];
        float sum0 = 0.f, sum1 = 0.f;
#pragma unroll
        for (int f = 0; f < 8; f++) {
            float p0 = __expf(sacc[f][0] - mn0);
            float p1 = __expf(sacc[f][1] - mn0);
            float p2 = __expf(sacc[f][2] - mn1);
            float p3 = __expf(sacc[f][3] - mn1);
            sum0 += p0 + p1; sum1 += p2 + p3;
            int jc = f >> 1, half = (f & 1) << 1;
            pa[jc][half]     = pack_h2(p0, p1);
            pa[jc][half + 1] = pack_h2(p2, p3);
        }
        sum0 += __shfl_xor_sync(0xffffffffu, sum0, 1);
        sum0 += __shfl_xor_sync(0xffffffffu, sum0, 2);
        sum1 += __shfl_xor_sync(0xffffffffu, sum1, 1);
        sum1 += __shfl_xor_sync(0xffffffffu, sum1, 2);
        l0 = l0 * fac0 + sum0;
        l1 = l1 * fac1 + sum1;

#pragma unroll
        for (int f = 0; f < 8; f++) {
            O[f][0] *= fac0; O[f][1] *= fac0;
            O[f][2] *= fac1; O[f][3] *= fac1;
        }

        // O += P Vh (1-pass), V via ldmatrix.trans
        const uint32_t vb = kb + 2 * KVT64;
#pragma unroll
        for (int jc = 0; jc < 4; jc++) {
#pragma unroll
            for (int dbk = 0; dbk < 4; dbk++) {
                uint32_t rh[4];
                LDSM4T(rh, vb + (jc * 16) * ARS + dbk * 32 + v_off);
                uint32_t bh0[2] = {rh[0], rh[1]}, bh1[2] = {rh[2], rh[3]};
                MMA16816(O[2 * dbk], pa[jc], bh0);
                MMA16816(O[2 * dbk + 1], pa[jc], bh1);
            }
        }
        __syncthreads();
    }

    // epilogue: normalize, split to fp16 hi/lo, store ctx
    const float inv0 = 1.0f / l0, inv1 = 1.0f / l1;
    const size_t row0 = (size_t)(b * LEN + i0 + wid * 16 + r0) * DM;
    const size_t row1 = row0 + 8 * DM;
    const int colb = h * 64 + c0;
#pragma unroll
    for (int f = 0; f < 8; f++) {
        float v0 = O[f][0] * inv0, v1 = O[f][1] * inv0;
        float v2 = O[f][2] * inv1, v3 = O[f][3] * inv1;
        __half h0 = __float2half_rn(v0), h1 = __float2half_rn(v1);
        __half h2 = __float2half_rn(v2), h3 = __float2half_rn(v3);
        *(uint32_t*)(ctxhi + row0 + colb + f * 8) = pack_hh(h0, h1);
        *(uint32_t*)(ctxhi + row1 + colb + f * 8) = pack_hh(h2, h3);
        *(uint32_t*)(ctxlo + row0 + colb + f * 8) =
            pack_h2(v0 - __half2float(h0), v1 - __half2float(h1));
        *(uint32_t*)(ctxlo + row1 + colb + f * 8) =
            pack_h2(v2 - __half2float(h2), v3 - __half2float(h3));
    }
}

// ---------------- launch ----------------
extern "C" void kernel_launch(void* const* d_in, const int* in_sizes, int n_in,
                              void* d_out, int out_size) {
    const float* x              = (const float*)d_in[0];
    const float* pf             = (const float*)d_in[1];
    const int*   ids            = (const int*)d_in[2];
    const float* ss             = (const float*)d_in[3];
    const float* Wq             = (const float*)d_in[4];
    const float* Wk             = (const float*)d_in[5];
    const float* Wv             = (const float*)d_in[6];
    const float* Wo             = (const float*)d_in[7];
    const float* bo             = (const float*)d_in[8];
    const float* dist_bias      = (const float*)d_in[9];
    const float* inter_mat      = (const float*)d_in[10];
    const float* ss_w           = (const float*)d_in[11];
    const float* physics_scale  = (const float*)d_in[12];
    const float* distance_decay = (const float*)d_in[13];
    float* out = (float*)d_out;

    float *biasb, *proj;
    __half *ahi, *alo, *w, *qh, *ql;
    cudaGetSymbolAddress((void**)&biasb, g_bias);
    cudaGetSymbolAddress((void**)&proj, g_proj);
    cudaGetSymbolAddress((void**)&ahi,  g_a_hi);
    cudaGetSymbolAddress((void**)&alo,  g_a_lo);
    cudaGetSymbolAddress((void**)&w,    g_w);
    cudaGetSymbolAddress((void**)&qh,   g_qkv_hi);
    cudaGetSymbolAddress((void**)&ql,   g_qkv_lo);

    cudaFuncSetAttribute(gemm_mma<0>, cudaFuncAttributeMaxDynamicSharedMemorySize, 2 * 2 * TEN);
    cudaFuncSetAttribute(gemm_mma<1>, cudaFuncAttributeMaxDynamicSharedMemorySize, 2 * 3 * TEN);
    cudaFuncSetAttribute(attn_mma, cudaFuncAttributeMaxDynamicSharedMemorySize, ATTN_SMEM);

    // side stream + events, created once on the first (uncaptured) correctness call;
    // fork/join via events is the supported capture pattern.
    static cudaStream_t s_side = nullptr;
    static cudaEvent_t ev_fork = nullptr, ev_join = nullptr;
    if (s_side == nullptr) {
        cudaStreamCreateWithFlags(&s_side, cudaStreamNonBlocking);
        cudaEventCreateWithFlags(&ev_fork, cudaEventDisableTiming);
        cudaEventCreateWithFlags(&ev_join, cudaEventDisableTiming);
    }

    // fork: bias path on side stream, GEMM path on main stream
    cudaEventRecord(ev_fork, 0);
    cudaStreamWaitEvent(s_side, ev_fork, 0);

    proj_kernel<<<256, 256, 0, s_side>>>(ss, ss_w, proj);
    bias_kernel<<<dim3(32, 32, BSZ), dim3(32, 32), 0, s_side>>>(
        pf, ids, inter_mat, proj, physics_scale, distance_decay, biasb);
    cudaEventRecord(ev_join, s_side);

    conv4_kernel<<<dim3(1024, 4), 256>>>((const float4*)Wq, (const float4*)Wk,
                                         (const float4*)Wv, (const float4*)Wo, (__half2*)w);
    conv_kernel<<<4096, 256>>>((const float4*)x, (__half2*)ahi, 1024 * 1024);

    // QKV projection: 1-pass (x fp16 single) -> qkv hi/lo
    gemm_mma<0><<<dim3(24, 32), 256, 2 * 2 * TEN>>>(ahi, nullptr, w, nullptr,
                                                    nullptr, qh, ql, 3072, 0);

    // join: attention needs bias + qkv
    cudaStreamWaitEvent(0, ev_join, 0);

    // HMMA flash attention (j=64, 2 CTAs/SM) -> ctx hi/lo (overwrites g_a_hi/g_a_lo)
    attn_mma<<<dim3(8, NH, BSZ), 256, ATTN_SMEM>>>(qh, ql, biasb, dist_bias, ahi, alo);

    // out projection: 2-pass (ctx hi/lo) @ Wo^T + bo -> fp32 out
    gemm_mma<1><<<dim3(8, 32), 256, 2 * 3 * TEN>>>(ahi, alo, w, bo,
                                                   out, nullptr, nullptr, 1024, 3072);
}

// round 13
// speedup vs baseline: 4.6244x; 1.0864x over previous
#include <cuda_runtime.h>
#include <cuda_fp16.h>
#include <math.h>
#include <stdint.h>

#define BSZ 4
#define LEN 1024
#define DM 1024
#define NH 16
#define NAA 25

// ---------------- scratch (static device globals; no allocation) ----------------
__device__ float g_bias[BSZ * LEN * LEN];
__device__ float g_proj[BSZ * LEN * NH];
__device__ __half g_a_hi[4096 * 1024];          // x fp16, later ctx hi
__device__ __half g_a_lo[4096 * 1024];          // ctx lo
__device__ __half g_w[4096 * 1024];             // rows 0-3071 = Wq,Wk,Wv; 3072-4095 = Wo
__device__ __half g_qkv[BSZ * LEN * 3 * DM];    // fp16 single

static __device__ __forceinline__ uint32_t smem_u32(const void* p) {
    uint32_t a;
    asm("{ .reg .u64 t; cvta.to.shared.u64 t, %1; cvt.u32.u64 %0, t; }" : "=r"(a) : "l"(p));
    return a;
}
static __device__ __forceinline__ uint32_t pack_h2(float x, float y) {
    __half2 h = __floats2half2_rn(x, y);
    uint32_t u;
    __builtin_memcpy(&u, &h, 4);
    return u;
}
static __device__ __forceinline__ uint32_t pack_hh(__half x, __half y) {
    __half2 h = __halves2half2(x, y);
    uint32_t u;
    __builtin_memcpy(&u, &h, 4);
    return u;
}

#define LDSM4(r, addr)                                                            \
    asm volatile("ldmatrix.sync.aligned.m8n8.x4.shared.b16 {%0,%1,%2,%3}, [%4];"  \
                 : "=r"((r)[0]), "=r"((r)[1]), "=r"((r)[2]), "=r"((r)[3])         \
                 : "r"(addr))
#define LDSM4T(r, addr)                                                                \
    asm volatile("ldmatrix.sync.aligned.m8n8.x4.trans.shared.b16 {%0,%1,%2,%3}, [%4];" \
                 : "=r"((r)[0]), "=r"((r)[1]), "=r"((r)[2]), "=r"((r)[3])              \
                 : "r"(addr))
#define MMA16816(d, a, b)                                                         \
    asm volatile("mma.sync.aligned.m16n8k16.row.col.f32.f16.f16.f32 "             \
                 "{%0,%1,%2,%3}, {%4,%5,%6,%7}, {%8,%9}, {%0,%1,%2,%3};"          \
                 : "+f"((d)[0]), "+f"((d)[1]), "+f"((d)[2]), "+f"((d)[3])         \
                 : "r"((a)[0]), "r"((a)[1]), "r"((a)[2]), "r"((a)[3]),            \
                   "r"((b)[0]), "r"((b)[1]))
#define CPA16(d, g) asm volatile("cp.async.cg.shared.global [%0], [%1], 16;" :: "r"(d), "l"(g))

// ---------------- fp32 -> fp16 convert (single) ----------------
__global__ __launch_bounds__(256)
void conv_kernel(const float4* __restrict__ a, __half2* __restrict__ w, int n4) {
    int i = blockIdx.x * blockDim.x + threadIdx.x;
    if (i >= n4) return;
    float4 v = a[i];
    w[2 * i]     = __floats2half2_rn(v.x, v.y);
    w[2 * i + 1] = __floats2half2_rn(v.z, v.w);
}

// ---------------- fused fp32 -> fp16 convert for 4 weight tensors ----------------
__global__ __launch_bounds__(256)
void conv4_kernel(const float4* __restrict__ a0, const float4* __restrict__ a1,
                  const float4* __restrict__ a2, const float4* __restrict__ a3,
                  __half2* __restrict__ w) {
    const int tensor = blockIdx.y;
    const float4* a = (tensor == 0) ? a0 : (tensor == 1) ? a1 : (tensor == 2) ? a2 : a3;
    int i = blockIdx.x * blockDim.x + threadIdx.x;
    float4 v = a[i];
    __half2* dst = w + (size_t)tensor * 524288;
    dst[2 * i]     = __floats2half2_rn(v.x, v.y);
    dst[2 * i + 1] = __floats2half2_rn(v.z, v.w);
}

// ---------------- HMMA fp16 GEMM: C[M,N] = A[M,K] @ W[N,K]^T ----------------
#define RS 80
#define TEN 10240
#define NCH 32

template <int TWO>
__global__ __launch_bounds__(256, 1)
void gemm_mma(const __half* __restrict__ Ah, const __half* __restrict__ Al,
              const __half* __restrict__ W,
              const float* __restrict__ bias, float* __restrict__ Cf,
              __half* __restrict__ Chi, __half* __restrict__ Clo,
              int N, int wrow0) {
    const int NT = TWO ? 3 : 2;
    const int STG = NT * TEN;
    extern __shared__ char sm[];
    const uint32_t sb = smem_u32(sm);
    const int t = threadIdx.x, wid = t >> 5, lane = t & 31;
    const int m0 = blockIdx.y << 7, n0 = blockIdx.x << 7;
    const int wm = wid & 1, wn = wid >> 1;

    const char* gsrc[3];
    gsrc[0] = (const char*)(Ah + (size_t)m0 * 1024);
    gsrc[1] = TWO ? (const char*)(Al + (size_t)m0 * 1024)
                  : (const char*)(W + (size_t)(wrow0 + n0) * 1024);
    gsrc[2] = (const char*)(W + (size_t)(wrow0 + n0) * 1024);

    const int mat = lane >> 3, lr = lane & 7;
    const uint32_t a_off = (uint32_t)((((mat & 1) << 3) + lr) * RS + ((mat >> 1) << 4));
    const uint32_t b_off = (uint32_t)((((mat >> 1) << 3) + lr) * RS + ((mat & 1) << 4));

    auto load_stage = [&](int st, int c) {
        uint32_t dbase = sb + st * STG;
#pragma unroll
        for (int q = 0; q < NT; q++) {
#pragma unroll
            for (int h = 0; h < 2; h++) {
                int idx = t + h * 256;
                int row = idx >> 2, seg = idx & 3;
                const char* g = gsrc[q] + (size_t)row * 2048 + c * 64 + seg * 16;
                uint32_t d = dbase + q * TEN + row * RS + seg * 16;
                CPA16(d, g);
            }
        }
        asm volatile("cp.async.commit_group;" ::: "memory");
    };

    float acc[4][4][4];
#pragma unroll
    for (int i = 0; i < 4; i++)
#pragma unroll
        for (int j = 0; j < 4; j++)
#pragma unroll
            for (int k = 0; k < 4; k++) acc[i][j][k] = 0.f;

    load_stage(0, 0);

    for (int c = 0; c < NCH; c++) {
        const int st = c & 1;
        if (c + 1 < NCH) {
            load_stage(st ^ 1, c + 1);
            asm volatile("cp.async.wait_group 1;" ::: "memory");
        } else {
            asm volatile("cp.async.wait_group 0;" ::: "memory");
        }
        __syncthreads();

        const uint32_t abase = sb + st * STG;
#pragma unroll
        for (int k16 = 0; k16 < 2; k16++) {
            uint32_t ah[4][4], al[4][4], bfrag[4][2];
#pragma unroll
            for (int mt = 0; mt < 4; mt++) {
                uint32_t addr = abase + (wm * 64 + mt * 16) * RS + k16 * 32 + a_off;
                LDSM4(ah[mt], addr);
                if (TWO) LDSM4(al[mt], addr + TEN);
            }
#pragma unroll
            for (int p = 0; p < 2; p++) {
                uint32_t addr = abase + (NT - 1) * TEN + (wn * 32 + p * 16) * RS + k16 * 32 + b_off;
                uint32_t r[4];
                LDSM4(r, addr);
                bfrag[2 * p][0] = r[0]; bfrag[2 * p][1] = r[1];
                bfrag[2 * p + 1][0] = r[2]; bfrag[2 * p + 1][1] = r[3];
            }
#pragma unroll
            for (int mt = 0; mt < 4; mt++)
#pragma unroll
                for (int nt = 0; nt < 4; nt++) {
                    MMA16816(acc[mt][nt], ah[mt], bfrag[nt]);
                    if (TWO) MMA16816(acc[mt][nt], al[mt], bfrag[nt]);
                }
        }
        __syncthreads();
    }

    const int qrow = lane >> 2, qcol = (lane & 3) * 2;
#pragma unroll
    for (int mt = 0; mt < 4; mt++) {
        const int r0 = m0 + wm * 64 + mt * 16 + qrow;
#pragma unroll
        for (int nt = 0; nt < 4; nt++) {
            const int col = n0 + wn * 32 + nt * 8 + qcol;
            if (Cf) {
                float bx = 0.f, by = 0.f;
                if (bias) { bx = bias[col]; by = bias[col + 1]; }
                *(float2*)(Cf + (size_t)r0 * N + col) =
                    make_float2(acc[mt][nt][0] + bx, acc[mt][nt][1] + by);
                *(float2*)(Cf + (size_t)(r0 + 8) * N + col) =
                    make_float2(acc[mt][nt][2] + bx, acc[mt][nt][3] + by);
            } else {
#pragma unroll
                for (int rr = 0; rr < 2; rr++) {
                    float vx = acc[mt][nt][2 * rr], vy = acc[mt][nt][2 * rr + 1];
                    __half hx = __float2half_rn(vx), hy = __float2half_rn(vy);
                    size_t off = (size_t)(r0 + rr * 8) * N + col;
                    *(uint32_t*)(Chi + off) = pack_hh(hx, hy);
                    if (Clo)
                        *(uint32_t*)(Clo + off) =
                            pack_h2(vx - __half2float(hx), vy - __half2float(hy));
                }
            }
        }
    }
}

// ---------------- proj = secondary_structure @ ss_w^T ----------------
__global__ __launch_bounds__(256) void proj_kernel(const float* __restrict__ ss,
                                                   const float* __restrict__ ss_w,
                                                   float* __restrict__ proj) {
    __shared__ float w[NH][8];
    int t = threadIdx.x;
    if (t < NH * 8) w[t / 8][t % 8] = ss_w[t];
    __syncthreads();
    int idx = blockIdx.x * blockDim.x + t;
    int h = idx & 15;
    int bl = idx >> 4;
    const float* s = ss + bl * 8;
    float acc = 0.f;
#pragma unroll
    for (int c = 0; c < 8; c++) acc += s[c] * w[h][c];
    proj[idx] = acc;
}

// ---------------- shared bias tensor ----------------
__global__ __launch_bounds__(1024) void bias_kernel(const float* __restrict__ pf,
                                                    const int* __restrict__ ids,
                                                    const float* __restrict__ inter_mat,
                                                    const float* __restrict__ projp,
                                                    const float* __restrict__ physics_scale,
                                                    const float* __restrict__ distance_decay,
                                                    float* __restrict__ biasout) {
    __shared__ float sym[NAA * NAA];
    __shared__ float pi[32][17];
    __shared__ float pj[32][17];
    __shared__ int idi[32], idj[32];

    const int b = blockIdx.z;
    const int i0 = blockIdx.y * 32;
    const int j0 = blockIdx.x * 32;
    const int t = threadIdx.y * 32 + threadIdx.x;

    for (int s = t; s < NAA * NAA; s += 1024) {
        int r = s / NAA, c = s % NAA;
        sym[s] = 0.5f * (inter_mat[r * NAA + c] + inter_mat[c * NAA + r]);
    }
    if (t < 32)       idi[t]      = min(max(ids[b * LEN + i0 + t], 0), NAA - 1);
    else if (t < 64)  idj[t - 32] = min(max(ids[b * LEN + j0 + (t - 32)], 0), NAA - 1);
    if (t < 512) {
        int r = t / 16, c = t % 16;
        pi[r][c] = projp[(b * LEN + i0 + r) * NH + c];
    } else {
        int u = t - 512;
        int r = u / 16, c = u % 16;
        pj[r][c] = projp[(b * LEN + j0 + r) * NH + c];
    }
    __syncthreads();

    const int i = threadIdx.y, j = threadIdx.x;
    float decay = fminf(fmaxf(distance_decay[0], 0.1f), 5.0f);
    float sig = 1.0f / (1.0f + __expf(-physics_scale[0]));

    float d = pf[(size_t)b * LEN * LEN + (size_t)(i0 + i) * LEN + (j0 + j)];
    d = fminf(fmaxf(d, 0.1f), 50.0f);
    float pen = -__powf(d, decay) * sig;

    float it = sym[idi[i] * NAA + idj[j]] *
               (1.0f / (1.0f + fabsf((float)(i0 + i) - (float)(j0 + j))));

    float dot = 0.f;
#pragma unroll
    for (int hh = 0; hh < NH; hh++) dot += pi[i][hh] * pj[j][hh];
    float st = 1.0f / (1.0f + __expf(-dot)) - 0.5f;

    biasout[(size_t)b * LEN * LEN + (size_t)(i0 + i) * LEN + (j0 + j)] = pen + it + st;
}

// ---------------- HMMA fp16 flash attention: j-tile 64, 2 CTAs/SM ----------------
// 128 q-rows per CTA, 8 warps x 16 rows. S = Qh Kh^T (1-pass); O += P Vh (1-pass).
#define ARS 144
#define QB (128 * ARS)           // 18432
#define KVT64 (64 * ARS)         // 9216 per KV tensor
#define KVSTG (2 * KVT64)        // Kh, Vh = 18432
#define ATTN_SMEM (QB + 2 * KVSTG)   // 55296

__global__ __launch_bounds__(256, 2)
void attn_mma(const __half* __restrict__ qkv,
              const float* __restrict__ biasp, const float* __restrict__ dist_bias,
              __half* __restrict__ ctxhi, __half* __restrict__ ctxlo) {
    extern __shared__ char sm[];
    const uint32_t sb = smem_u32(sm);
    const int t = threadIdx.x, wid = t >> 5, lane = t & 31;
    const int i0 = blockIdx.x * 128, h = blockIdx.y, b = blockIdx.z;
    const float db = dist_bias[h];

    const int mat = lane >> 3, lr = lane & 7;
    const uint32_t a_off = (uint32_t)((((mat & 1) << 3) + lr) * ARS + ((mat >> 1) << 4));
    const uint32_t b_off = (uint32_t)((((mat >> 1) << 3) + lr) * ARS + ((mat & 1) << 4));
    const uint32_t v_off = (uint32_t)((lane & 15) * ARS + ((lane >> 4) << 4));

    // Q tile: 128 rows x 8 chunks of 16B
#pragma unroll
    for (int i = 0; i < 4; i++) {
        int idx = t + i * 256;
        int row = idx >> 3, seg = idx & 7;
        const char* g = (const char*)(qkv + (size_t)(b * LEN + i0 + row) * 3072 + h * 64) + seg * 16;
        CPA16(sb + row * ARS + seg * 16, g);
    }
    auto load_kv = [&](int st, int jt) {
        int j0 = jt * 64;
#pragma unroll
        for (int i = 0; i < 4; i++) {
            int idx = t + i * 256;                 // 1024 chunks: 2 tensors x 64 rows x 8 segs
            int tensor = idx >> 9;                 // 0 Kh, 1 Vh
            int row = (idx >> 3) & 63;
            int seg = idx & 7;
            int coloff = (tensor ? 2048 : 1024) + h * 64;
            const char* g = (const char*)(qkv + (size_t)(b * LEN + j0 + row) * 3072 + coloff) + seg * 16;
            CPA16(sb + QB + st * KVSTG + tensor * KVT64 + row * ARS + seg * 16, g);
        }
        asm volatile("cp.async.commit_group;" ::: "memory");
    };
    load_kv(0, 0);

    float O[8][4];
#pragma unroll
    for (int f = 0; f < 8; f++)
#pragma unroll
        for (int k = 0; k < 4; k++) O[f][k] = 0.f;
    float m0r = -3.0e38f, m1r = -3.0e38f, l0 = 0.f, l1 = 0.f;

    const int r0 = lane >> 2, c0 = (lane & 3) * 2;
    const float* bp = biasp + ((size_t)b * LEN + i0 + wid * 16) * LEN;

    for (int jt = 0; jt < 16; jt++) {
        const int st = jt & 1;
        // bias prefetch (gmem/L2) — issued before the cp.async wait
        float2 bpre[8][2];
        {
            const float* bj = bp + jt * 64 + c0;
#pragma unroll
            for (int f = 0; f < 8; f++) {
                bpre[f][0] = *(const float2*)(bj + (size_t)r0 * LEN + f * 8);
                bpre[f][1] = *(const float2*)(bj + (size_t)(r0 + 8) * LEN + f * 8);
            }
        }
        if (jt + 1 < 16) {
            load_kv(st ^ 1, jt + 1);
            asm volatile("cp.async.wait_group 1;" ::: "memory");
        } else {
            asm volatile("cp.async.wait_group 0;" ::: "memory");
        }
        __syncthreads();

        // S = Q K^T (1-pass)
        float sacc[8][4];
#pragma unroll
        for (int f = 0; f < 8; f++)
#pragma unroll
            for (int k = 0; k < 4; k++) sacc[f][k] = 0.f;

        const uint32_t kb = sb + QB + st * KVSTG;
#pragma unroll
        for (int kk = 0; kk < 4; kk++) {
            uint32_t a[4];
            LDSM4(a, sb + (wid * 16) * ARS + kk * 32 + a_off);
#pragma unroll
            for (int p = 0; p < 4; p++) {
                uint32_t rh[4];
                LDSM4(rh, kb + (p * 16) * ARS + kk * 32 + b_off);
                uint32_t b0[2] = {rh[0], rh[1]}, b1[2] = {rh[2], rh[3]};
                MMA16816(sacc[2 * p], a, b0);
                MMA16816(sacc[2 * p + 1], a, b1);
            }
        }

        // bias + online softmax
        float mx0 = -3.0e38f, mx1 = -3.0e38f;
#pragma unroll
        for (int f = 0; f < 8; f++) {
            sacc[f][0] = sacc[f][0] * 0.125f + bpre[f][0].x + db;
            sacc[f][1] = sacc[f][1] * 0.125f + bpre[f][0].y + db;
            sacc[f][2] = sacc[f][2] * 0.125f + bpre[f][1].x + db;
            sacc[f][3] = sacc[f][3] * 0.125f + bpre[f][1].y + db;
            mx0 = fmaxf(mx0, fmaxf(sacc[f][0], sacc[f][1]));
            mx1 = fmaxf(mx1, fmaxf(sacc[f][2], sacc[f][3]));
        }
        mx0 = fmaxf(mx0, __shfl_xor_sync(0xffffffffu, mx0, 1));
        mx0 = fmaxf(mx0, __shfl_xor_sync(0xffffffffu, mx0, 2));
        mx1 = fmaxf(mx1, __shfl_xor_sync(0xffffffffu, mx1, 1));
        mx1 = fmaxf(mx1, __shfl_xor_sync(0xffffffffu, mx1, 2));

        float mn0 = fmaxf(m0r, mx0), mn1 = fmaxf(m1r, mx1);
        float fac0 = __expf(m0r - mn0), fac1 = __expf(m1r - mn1);
        m0r = mn0; m1r = mn1;

        uint32_t pa[4][4];
        float sum0 = 0.f, sum1 = 0.f;
#pragma unroll
        for (int f = 0; f < 8; f++) {
            float p0 = __expf(sacc[f][0] - mn0);
            float p1 = __expf(sacc[f][1] - mn0);
            float p2 = __expf(sacc[f][2] - mn1);
            float p3 = __expf(sacc[f][3] - mn1);
            sum0 += p0 + p1; sum1 += p2 + p3;
            int jc = f >> 1, half = (f & 1) << 1;
            pa[jc][half]     = pack_h2(p0, p1);
            pa[jc][half + 1] = pack_h2(p2, p3);
        }
        sum0 += __shfl_xor_sync(0xffffffffu, sum0, 1);
        sum0 += __shfl_xor_sync(0xffffffffu, sum0, 2);
        sum1 += __shfl_xor_sync(0xffffffffu, sum1, 1);
        sum1 += __shfl_xor_sync(0xffffffffu, sum1, 2);
        l0 = l0 * fac0 + sum0;
        l1 = l1 * fac1 + sum1;

#pragma unroll
        for (int f = 0; f < 8; f++) {
            O[f][0] *= fac0; O[f][1] *= fac0;
            O[f][2] *= fac1; O[f][3] *= fac1;
        }

        // O += P Vh (1-pass), V via ldmatrix.trans
        const uint32_t vb = kb + KVT64;
#pragma unroll
        for (int jc = 0; jc < 4; jc++) {
#pragma unroll
            for (int dbk = 0; dbk < 4; dbk++) {
                uint32_t rh[4];
                LDSM4T(rh, vb + (jc * 16) * ARS + dbk * 32 + v_off);
                uint32_t bh0[2] = {rh[0], rh[1]}, bh1[2] = {rh[2], rh[3]};
                MMA16816(O[2 * dbk], pa[jc], bh0);
                MMA16816(O[2 * dbk + 1], pa[jc], bh1);
            }
        }
        __syncthreads();
    }

    // epilogue: normalize, split to fp16 hi/lo, store ctx
    const float inv0 = 1.0f / l0, inv1 = 1.0f / l1;
    const size_t row0 = (size_t)(b * LEN + i0 + wid * 16 + r0) * DM;
    const size_t row1 = row0 + 8 * DM;
    const int colb = h * 64 + c0;
#pragma unroll
    for (int f = 0; f < 8; f++) {
        float v0 = O[f][0] * inv0, v1 = O[f][1] * inv0;
        float v2 = O[f][2] * inv1, v3 = O[f][3] * inv1;
        __half h0 = __float2half_rn(v0), h1 = __float2half_rn(v1);
        __half h2 = __float2half_rn(v2), h3 = __float2half_rn(v3);
        *(uint32_t*)(ctxhi + row0 + colb + f * 8) = pack_hh(h0, h1);
        *(uint32_t*)(ctxhi + row1 + colb + f * 8) = pack_hh(h2, h3);
        *(uint32_t*)(ctxlo + row0 + colb + f * 8) =
            pack_h2(v0 - __half2float(h0), v1 - __half2float(h1));
        *(uint32_t*)(ctxlo + row1 + colb + f * 8) =
            pack_h2(v2 - __half2float(h2), v3 - __half2float(h3));
    }
}

// ---------------- launch ----------------
extern "C" void kernel_launch(void* const* d_in, const int* in_sizes, int n_in,
                              void* d_out, int out_size) {
    const float* x              = (const float*)d_in[0];
    const float* pf             = (const float*)d_in[1];
    const int*   ids            = (const int*)d_in[2];
    const float* ss             = (const float*)d_in[3];
    const float* Wq             = (const float*)d_in[4];
    const float* Wk             = (const float*)d_in[5];
    const float* Wv             = (const float*)d_in[6];
    const float* Wo             = (const float*)d_in[7];
    const float* bo             = (const float*)d_in[8];
    const float* dist_bias      = (const float*)d_in[9];
    const float* inter_mat      = (const float*)d_in[10];
    const float* ss_w           = (const float*)d_in[11];
    const float* physics_scale  = (const float*)d_in[12];
    const float* distance_decay = (const float*)d_in[13];
    float* out = (float*)d_out;

    float *biasb, *proj;
    __half *ahi, *alo, *w, *qkv;
    cudaGetSymbolAddress((void**)&biasb, g_bias);
    cudaGetSymbolAddress((void**)&proj, g_proj);
    cudaGetSymbolAddress((void**)&ahi,  g_a_hi);
    cudaGetSymbolAddress((void**)&alo,  g_a_lo);
    cudaGetSymbolAddress((void**)&w,    g_w);
    cudaGetSymbolAddress((void**)&qkv,  g_qkv);

    cudaFuncSetAttribute(gemm_mma<0>, cudaFuncAttributeMaxDynamicSharedMemorySize, 2 * 2 * TEN);
    cudaFuncSetAttribute(gemm_mma<1>, cudaFuncAttributeMaxDynamicSharedMemorySize, 2 * 3 * TEN);
    cudaFuncSetAttribute(attn_mma, cudaFuncAttributeMaxDynamicSharedMemorySize, ATTN_SMEM);

    static cudaStream_t s_side = nullptr;
    static cudaEvent_t ev_fork = nullptr, ev_join = nullptr;
    if (s_side == nullptr) {
        cudaStreamCreateWithFlags(&s_side, cudaStreamNonBlocking);
        cudaEventCreateWithFlags(&ev_fork, cudaEventDisableTiming);
        cudaEventCreateWithFlags(&ev_join, cudaEventDisableTiming);
    }

    // fork: bias path on side stream, GEMM path on main stream
    cudaEventRecord(ev_fork, 0);
    cudaStreamWaitEvent(s_side, ev_fork, 0);

    proj_kernel<<<256, 256, 0, s_side>>>(ss, ss_w, proj);
    bias_kernel<<<dim3(32, 32, BSZ), dim3(32, 32), 0, s_side>>>(
        pf, ids, inter_mat, proj, physics_scale, distance_decay, biasb);
    cudaEventRecord(ev_join, s_side);

    conv4_kernel<<<dim3(1024, 4), 256>>>((const float4*)Wq, (const float4*)Wk,
                                         (const float4*)Wv, (const float4*)Wo, (__half2*)w);
    conv_kernel<<<4096, 256>>>((const float4*)x, (__half2*)ahi, 1024 * 1024);

    // QKV projection: 1-pass, fp16-single output
    gemm_mma<0><<<dim3(24, 32), 256, 2 * 2 * TEN>>>(ahi, nullptr, w, nullptr,
                                                    nullptr, qkv, nullptr, 3072, 0);

    // join: attention needs bias + qkv
    cudaStreamWaitEvent(0, ev_join, 0);

    // HMMA flash attention (1-pass S, 1-pass PV) -> ctx hi/lo
    attn_mma<<<dim3(8, NH, BSZ), 256, ATTN_SMEM>>>(qkv, biasb, dist_bias, ahi, alo);

    // out projection: 2-pass (ctx hi/lo) @ Wo^T + bo -> fp32 out
    gemm_mma<1><<<dim3(8, 32), 256, 2 * 3 * TEN>>>(ahi, alo, w, bo,
                                                   out, nullptr, nullptr, 1024, 3072);
}

// round 16
// speedup vs baseline: 5.0014x; 1.0815x over previous
#include <cuda_runtime.h>
#include <cuda_fp16.h>
#include <math.h>
#include <stdint.h>

#define BSZ 4
#define LEN 1024
#define DM 1024
#define NH 16
#define NAA 25

// ---------------- scratch (static device globals; no allocation) ----------------
__device__ float g_bias[BSZ * LEN * LEN];
__device__ float g_proj[BSZ * LEN * NH];
__device__ __half g_a[4096 * 1024];             // x fp16, later ctx fp16
__device__ __half g_w[4096 * 1024];             // rows 0-3071 = Wq,Wk,Wv; 3072-4095 = Wo
__device__ __half g_qkv[BSZ * LEN * 3 * DM];    // fp16 (q pre-scaled by 0.125)

static __device__ __forceinline__ uint32_t smem_u32(const void* p) {
    uint32_t a;
    asm("{ .reg .u64 t; cvta.to.shared.u64 t, %1; cvt.u32.u64 %0, t; }" : "=r"(a) : "l"(p));
    return a;
}
static __device__ __forceinline__ uint32_t pack_h2(float x, float y) {
    __half2 h = __floats2half2_rn(x, y);
    uint32_t u;
    __builtin_memcpy(&u, &h, 4);
    return u;
}

#define LDSM4(r, addr)                                                            \
    asm volatile("ldmatrix.sync.aligned.m8n8.x4.shared.b16 {%0,%1,%2,%3}, [%4];"  \
                 : "=r"((r)[0]), "=r"((r)[1]), "=r"((r)[2]), "=r"((r)[3])         \
                 : "r"(addr))
#define LDSM4T(r, addr)                                                                \
    asm volatile("ldmatrix.sync.aligned.m8n8.x4.trans.shared.b16 {%0,%1,%2,%3}, [%4];" \
                 : "=r"((r)[0]), "=r"((r)[1]), "=r"((r)[2]), "=r"((r)[3])              \
                 : "r"(addr))
#define MMA16816(d, a, b)                                                         \
    asm volatile("mma.sync.aligned.m16n8k16.row.col.f32.f16.f16.f32 "             \
                 "{%0,%1,%2,%3}, {%4,%5,%6,%7}, {%8,%9}, {%0,%1,%2,%3};"          \
                 : "+f"((d)[0]), "+f"((d)[1]), "+f"((d)[2]), "+f"((d)[3])         \
                 : "r"((a)[0]), "r"((a)[1]), "r"((a)[2]), "r"((a)[3]),            \
                   "r"((b)[0]), "r"((b)[1]))
#define CPA16(d, g) asm volatile("cp.async.cg.shared.global [%0], [%1], 16;" :: "r"(d), "l"(g))

// ---------------- fp32 -> fp16 convert ----------------
__global__ __launch_bounds__(256)
void conv_kernel(const float4* __restrict__ a, __half2* __restrict__ w, int n4) {
    int i = blockIdx.x * blockDim.x + threadIdx.x;
    if (i >= n4) return;
    float4 v = a[i];
    w[2 * i]     = __floats2half2_rn(v.x, v.y);
    w[2 * i + 1] = __floats2half2_rn(v.z, v.w);
}

__global__ __launch_bounds__(256)
void conv4_kernel(const float4* __restrict__ a0, const float4* __restrict__ a1,
                  const float4* __restrict__ a2, const float4* __restrict__ a3,
                  __half2* __restrict__ w) {
    const int tensor = blockIdx.y;
    const float4* a = (tensor == 0) ? a0 : (tensor == 1) ? a1 : (tensor == 2) ? a2 : a3;
    int i = blockIdx.x * blockDim.x + threadIdx.x;
    float4 v = a[i];
    __half2* dst = w + (size_t)tensor * 524288;
    dst[2 * i]     = __floats2half2_rn(v.x, v.y);
    dst[2 * i + 1] = __floats2half2_rn(v.z, v.w);
}

// ---------------- HMMA fp16 1-pass GEMM: C[M,N] = A[M,K] @ W[N,K]^T ----------------
// Cf!=0: fp32 out (+bias). Else fp16 out to Ch; cols < qcols scaled by 0.125.
#define RS 80
#define TEN 10240
#define STG (2 * TEN)
#define NCH 32

__global__ __launch_bounds__(256, 1)
void gemm_mma(const __half* __restrict__ A, const __half* __restrict__ W,
              const float* __restrict__ bias, float* __restrict__ Cf,
              __half* __restrict__ Ch, int N, int wrow0, int m_off, int qcols) {
    extern __shared__ char sm[];
    const uint32_t sb = smem_u32(sm);
    const int t = threadIdx.x, wid = t >> 5, lane = t & 31;
    const int m0 = (blockIdx.y << 7) + m_off, n0 = blockIdx.x << 7;
    const int wm = wid & 1, wn = wid >> 1;

    const char* gsrc[2];
    gsrc[0] = (const char*)(A + (size_t)m0 * 1024);
    gsrc[1] = (const char*)(W + (size_t)(wrow0 + n0) * 1024);

    const int mat = lane >> 3, lr = lane & 7;
    const uint32_t a_off = (uint32_t)((((mat & 1) << 3) + lr) * RS + ((mat >> 1) << 4));
    const uint32_t b_off = (uint32_t)((((mat >> 1) << 3) + lr) * RS + ((mat & 1) << 4));

    auto load_stage = [&](int st, int c) {
        uint32_t dbase = sb + st * STG;
#pragma unroll
        for (int q = 0; q < 2; q++) {
#pragma unroll
            for (int h = 0; h < 2; h++) {
                int idx = t + h * 256;
                int row = idx >> 2, seg = idx & 3;
                const char* g = gsrc[q] + (size_t)row * 2048 + c * 64 + seg * 16;
                CPA16(dbase + q * TEN + row * RS + seg * 16, g);
            }
        }
        asm volatile("cp.async.commit_group;" ::: "memory");
    };

    float acc[4][4][4];
#pragma unroll
    for (int i = 0; i < 4; i++)
#pragma unroll
        for (int j = 0; j < 4; j++)
#pragma unroll
            for (int k = 0; k < 4; k++) acc[i][j][k] = 0.f;

    load_stage(0, 0);

    for (int c = 0; c < NCH; c++) {
        const int st = c & 1;
        if (c + 1 < NCH) {
            load_stage(st ^ 1, c + 1);
            asm volatile("cp.async.wait_group 1;" ::: "memory");
        } else {
            asm volatile("cp.async.wait_group 0;" ::: "memory");
        }
        __syncthreads();

        const uint32_t abase = sb + st * STG;
#pragma unroll
        for (int k16 = 0; k16 < 2; k16++) {
            uint32_t ah[4][4], bfrag[4][2];
#pragma unroll
            for (int mt = 0; mt < 4; mt++)
                LDSM4(ah[mt], abase + (wm * 64 + mt * 16) * RS + k16 * 32 + a_off);
#pragma unroll
            for (int p = 0; p < 2; p++) {
                uint32_t r[4];
                LDSM4(r, abase + TEN + (wn * 32 + p * 16) * RS + k16 * 32 + b_off);
                bfrag[2 * p][0] = r[0]; bfrag[2 * p][1] = r[1];
                bfrag[2 * p + 1][0] = r[2]; bfrag[2 * p + 1][1] = r[3];
            }
#pragma unroll
            for (int mt = 0; mt < 4; mt++)
#pragma unroll
                for (int nt = 0; nt < 4; nt++)
                    MMA16816(acc[mt][nt], ah[mt], bfrag[nt]);
        }
        __syncthreads();
    }

    const int qrow = lane >> 2, qcol = (lane & 3) * 2;
#pragma unroll
    for (int mt = 0; mt < 4; mt++) {
        const int r0 = m0 + wm * 64 + mt * 16 + qrow;
#pragma unroll
        for (int nt = 0; nt < 4; nt++) {
            const int col = n0 + wn * 32 + nt * 8 + qcol;
            if (Cf) {
                float bx = 0.f, by = 0.f;
                if (bias) { bx = bias[col]; by = bias[col + 1]; }
                *(float2*)(Cf + (size_t)r0 * N + col) =
                    make_float2(acc[mt][nt][0] + bx, acc[mt][nt][1] + by);
                *(float2*)(Cf + (size_t)(r0 + 8) * N + col) =
                    make_float2(acc[mt][nt][2] + bx, acc[mt][nt][3] + by);
            } else {
                const float s = (col < qcols) ? 0.125f : 1.0f;   // fold 1/sqrt(dk) into q
#pragma unroll
                for (int rr = 0; rr < 2; rr++) {
                    size_t off = (size_t)(r0 + rr * 8) * N + col;
                    *(uint32_t*)(Ch + off) =
                        pack_h2(acc[mt][nt][2 * rr] * s, acc[mt][nt][2 * rr + 1] * s);
                }
            }
        }
    }
}

// ---------------- proj = secondary_structure @ ss_w^T ----------------
__global__ __launch_bounds__(256) void proj_kernel(const float* __restrict__ ss,
                                                   const float* __restrict__ ss_w,
                                                   float* __restrict__ proj) {
    __shared__ float w[NH][8];
    int t = threadIdx.x;
    if (t < NH * 8) w[t / 8][t % 8] = ss_w[t];
    __syncthreads();
    int idx = blockIdx.x * blockDim.x + t;
    int h = idx & 15;
    int bl = idx >> 4;
    const float* s = ss + bl * 8;
    float acc = 0.f;
#pragma unroll
    for (int c = 0; c < 8; c++) acc += s[c] * w[h][c];
    proj[idx] = acc;
}

// ---------------- shared bias tensor (dist_bias dropped: softmax shift-invariant) ----------------
__global__ __launch_bounds__(1024) void bias_kernel(const float* __restrict__ pf,
                                                    const int* __restrict__ ids,
                                                    const float* __restrict__ inter_mat,
                                                    const float* __restrict__ projp,
                                                    const float* __restrict__ physics_scale,
                                                    const float* __restrict__ distance_decay,
                                                    float* __restrict__ biasout) {
    __shared__ float sym[NAA * NAA];
    __shared__ float pi[32][17];
    __shared__ float pj[32][17];
    __shared__ int idi[32], idj[32];

    const int b = blockIdx.z;
    const int i0 = blockIdx.y * 32;
    const int j0 = blockIdx.x * 32;
    const int t = threadIdx.y * 32 + threadIdx.x;

    for (int s = t; s < NAA * NAA; s += 1024) {
        int r = s / NAA, c = s % NAA;
        sym[s] = 0.5f * (inter_mat[r * NAA + c] + inter_mat[c * NAA + r]);
    }
    if (t < 32)       idi[t]      = min(max(ids[b * LEN + i0 + t], 0), NAA - 1);
    else if (t < 64)  idj[t - 32] = min(max(ids[b * LEN + j0 + (t - 32)], 0), NAA - 1);
    if (t < 512) {
        int r = t / 16, c = t % 16;
        pi[r][c] = projp[(b * LEN + i0 + r) * NH + c];
    } else {
        int u = t - 512;
        int r = u / 16, c = u % 16;
        pj[r][c] = projp[(b * LEN + j0 + r) * NH + c];
    }
    __syncthreads();

    const int i = threadIdx.y, j = threadIdx.x;
    float decay = fminf(fmaxf(distance_decay[0], 0.1f), 5.0f);
    float sig = 1.0f / (1.0f + __expf(-physics_scale[0]));

    float d = pf[(size_t)b * LEN * LEN + (size_t)(i0 + i) * LEN + (j0 + j)];
    d = fminf(fmaxf(d, 0.1f), 50.0f);
    float pen = -__powf(d, decay) * sig;

    float it = sym[idi[i] * NAA + idj[j]] *
               (1.0f / (1.0f + fabsf((float)(i0 + i) - (float)(j0 + j))));

    float dot = 0.f;
#pragma unroll
    for (int hh = 0; hh < NH; hh++) dot += pi[i][hh] * pj[j][hh];
    float st = 1.0f / (1.0f + __expf(-dot)) - 0.5f;

    biasout[(size_t)b * LEN * LEN + (size_t)(i0 + i) * LEN + (j0 + j)] = pen + it + st;
}

// ---------------- HMMA fp16 flash attention: j-tile 64, 2 CTAs/SM ----------------
// q pre-scaled by 0.125; S = q k^T (1-pass); O += P v (1-pass); ctx out single fp16.
#define ARS 144
#define QB (128 * ARS)
#define KVT64 (64 * ARS)
#define KVSTG (2 * KVT64)
#define ATTN_SMEM (QB + 2 * KVSTG)   // 55296

__global__ __launch_bounds__(256, 2)
void attn_mma(const __half* __restrict__ qkv,
              const float* __restrict__ biasp, __half* __restrict__ ctx, int b_off) {
    extern __shared__ char sm[];
    const uint32_t sb = smem_u32(sm);
    const int t = threadIdx.x, wid = t >> 5, lane = t & 31;
    const int i0 = blockIdx.x * 128, h = blockIdx.y, b = blockIdx.z + b_off;

    const int mat = lane >> 3, lr = lane & 7;
    const uint32_t a_off = (uint32_t)((((mat & 1) << 3) + lr) * ARS + ((mat >> 1) << 4));
    const uint32_t b_offd = (uint32_t)((((mat >> 1) << 3) + lr) * ARS + ((mat & 1) << 4));
    const uint32_t v_off = (uint32_t)((lane & 15) * ARS + ((lane >> 4) << 4));

#pragma unroll
    for (int i = 0; i < 4; i++) {
        int idx = t + i * 256;
        int row = idx >> 3, seg = idx & 7;
        const char* g = (const char*)(qkv + (size_t)(b * LEN + i0 + row) * 3072 + h * 64) + seg * 16;
        CPA16(sb + row * ARS + seg * 16, g);
    }
    auto load_kv = [&](int st, int jt) {
        int j0 = jt * 64;
#pragma unroll
        for (int i = 0; i < 4; i++) {
            int idx = t + i * 256;
            int tensor = idx >> 9;                 // 0 Kh, 1 Vh
            int row = (idx >> 3) & 63;
            int seg = idx & 7;
            int coloff = (tensor ? 2048 : 1024) + h * 64;
            const char* g = (const char*)(qkv + (size_t)(b * LEN + j0 + row) * 3072 + coloff) + seg * 16;
            CPA16(sb + QB + st * KVSTG + tensor * KVT64 + row * ARS + seg * 16, g);
        }
        asm volatile("cp.async.commit_group;" ::: "memory");
    };
    load_kv(0, 0);

    float O[8][4];
#pragma unroll
    for (int f = 0; f < 8; f++)
#pragma unroll
        for (int k = 0; k < 4; k++) O[f][k] = 0.f;
    float m0r = -3.0e38f, m1r = -3.0e38f, l0 = 0.f, l1 = 0.f;

    const int r0 = lane >> 2, c0 = (lane & 3) * 2;
    const float* bp = biasp + ((size_t)b * LEN + i0 + wid * 16) * LEN;

    for (int jt = 0; jt < 16; jt++) {
        const int st = jt & 1;
        float2 bpre[8][2];
        {
            const float* bj = bp + jt * 64 + c0;
#pragma unroll
            for (int f = 0; f < 8; f++) {
                bpre[f][0] = *(const float2*)(bj + (size_t)r0 * LEN + f * 8);
                bpre[f][1] = *(const float2*)(bj + (size_t)(r0 + 8) * LEN + f * 8);
            }
        }
        if (jt + 1 < 16) {
            load_kv(st ^ 1, jt + 1);
            asm volatile("cp.async.wait_group 1;" ::: "memory");
        } else {
            asm volatile("cp.async.wait_group 0;" ::: "memory");
        }
        __syncthreads();

        float sacc[8][4];
#pragma unroll
        for (int f = 0; f < 8; f++)
#pragma unroll
            for (int k = 0; k < 4; k++) sacc[f][k] = 0.f;

        const uint32_t kb = sb + QB + st * KVSTG;
#pragma unroll
        for (int kk = 0; kk < 4; kk++) {
            uint32_t a[4];
            LDSM4(a, sb + (wid * 16) * ARS + kk * 32 + a_off);
#pragma unroll
            for (int p = 0; p < 4; p++) {
                uint32_t rh[4];
                LDSM4(rh, kb + (p * 16) * ARS + kk * 32 + b_offd);
                uint32_t b0[2] = {rh[0], rh[1]}, b1[2] = {rh[2], rh[3]};
                MMA16816(sacc[2 * p], a, b0);
                MMA16816(sacc[2 * p + 1], a, b1);
            }
        }

        // bias + online softmax (q pre-scaled; dist_bias dropped)
        float mx0 = -3.0e38f, mx1 = -3.0e38f;
#pragma unroll
        for (int f = 0; f < 8; f++) {
            sacc[f][0] += bpre[f][0].x;
            sacc[f][1] += bpre[f][0].y;
            sacc[f][2] += bpre[f][1].x;
            sacc[f][3] += bpre[f][1].y;
            mx0 = fmaxf(mx0, fmaxf(sacc[f][0], sacc[f][1]));
            mx1 = fmaxf(mx1, fmaxf(sacc[f][2], sacc[f][3]));
        }
        mx0 = fmaxf(mx0, __shfl_xor_sync(0xffffffffu, mx0, 1));
        mx0 = fmaxf(mx0, __shfl_xor_sync(0xffffffffu, mx0, 2));
        mx1 = fmaxf(mx1, __shfl_xor_sync(0xffffffffu, mx1, 1));
        mx1 = fmaxf(mx1, __shfl_xor_sync(0xffffffffu, mx1, 2));

        float mn0 = fmaxf(m0r, mx0), mn1 = fmaxf(m1r, mx1);
        float fac0 = __expf(m0r - mn0), fac1 = __expf(m1r - mn1);
        m0r = mn0; m1r = mn1;

        uint32_t pa[4][4];
        float sum0 = 0.f, sum1 = 0.f;
#pragma unroll
        for (int f = 0; f < 8; f++) {
            float p0 = __expf(sacc[f][0] - mn0);
            float p1 = __expf(sacc[f][1] - mn0);
            float p2 = __expf(sacc[f][2] - mn1);
            float p3 = __expf(sacc[f][3] - mn1);
            sum0 += p0 + p1; sum1 += p2 + p3;
            int jc = f >> 1, half = (f & 1) << 1;
            pa[jc][half]     = pack_h2(p0, p1);
            pa[jc][half + 1] = pack_h2(p2, p3);
        }
        sum0 += __shfl_xor_sync(0xffffffffu, sum0, 1);
        sum0 += __shfl_xor_sync(0xffffffffu, sum0, 2);
        sum1 += __shfl_xor_sync(0xffffffffu, sum1, 1);
        sum1 += __shfl_xor_sync(0xffffffffu, sum1, 2);
        l0 = l0 * fac0 + sum0;
        l1 = l1 * fac1 + sum1;

#pragma unroll
        for (int f = 0; f < 8; f++) {
            O[f][0] *= fac0; O[f][1] *= fac0;
            O[f][2] *= fac1; O[f][3] *= fac1;
        }

        const uint32_t vb = kb + KVT64;
#pragma unroll
        for (int jc = 0; jc < 4; jc++) {
#pragma unroll
            for (int dbk = 0; dbk < 4; dbk++) {
                uint32_t rh[4];
                LDSM4T(rh, vb + (jc * 16) * ARS + dbk * 32 + v_off);
                uint32_t bh0[2] = {rh[0], rh[1]}, bh1[2] = {rh[2], rh[3]};
                MMA16816(O[2 * dbk], pa[jc], bh0);
                MMA16816(O[2 * dbk + 1], pa[jc], bh1);
            }
        }
        __syncthreads();
    }

    // epilogue: normalize, store ctx single fp16
    const float inv0 = 1.0f / l0, inv1 = 1.0f / l1;
    const size_t row0 = (size_t)(b * LEN + i0 + wid * 16 + r0) * DM;
    const size_t row1 = row0 + 8 * DM;
    const int colb = h * 64 + c0;
#pragma unroll
    for (int f = 0; f < 8; f++) {
        *(uint32_t*)(ctx + row0 + colb + f * 8) = pack_h2(O[f][0] * inv0, O[f][1] * inv0);
        *(uint32_t*)(ctx + row1 + colb + f * 8) = pack_h2(O[f][2] * inv1, O[f][3] * inv1);
    }
}

// ---------------- launch ----------------
extern "C" void kernel_launch(void* const* d_in, const int* in_sizes, int n_in,
                              void* d_out, int out_size) {
    const float* x              = (const float*)d_in[0];
    const float* pf             = (const float*)d_in[1];
    const int*   ids            = (const int*)d_in[2];
    const float* ss             = (const float*)d_in[3];
    const float* Wq             = (const float*)d_in[4];
    const float* Wk             = (const float*)d_in[5];
    const float* Wv             = (const float*)d_in[6];
    const float* Wo             = (const float*)d_in[7];
    const float* bo             = (const float*)d_in[8];
    const float* inter_mat      = (const float*)d_in[10];
    const float* ss_w           = (const float*)d_in[11];
    const float* physics_scale  = (const float*)d_in[12];
    const float* distance_decay = (const float*)d_in[13];
    float* out = (float*)d_out;

    float *biasb, *proj;
    __half *a, *w, *qkv;
    cudaGetSymbolAddress((void**)&biasb, g_bias);
    cudaGetSymbolAddress((void**)&proj, g_proj);
    cudaGetSymbolAddress((void**)&a,    g_a);
    cudaGetSymbolAddress((void**)&w,    g_w);
    cudaGetSymbolAddress((void**)&qkv,  g_qkv);

    cudaFuncSetAttribute(gemm_mma, cudaFuncAttributeMaxDynamicSharedMemorySize, 2 * STG);
    cudaFuncSetAttribute(attn_mma, cudaFuncAttributeMaxDynamicSharedMemorySize, ATTN_SMEM);

    static cudaStream_t s_side = nullptr;
    static cudaEvent_t ev_fork = nullptr, evG0 = nullptr, evG1 = nullptr,
                       evA0 = nullptr, evA1 = nullptr;
    if (s_side == nullptr) {
        cudaStreamCreateWithFlags(&s_side, cudaStreamNonBlocking);
        cudaEventCreateWithFlags(&ev_fork, cudaEventDisableTiming);
        cudaEventCreateWithFlags(&evG0, cudaEventDisableTiming);
        cudaEventCreateWithFlags(&evG1, cudaEventDisableTiming);
        cudaEventCreateWithFlags(&evA0, cudaEventDisableTiming);
        cudaEventCreateWithFlags(&evA1, cudaEventDisableTiming);
    }

    // fork: bias path starts on side stream
    cudaEventRecord(ev_fork, 0);
    cudaStreamWaitEvent(s_side, ev_fork, 0);
    proj_kernel<<<256, 256, 0, s_side>>>(ss, ss_w, proj);
    bias_kernel<<<dim3(32, 32, BSZ), dim3(32, 32), 0, s_side>>>(
        pf, ids, inter_mat, proj, physics_scale, distance_decay, biasb);

    // main: converts + QKV GEMM in two M-halves (q cols pre-scaled by 0.125)
    conv4_kernel<<<dim3(1024, 4), 256>>>((const float4*)Wq, (const float4*)Wk,
                                         (const float4*)Wv, (const float4*)Wo, (__half2*)w);
    conv_kernel<<<4096, 256>>>((const float4*)x, (__half2*)a, 1024 * 1024);

    gemm_mma<<<dim3(24, 16), 256, 2 * STG>>>(a, w, nullptr, nullptr, qkv, 3072, 0, 0, 1024);
    cudaEventRecord(evG0, 0);
    gemm_mma<<<dim3(24, 16), 256, 2 * STG>>>(a, w, nullptr, nullptr, qkv, 3072, 0, 2048, 1024);
    cudaEventRecord(evG1, 0);

    // side: attn halves (batches 0-1, then 2-3); h0 overlaps gemm h1
    cudaStreamWaitEvent(s_side, evG0, 0);
    attn_mma<<<dim3(8, NH, 2), 256, ATTN_SMEM, s_side>>>(qkv, biasb, a, 0);
    cudaEventRecord(evA0, s_side);
    cudaStreamWaitEvent(s_side, evG1, 0);
    attn_mma<<<dim3(8, NH, 2), 256, ATTN_SMEM, s_side>>>(qkv, biasb, a, 2);
    cudaEventRecord(evA1, s_side);

    // main: out-proj halves (1-pass, ctx fp16); h0 overlaps attn h1
    cudaStreamWaitEvent(0, evA0, 0);
    gemm_mma<<<dim3(8, 16), 256, 2 * STG>>>(a, w, bo, out, nullptr, 1024, 3072, 0, 0);
    cudaStreamWaitEvent(0, evA1, 0);
    gemm_mma<<<dim3(8, 16), 256, 2 * STG>>>(a, w, bo, out, nullptr, 1024, 3072, 2048, 0);
}